// round 10
// baseline (speedup 1.0000x reference)
#include <cuda_runtime.h>
#include <cuda_bf16.h>
#include <cstdint>

// Problem constants
#define B 4
#define S 1024
#define D 1024
#define H 16
#define DK 64
#define L 2047          // 2*S - 1
#define LP 1088         // P rows actually used by attention (max read 1086)
#define BS (B*S)        // 4096

// ---------------------------------------------------------------------------
// Scratch (static device globals; no runtime allocation allowed)
// ---------------------------------------------------------------------------
__device__ float g_ub[B * H * S];
__device__ float g_Bv[H * L];
__device__ float g_uw[H * D];
__device__ float g_vw[H * D];
__device__ float g_cuv[32];

// bf16 hi/lo splits (inputs to tensor-core GEMMs)
__device__ __nv_bfloat16 g_xh[BS * D], g_xl[BS * D];
__device__ __nv_bfloat16 g_Rh[LP * D], g_Rl[LP * D];
__device__ __nv_bfloat16 g_Wsh[5 * D * D], g_Wsl[5 * D * D];   // q,k,v,r,o

// bf16 hi/lo GEMM outputs (attention inputs)
__device__ __nv_bfloat16 g_Qbh[BS * D], g_Qbl[BS * D];
__device__ __nv_bfloat16 g_Kbh[BS * D], g_Kbl[BS * D];
__device__ __nv_bfloat16 g_Vbh[BS * D], g_Vbl[BS * D];
__device__ __nv_bfloat16 g_Pbh[LP * D], g_Pbl[LP * D];

// attention output (bf16 pairs; input to out-projection)
__device__ __nv_bfloat16 g_vh[BS * D], g_vl[BS * D];

// ---------------------------------------------------------------------------
// PTX helpers: portable sm_80+ (ldmatrix / mma.sync / cp.async).
// ---------------------------------------------------------------------------
__device__ __forceinline__ uint32_t smem_to_u32(const void* p) {
    uint32_t a;
    asm("{ .reg .u64 t; cvta.to.shared.u64 t, %1; cvt.u32.u64 %0, t; }"
        : "=r"(a) : "l"(p));
    return a;
}

__device__ __forceinline__ void ldsm4(uint32_t* r, uint32_t addr) {
    asm volatile("ldmatrix.sync.aligned.m8n8.x4.shared.b16 {%0,%1,%2,%3}, [%4];"
                 : "=r"(r[0]), "=r"(r[1]), "=r"(r[2]), "=r"(r[3]) : "r"(addr));
}
__device__ __forceinline__ void ldsm4t(uint32_t* r, uint32_t addr) {
    asm volatile("ldmatrix.sync.aligned.m8n8.x4.trans.shared.b16 {%0,%1,%2,%3}, [%4];"
                 : "=r"(r[0]), "=r"(r[1]), "=r"(r[2]), "=r"(r[3]) : "r"(addr));
}

__device__ __forceinline__ void mma16816(float* d, const uint32_t* a,
                                         const uint32_t* b) {
    asm volatile(
        "mma.sync.aligned.m16n8k16.row.col.f32.bf16.bf16.f32 "
        "{%0,%1,%2,%3}, {%4,%5,%6,%7}, {%8,%9}, {%0,%1,%2,%3};"
        : "+f"(d[0]), "+f"(d[1]), "+f"(d[2]), "+f"(d[3])
        : "r"(a[0]), "r"(a[1]), "r"(a[2]), "r"(a[3]), "r"(b[0]), "r"(b[1]));
}

__device__ __forceinline__ void cp16(uint32_t dst, const void* src, int sz) {
    asm volatile("cp.async.cg.shared.global [%0], [%1], 16, %2;\n"
                 :: "r"(dst), "l"(src), "r"(sz));
}
__device__ __forceinline__ void cp_commit() {
    asm volatile("cp.async.commit_group;\n" ::: "memory");
}
template <int N> __device__ __forceinline__ void cp_wait() {
    asm volatile("cp.async.wait_group %0;\n" :: "n"(N) : "memory");
}

// ---------------------------------------------------------------------------
// fp32 -> bf16 hi/lo splits
// ---------------------------------------------------------------------------
__global__ void split_kernel(const float* __restrict__ s,
                             __nv_bfloat16* __restrict__ hi,
                             __nv_bfloat16* __restrict__ lo, int n)
{
    int i = blockIdx.x * 256 + threadIdx.x;
    if (i < n) {
        float x = s[i];
        __nv_bfloat16 h = __float2bfloat16(x);
        float r = x - __bfloat162float(h);
        hi[i] = h;
        lo[i] = __float2bfloat16(r);
    }
}

struct SplitBatch { const float* src[5]; };

__global__ void splitW_kernel(const SplitBatch sb,
                              __nv_bfloat16* __restrict__ hi,
                              __nv_bfloat16* __restrict__ lo)
{
    int z = blockIdx.y;
    int i = blockIdx.x * 256 + threadIdx.x;
    size_t off = (size_t)z * D * D + i;
    float x = sb.src[z][i];
    __nv_bfloat16 h = __float2bfloat16(x);
    hi[off] = h;
    lo[off] = __float2bfloat16(x - __bfloat162float(h));
}

// ---------------------------------------------------------------------------
// rel_u/rel_v pre-contraction:
//   uw[h,e] = sum_d rel_u[h,d] * Wr[h*64+d, e]   (and vw with rel_v)
//   cu[h]   = sum_d rel_u[h,d] * br[h*64+d]      (and cv)
// Then ubias = x @ uw^T + cu  and  Bv = R @ vw^T + cv  (rank-16 GEMMs).
// ---------------------------------------------------------------------------
__global__ void contract_w(const float* __restrict__ Wr,
                           const float* __restrict__ rel_u,
                           const float* __restrict__ rel_v,
                           float* __restrict__ uw, float* __restrict__ vw)
{
    int idx = blockIdx.x * 256 + threadIdx.x;   // 0 .. 2*H*D-1
    int t  = idx >> 14;                          // 0: uw, 1: vw
    int he = idx & (H * D - 1);
    int h = he >> 10;
    int e = he & (D - 1);
    const float* rel = t ? rel_v : rel_u;
    float s = 0.f;
#pragma unroll 8
    for (int d = 0; d < DK; d++)
        s = fmaf(__ldg(&rel[h * DK + d]), Wr[(size_t)(h * DK + d) * D + e], s);
    (t ? vw : uw)[he] = s;
}

__global__ void contract_c(const float* __restrict__ br,
                           const float* __restrict__ rel_u,
                           const float* __restrict__ rel_v,
                           float* __restrict__ cuv)
{
    int t = threadIdx.x;
    if (t < 32) {
        int h = t & 15;
        const float* rel = (t < 16) ? rel_u : rel_v;
        float s = 0.f;
        for (int d = 0; d < DK; d++)
            s = fmaf(rel[h * DK + d], br[h * DK + d], s);
        cuv[t] = s;
    }
}

// warp-per-row rank-16 GEMM: out[h-major] = A_row . w[h] + c[h]
// mode 0 (ubias): A = x [4096 rows], out[(b*H+h)*S + z], row = b*S + z
// mode 1 (Bv):    A = R [LP rows],   out[h*L + l],       row = l
__global__ __launch_bounds__(256) void rank16_kernel(
    const float* __restrict__ A, const float* __restrict__ w,
    const float* __restrict__ c, float* __restrict__ out,
    int nrows, int mode)
{
    int row  = blockIdx.x * 8 + (threadIdx.x >> 5);
    int lane = threadIdx.x & 31;
    if (row >= nrows) return;
    const float4* ar = (const float4*)(A + (size_t)row * D);
    float acc[16];
#pragma unroll
    for (int h = 0; h < 16; h++) acc[h] = 0.f;
#pragma unroll
    for (int j = 0; j < 8; j++) {
        float4 xv = ar[lane + j * 32];
#pragma unroll
        for (int h = 0; h < 16; h++) {
            float4 wv = ((const float4*)(w + h * D))[lane + j * 32];
            acc[h] += xv.x * wv.x + xv.y * wv.y + xv.z * wv.z + xv.w * wv.w;
        }
    }
    float mine = 0.f;
#pragma unroll
    for (int h = 0; h < 16; h++) {
        float v = acc[h];
        v += __shfl_xor_sync(0xffffffffu, v, 16);
        v += __shfl_xor_sync(0xffffffffu, v, 8);
        v += __shfl_xor_sync(0xffffffffu, v, 4);
        v += __shfl_xor_sync(0xffffffffu, v, 2);
        v += __shfl_xor_sync(0xffffffffu, v, 1);
        if (lane == h) mine = v;
    }
    if (lane < 16) {
        float val = mine + c[lane + (mode == 1 ? 16 : 0)];
        if (mode == 0) {
            int b = row >> 10, z = row & 1023;
            out[((b << 4) + lane) * S + z] = val;
        } else {
            out[lane * L + row] = val;
        }
    }
}

// ---------------------------------------------------------------------------
// HMMA GEMM: C[M,1024] = A[M,1024] @ W[1024,1024]^T + bias
// bf16x3 compensation. mode 0: fp32 C;  mode 1: bf16 hi/lo pair outputs.
// z < zsplit: A = (Ah1, Al1), M = M1.  z >= zsplit: A = (Ah2, Al2), M = M2.
// ---------------------------------------------------------------------------
struct GemmBatch {
    const __nv_bfloat16* Wh[4];
    const __nv_bfloat16* Wl[4];
    const float* bias[4];
    float* C[4];
    __nv_bfloat16* Ch[4];
    __nv_bfloat16* Cl[4];
    int mode[4];
};

#define RS      40                   // bf16 elems per smem row (80 bytes)
#define TILE_B  (128 * RS * 2)       // 10240 B
#define STAGE_B (4 * TILE_B)
#define GEMM_SMEM (2 * STAGE_B)      // 81920
#define NC      32

__device__ __forceinline__ void load_chunk(
    uint32_t sbase, int tid,
    const __nv_bfloat16* Ah, const __nv_bfloat16* Al,
    const __nv_bfloat16* Wh, const __nv_bfloat16* Wl,
    int bm, int bn, int M, int c, int st)
{
    const int kbase = c * 32;
    const uint32_t stoff = sbase + st * STAGE_B;
#pragma unroll
    for (int t = 0; t < 4; t++) {
        const __nv_bfloat16* base = (t == 0) ? Ah : (t == 1) ? Al : (t == 2) ? Wh : Wl;
        const int rb = (t < 2) ? bm : bn;
#pragma unroll
        for (int j = 0; j < 2; j++) {
            int idx = tid + j * 256;
            int row = idx >> 2, g = idx & 3;
            int gr = rb + row;
            int sz = (t >= 2 || gr < M) ? 16 : 0;
            const void* src = base + (size_t)gr * 1024 + kbase + g * 8;
            uint32_t dst = stoff + t * TILE_B + row * 80 + g * 16;
            cp16(dst, src, sz);
        }
    }
}

__global__ __launch_bounds__(256, 2)
void gemm_tc(const __nv_bfloat16* __restrict__ Ah1,
             const __nv_bfloat16* __restrict__ Al1,
             const __nv_bfloat16* __restrict__ Ah2,
             const __nv_bfloat16* __restrict__ Al2,
             const GemmBatch bat, int M1, int M2, int zsplit)
{
    extern __shared__ char smem[];
    const uint32_t sbase = smem_to_u32(smem);
    const int tid  = threadIdx.x;
    const int wid  = tid >> 5;
    const int lane = tid & 31;
    const int bn = blockIdx.x * 128;
    const int bm = blockIdx.y * 128;
    const int z  = blockIdx.z;

    const __nv_bfloat16* Ah = (z < zsplit) ? Ah1 : Ah2;
    const __nv_bfloat16* Al = (z < zsplit) ? Al1 : Al2;
    const int M = (z < zsplit) ? M1 : M2;
    if (bm >= M) return;               // early-exit tail tiles (P trim)

    const __nv_bfloat16* Wh = bat.Wh[z];
    const __nv_bfloat16* Wl = bat.Wl[z];

    const int mb = (wid >> 2) * 64;
    const int nb = (wid & 3) * 32;

    const int li = lane >> 3, lr = lane & 7;
    const int a_off = ((li & 1) * 8 + lr) * 80 + (li >> 1) * 16;
    const int b_off = ((li >> 1) * 8 + lr) * 80 + (li & 1) * 16;

    float acc[4][4][4];
#pragma unroll
    for (int mf = 0; mf < 4; mf++)
#pragma unroll
        for (int nf = 0; nf < 4; nf++)
#pragma unroll
            for (int e = 0; e < 4; e++) acc[mf][nf][e] = 0.f;

    load_chunk(sbase, tid, Ah, Al, Wh, Wl, bm, bn, M, 0, 0);
    cp_commit();

    for (int c = 0; c < NC; c++) {
        const int st = c & 1;
        cp_wait<0>();
        __syncthreads();
        if (c + 1 < NC) {
            load_chunk(sbase, tid, Ah, Al, Wh, Wl, bm, bn, M, c + 1, st ^ 1);
            cp_commit();
        }

        const uint32_t aH = sbase + st * STAGE_B + 0 * TILE_B + (mb)*80 + a_off;
        const uint32_t aL = aH + TILE_B;
        const uint32_t wH = sbase + st * STAGE_B + 2 * TILE_B + (nb)*80 + b_off;
        const uint32_t wL = wH + TILE_B;

#pragma unroll
        for (int k16 = 0; k16 < 2; k16++) {
            const int ko = k16 * 32;
            uint32_t ah[4][4], al[4][4], bh[2][4], bl[2][4];
#pragma unroll
            for (int mf = 0; mf < 4; mf++) {
                ldsm4(ah[mf], aH + mf * 16 * 80 + ko);
                ldsm4(al[mf], aL + mf * 16 * 80 + ko);
            }
#pragma unroll
            for (int n2 = 0; n2 < 2; n2++) {
                ldsm4(bh[n2], wH + n2 * 16 * 80 + ko);
                ldsm4(bl[n2], wL + n2 * 16 * 80 + ko);
            }
#pragma unroll
            for (int mf = 0; mf < 4; mf++)
#pragma unroll
                for (int nf = 0; nf < 4; nf++) {
                    const uint32_t* bph = &bh[nf >> 1][(nf & 1) * 2];
                    const uint32_t* bpl = &bl[nf >> 1][(nf & 1) * 2];
                    mma16816(acc[mf][nf], ah[mf], bph);
                    mma16816(acc[mf][nf], ah[mf], bpl);
                    mma16816(acc[mf][nf], al[mf], bph);
                }
        }
    }

    const float* bias = bat.bias[z];
    const int lr4 = lane >> 2, lc2 = (lane & 3) * 2;
    if (bat.mode[z] == 0) {
        float* C = bat.C[z];
#pragma unroll
        for (int mf = 0; mf < 4; mf++)
#pragma unroll
            for (int nf = 0; nf < 4; nf++) {
                int gn = bn + nb + nf * 8 + lc2;
                float2 bi = *(const float2*)(bias + gn);
                int gm0 = bm + mb + mf * 16 + lr4;
                if (gm0 < M) {
                    float2 v = make_float2(acc[mf][nf][0] + bi.x, acc[mf][nf][1] + bi.y);
                    *(float2*)(C + (size_t)gm0 * 1024 + gn) = v;
                }
                int gm1 = gm0 + 8;
                if (gm1 < M) {
                    float2 v = make_float2(acc[mf][nf][2] + bi.x, acc[mf][nf][3] + bi.y);
                    *(float2*)(C + (size_t)gm1 * 1024 + gn) = v;
                }
            }
    } else {
        __nv_bfloat16* Ch = bat.Ch[z];
        __nv_bfloat16* Cl = bat.Cl[z];
#pragma unroll
        for (int mf = 0; mf < 4; mf++)
#pragma unroll
            for (int nf = 0; nf < 4; nf++) {
                int gn = bn + nb + nf * 8 + lc2;
                float2 bi = *(const float2*)(bias + gn);
#pragma unroll
                for (int half = 0; half < 2; half++) {
                    int gm = bm + mb + mf * 16 + lr4 + half * 8;
                    if (gm < M) {
                        float vx = acc[mf][nf][half * 2 + 0] + bi.x;
                        float vy = acc[mf][nf][half * 2 + 1] + bi.y;
                        __nv_bfloat16 hx = __float2bfloat16(vx);
                        __nv_bfloat16 hy = __float2bfloat16(vy);
                        __nv_bfloat162 hv; hv.x = hx; hv.y = hy;
                        __nv_bfloat162 lv;
                        lv.x = __float2bfloat16(vx - __bfloat162float(hx));
                        lv.y = __float2bfloat16(vy - __bfloat162float(hy));
                        *(__nv_bfloat162*)(Ch + (size_t)gm * 1024 + gn) = hv;
                        *(__nv_bfloat162*)(Cl + (size_t)gm * 1024 + gn) = lv;
                    }
                }
            }
    }
}

// ---------------------------------------------------------------------------
// Tensorized fused relative attention (flash-style, causal, bf16x3 MMA).
// CTA: 64 q-rows, 4 warps. Grid (bh, tiles) with heavy tiles scheduled first.
// ---------------------------------------------------------------------------
#define ATS      144                 // smem row stride bytes (72 bf16)
#define ST_KH    0
#define ST_KL    9216
#define ST_VH    18432
#define ST_VL    27648
#define ST_PH    36864               // 128 rows
#define ST_PL    55296
#define ST_UB    73728               // 64 floats
#define ST_BV    73984               // 127 floats (+pad)
#define ST_SIZE  74496
#define SM_Q     0                   // Qh 9216, Ql 9216
#define SM_ST    18432
#define SM_QPS   (18432 + 2 * ST_SIZE)          // fp32 64 x 132
#define SM_PRB   (SM_QPS + 33792)               // phs 9216, pls 9216
#define ATTN_SMEM_BYTES (SM_PRB + 18432)        // 219648

__device__ __forceinline__ void attn_load_stage(
    uint32_t stg, int tid,
    const __nv_bfloat16* Kh, const __nv_bfloat16* Kl,
    const __nv_bfloat16* Vh, const __nv_bfloat16* Vl,
    const __nv_bfloat16* Ph, const __nv_bfloat16* Pl)
{
#pragma unroll
    for (int j = 0; j < 4; j++) {
        int idx = tid + j * 128;
        int row = idx >> 3, g = idx & 7;
        const size_t go = (size_t)row * D + g * 8;
        uint32_t so = row * ATS + g * 16;
        cp16(stg + ST_KH + so, Kh + go, 16);
        cp16(stg + ST_KL + so, Kl + go, 16);
        cp16(stg + ST_VH + so, Vh + go, 16);
        cp16(stg + ST_VL + so, Vl + go, 16);
    }
#pragma unroll
    for (int j = 0; j < 8; j++) {
        int idx = tid + j * 128;
        if (idx < 1016) {                       // 127 rows x 8 segs
            int row = idx >> 3, g = idx & 7;
            const size_t go = (size_t)row * D + g * 8;
            uint32_t so = row * ATS + g * 16;
            cp16(stg + ST_PH + so, Ph + go, 16);
            cp16(stg + ST_PL + so, Pl + go, 16);
        }
    }
}

__global__ __launch_bounds__(128, 1) void attn_mma(
    const __nv_bfloat16* __restrict__ Qh, const __nv_bfloat16* __restrict__ Ql,
    const __nv_bfloat16* __restrict__ Kh, const __nv_bfloat16* __restrict__ Kl,
    const __nv_bfloat16* __restrict__ Vh, const __nv_bfloat16* __restrict__ Vl,
    const __nv_bfloat16* __restrict__ Ph, const __nv_bfloat16* __restrict__ Pl,
    const float* __restrict__ ubias, const float* __restrict__ Bv,
    __nv_bfloat16* __restrict__ Oh, __nv_bfloat16* __restrict__ Ol)
{
    extern __shared__ char smem[];
    const uint32_t sb = smem_to_u32(smem);
    const int tid  = threadIdx.x;
    const int wid  = tid >> 5;
    const int lane = tid & 31;
    const int st = (S / 64 - 1) - blockIdx.y;    // heavy tiles first
    const int b  = blockIdx.x >> 4;
    const int h  = blockIdx.x & 15;
    const int s0 = st * 64;

    const int li = lane >> 3, lr = lane & 7;
    const int a_off = ((li & 1) * 8 + lr) * ATS + (li >> 1) * 16;
    const int b_off = ((li >> 1) * 8 + lr) * ATS + (li & 1) * 16;

    const int r0 = wid * 16 + (lane >> 2);
    const int colbase = (lane & 3) * 2;

    // -------- prologue: Q tile + stage 0 --------
    {
        const __nv_bfloat16* Qgh = Qh + (size_t)(b * S + s0) * D + h * DK;
        const __nv_bfloat16* Qgl = Ql + (size_t)(b * S + s0) * D + h * DK;
#pragma unroll
        for (int j = 0; j < 4; j++) {
            int idx = tid + j * 128;
            int row = idx >> 3, g = idx & 7;
            const size_t go = (size_t)row * D + g * 8;
            uint32_t so = row * ATS + g * 16;
            cp16(sb + SM_Q + so, Qgh + go, 16);
            cp16(sb + SM_Q + 9216 + so, Qgl + go, 16);
        }
        const size_t kvoff = (size_t)(b * S) * D + h * DK;
        int lbase0 = -st * 64 + 960;
        attn_load_stage(sb + SM_ST, tid,
                        Kh + kvoff, Kl + kvoff, Vh + kvoff, Vl + kvoff,
                        Ph + (size_t)lbase0 * D + h * DK,
                        Pl + (size_t)lbase0 * D + h * DK);
        float* ubS = (float*)(smem + SM_ST + ST_UB);
        float* bvS = (float*)(smem + SM_ST + ST_BV);
        if (tid < 64)  ubS[tid] = ubias[(b * H + h) * S + tid];
        if (tid < 127) bvS[tid] = Bv[h * L + lbase0 + tid];
        cp_commit();
    }

    float cO[8][4];
#pragma unroll
    for (int nf = 0; nf < 8; nf++)
#pragma unroll
        for (int e = 0; e < 4; e++) cO[nf][e] = 0.f;
    float mrow[2] = {-1e30f, -1e30f};
    float lsum[2] = {0.f, 0.f};

    for (int zt = 0; zt <= st; zt++) {
        const int s = zt & 1;
        const uint32_t stg = sb + SM_ST + s * ST_SIZE;

        cp_wait<0>();
        __syncthreads();

        if (zt < st) {
            const int z1 = (zt + 1) * 64;
            const int lb1 = (zt + 1 - st) * 64 + 960;
            const size_t kvoff = (size_t)(b * S + z1) * D + h * DK;
            uint32_t nstg = sb + SM_ST + (s ^ 1) * ST_SIZE;
            attn_load_stage(nstg, tid,
                            Kh + kvoff, Kl + kvoff, Vh + kvoff, Vl + kvoff,
                            Ph + (size_t)lb1 * D + h * DK,
                            Pl + (size_t)lb1 * D + h * DK);
            float* ubS = (float*)(smem + SM_ST + (s ^ 1) * ST_SIZE + ST_UB);
            float* bvS = (float*)(smem + SM_ST + (s ^ 1) * ST_SIZE + ST_BV);
            if (tid < 64)  ubS[tid] = ubias[(b * H + h) * S + z1 + tid];
            if (tid < 127) bvS[tid] = Bv[h * L + lb1 + tid];
            cp_commit();
        }

        // -------- QP (64x128) and QK (64x64) MMA, bf16x3 --------
        float cQP[16][4], cQK[8][4];
#pragma unroll
        for (int nf = 0; nf < 16; nf++)
#pragma unroll
            for (int e = 0; e < 4; e++) cQP[nf][e] = 0.f;
#pragma unroll
        for (int nf = 0; nf < 8; nf++)
#pragma unroll
            for (int e = 0; e < 4; e++) cQK[nf][e] = 0.f;

#pragma unroll
        for (int k16 = 0; k16 < 4; k16++) {
            const int ko = k16 * 32;
            uint32_t qh[4], ql[4];
            ldsm4(qh, sb + SM_Q + wid * 2304 + a_off + ko);
            ldsm4(ql, sb + SM_Q + 9216 + wid * 2304 + a_off + ko);
#pragma unroll
            for (int n16 = 0; n16 < 4; n16++) {
                uint32_t kb[4], kl2[4];
                ldsm4(kb,  stg + ST_KH + b_off + n16 * 2304 + ko);
                ldsm4(kl2, stg + ST_KL + b_off + n16 * 2304 + ko);
#pragma unroll
                for (int sub = 0; sub < 2; sub++) {
                    const int nf = n16 * 2 + sub;
                    mma16816(cQK[nf], qh, &kb[sub * 2]);
                    mma16816(cQK[nf], qh, &kl2[sub * 2]);
                    mma16816(cQK[nf], ql, &kb[sub * 2]);
                }
            }
#pragma unroll
            for (int n16 = 0; n16 < 8; n16++) {
                uint32_t pb[4], pl2[4];
                ldsm4(pb,  stg + ST_PH + b_off + n16 * 2304 + ko);
                ldsm4(pl2, stg + ST_PL + b_off + n16 * 2304 + ko);
#pragma unroll
                for (int sub = 0; sub < 2; sub++) {
                    const int nf = n16 * 2 + sub;
                    mma16816(cQP[nf], qh, &pb[sub * 2]);
                    mma16816(cQP[nf], qh, &pl2[sub * 2]);
                    mma16816(cQP[nf], ql, &pb[sub * 2]);
                }
            }
        }

        // spill QP to smem for the Toeplitz gather (warp-local rows)
        float* QPs = (float*)(smem + SM_QPS);
#pragma unroll
        for (int nf = 0; nf < 16; nf++) {
            int j0 = nf * 8 + colbase;
            *(float2*)&QPs[r0 * 132 + j0]       = make_float2(cQP[nf][0], cQP[nf][1]);
            *(float2*)&QPs[(r0 + 8) * 132 + j0] = make_float2(cQP[nf][2], cQP[nf][3]);
        }
        __syncwarp();

        // -------- logits + online softmax --------
        const float* ubS = (const float*)(smem + SM_ST + s * ST_SIZE + ST_UB);
        const float* bvS = (const float*)(smem + SM_ST + s * ST_SIZE + ST_BV);
        const int p0 = 63 - r0;
        const int p1 = 55 - r0;
        float tm0 = -1e30f, tm1 = -1e30f;
#pragma unroll
        for (int nf = 0; nf < 8; nf++) {
            int j0 = nf * 8 + colbase, j1 = j0 + 1;
            float v0 = (cQK[nf][0] + QPs[r0 * 132 + j0 + p0] + ubS[j0] + bvS[j0 + p0]) * 0.125f;
            float v1 = (cQK[nf][1] + QPs[r0 * 132 + j1 + p0] + ubS[j1] + bvS[j1 + p0]) * 0.125f;
            float v2 = (cQK[nf][2] + QPs[(r0 + 8) * 132 + j0 + p1] + ubS[j0] + bvS[j0 + p1]) * 0.125f;
            float v3 = (cQK[nf][3] + QPs[(r0 + 8) * 132 + j1 + p1] + ubS[j1] + bvS[j1 + p1]) * 0.125f;
            if (zt == st) {
                if (j0 > r0) v0 = -1e30f;
                if (j1 > r0) v1 = -1e30f;
                if (j0 > r0 + 8) v2 = -1e30f;
                if (j1 > r0 + 8) v3 = -1e30f;
            }
            cQK[nf][0] = v0; cQK[nf][1] = v1; cQK[nf][2] = v2; cQK[nf][3] = v3;
            tm0 = fmaxf(tm0, fmaxf(v0, v1));
            tm1 = fmaxf(tm1, fmaxf(v2, v3));
        }
        tm0 = fmaxf(tm0, __shfl_xor_sync(0xffffffffu, tm0, 1));
        tm0 = fmaxf(tm0, __shfl_xor_sync(0xffffffffu, tm0, 2));
        tm1 = fmaxf(tm1, __shfl_xor_sync(0xffffffffu, tm1, 1));
        tm1 = fmaxf(tm1, __shfl_xor_sync(0xffffffffu, tm1, 2));

        float nm0 = fmaxf(mrow[0], tm0), nm1 = fmaxf(mrow[1], tm1);
        float sc0 = __expf(mrow[0] - nm0), sc1 = __expf(mrow[1] - nm1);

        __nv_bfloat16* phs = (__nv_bfloat16*)(smem + SM_PRB);
        __nv_bfloat16* pls = (__nv_bfloat16*)(smem + SM_PRB + 9216);
        float ps0 = 0.f, ps1 = 0.f;
#pragma unroll
        for (int nf = 0; nf < 8; nf++) {
            int j0 = nf * 8 + colbase;
            float e0 = __expf(cQK[nf][0] - nm0);
            float e1 = __expf(cQK[nf][1] - nm0);
            float e2 = __expf(cQK[nf][2] - nm1);
            float e3 = __expf(cQK[nf][3] - nm1);
            ps0 += e0 + e1;
            ps1 += e2 + e3;
            __nv_bfloat16 h0 = __float2bfloat16(e0), h1 = __float2bfloat16(e1);
            __nv_bfloat16 h2 = __float2bfloat16(e2), h3 = __float2bfloat16(e3);
            __nv_bfloat162 hv, lv;
            hv.x = h0; hv.y = h1;
            lv.x = __float2bfloat16(e0 - __bfloat162float(h0));
            lv.y = __float2bfloat16(e1 - __bfloat162float(h1));
            *(__nv_bfloat162*)&phs[r0 * 72 + j0] = hv;
            *(__nv_bfloat162*)&pls[r0 * 72 + j0] = lv;
            hv.x = h2; hv.y = h3;
            lv.x = __float2bfloat16(e2 - __bfloat162float(h2));
            lv.y = __float2bfloat16(e3 - __bfloat162float(h3));
            *(__nv_bfloat162*)&phs[(r0 + 8) * 72 + j0] = hv;
            *(__nv_bfloat162*)&pls[(r0 + 8) * 72 + j0] = lv;
        }
        ps0 += __shfl_xor_sync(0xffffffffu, ps0, 1);
        ps0 += __shfl_xor_sync(0xffffffffu, ps0, 2);
        ps1 += __shfl_xor_sync(0xffffffffu, ps1, 1);
        ps1 += __shfl_xor_sync(0xffffffffu, ps1, 2);
        lsum[0] = lsum[0] * sc0 + ps0;
        lsum[1] = lsum[1] * sc1 + ps1;
        mrow[0] = nm0; mrow[1] = nm1;

#pragma unroll
        for (int nf = 0; nf < 8; nf++) {
            cO[nf][0] *= sc0; cO[nf][1] *= sc0;
            cO[nf][2] *= sc1; cO[nf][3] *= sc1;
        }
        __syncwarp();

        // -------- PV MMA (probs x V), bf16x3 --------
#pragma unroll
        for (int k16 = 0; k16 < 4; k16++) {
            const int ko = k16 * 32;
            uint32_t aph[4], apl[4];
            ldsm4(aph, sb + SM_PRB + wid * 2304 + a_off + ko);
            ldsm4(apl, sb + SM_PRB + 9216 + wid * 2304 + a_off + ko);
#pragma unroll
            for (int n16 = 0; n16 < 4; n16++) {
                uint32_t vb[4], vl2[4];
                ldsm4t(vb,  stg + ST_VH + a_off + k16 * 2304 + n16 * 32);
                ldsm4t(vl2, stg + ST_VL + a_off + k16 * 2304 + n16 * 32);
#pragma unroll
                for (int sub = 0; sub < 2; sub++) {
                    const int nf = n16 * 2 + sub;
                    mma16816(cO[nf], aph, &vb[sub * 2]);
                    mma16816(cO[nf], aph, &vl2[sub * 2]);
                    mma16816(cO[nf], apl, &vb[sub * 2]);
                }
            }
        }
    }

    // -------- output: bf16 hi/lo pairs --------
    const float i0 = 1.f / lsum[0];
    const float i1 = 1.f / lsum[1];
    const size_t row0 = (size_t)(b * S + s0 + r0);
    const size_t row1 = row0 + 8;
#pragma unroll
    for (int nf = 0; nf < 8; nf++) {
        int col = h * DK + nf * 8 + colbase;
        float o0 = cO[nf][0] * i0, o1 = cO[nf][1] * i0;
        float o2 = cO[nf][2] * i1, o3 = cO[nf][3] * i1;
        __nv_bfloat16 h0 = __float2bfloat16(o0), h1 = __float2bfloat16(o1);
        __nv_bfloat16 h2 = __float2bfloat16(o2), h3 = __float2bfloat16(o3);
        __nv_bfloat162 hv, lv;
        hv.x = h0; hv.y = h1;
        lv.x = __float2bfloat16(o0 - __bfloat162float(h0));
        lv.y = __float2bfloat16(o1 - __bfloat162float(h1));
        *(__nv_bfloat162*)(Oh + row0 * D + col) = hv;
        *(__nv_bfloat162*)(Ol + row0 * D + col) = lv;
        hv.x = h2; hv.y = h3;
        lv.x = __float2bfloat16(o2 - __bfloat162float(h2));
        lv.y = __float2bfloat16(o3 - __bfloat162float(h3));
        *(__nv_bfloat162*)(Oh + row1 * D + col) = hv;
        *(__nv_bfloat162*)(Ol + row1 * D + col) = lv;
    }
}

// ---------------------------------------------------------------------------
// Launch
// ---------------------------------------------------------------------------
extern "C" void kernel_launch(void* const* d_in, const int* in_sizes, int n_in,
                              void* d_out, int out_size)
{
    const float* x      = (const float*)d_in[0];
    const float* Wq     = (const float*)d_in[1];
    const float* bq     = (const float*)d_in[2];
    const float* Wk     = (const float*)d_in[3];
    const float* bk     = (const float*)d_in[4];
    const float* Wv     = (const float*)d_in[5];
    const float* bv     = (const float*)d_in[6];
    const float* Wr     = (const float*)d_in[7];
    const float* br     = (const float*)d_in[8];
    const float* rel_u  = (const float*)d_in[9];
    const float* rel_v  = (const float*)d_in[10];
    const float* Wo     = (const float*)d_in[11];
    const float* bo     = (const float*)d_in[12];
    const float* relpos = (const float*)d_in[13];
    float* out = (float*)d_out;

    float *ubb, *bvb, *uwb, *vwb, *cuvb;
    cudaGetSymbolAddress((void**)&ubb,  g_ub);
    cudaGetSymbolAddress((void**)&bvb,  g_Bv);
    cudaGetSymbolAddress((void**)&uwb,  g_uw);
    cudaGetSymbolAddress((void**)&vwb,  g_vw);
    cudaGetSymbolAddress((void**)&cuvb, g_cuv);

    __nv_bfloat16 *xh, *xl, *Rh, *Rl, *Wsh, *Wsl, *vh, *vl;
    __nv_bfloat16 *Qbh, *Qbl, *Kbh, *Kbl, *Vbh, *Vbl, *Pbh, *Pbl;
    cudaGetSymbolAddress((void**)&xh,  g_xh);
    cudaGetSymbolAddress((void**)&xl,  g_xl);
    cudaGetSymbolAddress((void**)&Rh,  g_Rh);
    cudaGetSymbolAddress((void**)&Rl,  g_Rl);
    cudaGetSymbolAddress((void**)&Wsh, g_Wsh);
    cudaGetSymbolAddress((void**)&Wsl, g_Wsl);
    cudaGetSymbolAddress((void**)&vh,  g_vh);
    cudaGetSymbolAddress((void**)&vl,  g_vl);
    cudaGetSymbolAddress((void**)&Qbh, g_Qbh);
    cudaGetSymbolAddress((void**)&Qbl, g_Qbl);
    cudaGetSymbolAddress((void**)&Kbh, g_Kbh);
    cudaGetSymbolAddress((void**)&Kbl, g_Kbl);
    cudaGetSymbolAddress((void**)&Vbh, g_Vbh);
    cudaGetSymbolAddress((void**)&Vbl, g_Vbl);
    cudaGetSymbolAddress((void**)&Pbh, g_Pbh);
    cudaGetSymbolAddress((void**)&Pbl, g_Pbl);

    const float* R = relpos + (size_t)1 * D;   // rows [1, 2048)

    // --- splits + rel contractions ---
    split_kernel<<<(BS * D + 255) / 256, 256>>>(x, xh, xl, BS * D);
    SplitBatch sw;
    sw.src[0] = Wq; sw.src[1] = Wk; sw.src[2] = Wv; sw.src[3] = Wr; sw.src[4] = Wo;
    splitW_kernel<<<dim3(D * D / 256, 5), 256>>>(sw, Wsh, Wsl);
    split_kernel<<<(LP * D + 255) / 256, 256>>>(R, Rh, Rl, LP * D);
    contract_w<<<2 * H * D / 256, 256>>>(Wr, rel_u, rel_v, uwb, vwb);
    contract_c<<<1, 32>>>(br, rel_u, rel_v, cuvb);

    // --- ubias / Bv via rank-16 GEMMs (exact fp32) ---
    rank16_kernel<<<(BS + 7) / 8, 256>>>(x, uwb, cuvb, ubb, BS, 0);
    rank16_kernel<<<(LP + 7) / 8, 256>>>(R, vwb, cuvb, bvb, LP, 1);

    cudaFuncSetAttribute(gemm_tc, cudaFuncAttributeMaxDynamicSharedMemorySize,
                         GEMM_SMEM);

    // --- Q/K/V + P projections (merged, grid.z = 4) ---
    GemmBatch b1 = {};
    b1.Wh[0] = Wsh + 0 * (size_t)D * D; b1.Wl[0] = Wsl + 0 * (size_t)D * D;
    b1.bias[0] = bq; b1.mode[0] = 1; b1.Ch[0] = Qbh; b1.Cl[0] = Qbl;
    b1.Wh[1] = Wsh + 1 * (size_t)D * D; b1.Wl[1] = Wsl + 1 * (size_t)D * D;
    b1.bias[1] = bk; b1.mode[1] = 1; b1.Ch[1] = Kbh; b1.Cl[1] = Kbl;
    b1.Wh[2] = Wsh + 2 * (size_t)D * D; b1.Wl[2] = Wsl + 2 * (size_t)D * D;
    b1.bias[2] = bv; b1.mode[2] = 1; b1.Ch[2] = Vbh; b1.Cl[2] = Vbl;
    b1.Wh[3] = Wsh + 1 * (size_t)D * D; b1.Wl[3] = Wsl + 1 * (size_t)D * D;
    b1.bias[3] = bk; b1.mode[3] = 1; b1.Ch[3] = Pbh; b1.Cl[3] = Pbl;
    gemm_tc<<<dim3(8, 32, 4), 256, GEMM_SMEM>>>(xh, xl, Rh, Rl, b1, BS, LP, 3);

    // --- tensorized attention (heavy tiles first) ---
    cudaFuncSetAttribute(attn_mma, cudaFuncAttributeMaxDynamicSharedMemorySize,
                         ATTN_SMEM_BYTES);
    attn_mma<<<dim3(B * H, S / 64), 128, ATTN_SMEM_BYTES>>>(
        Qbh, Qbl, Kbh, Kbl, Vbh, Vbl, Pbh, Pbl, ubb, bvb, vh, vl);

    // --- output projection (fp32 out) ---
    GemmBatch b3 = {};
    b3.Wh[0] = Wsh + 4 * (size_t)D * D; b3.Wl[0] = Wsl + 4 * (size_t)D * D;
    b3.bias[0] = bo; b3.mode[0] = 0; b3.C[0] = out;
    gemm_tc<<<dim3(8, 32, 1), 256, GEMM_SMEM>>>(vh, vl, nullptr, nullptr, b3, BS, BS, 1);
}

// round 11
// speedup vs baseline: 1.3824x; 1.3824x over previous
#include <cuda_runtime.h>
#include <cuda_bf16.h>
#include <cstdint>

// Problem constants
#define B 4
#define S 1024
#define D 1024
#define H 16
#define DK 64
#define L 2047          // 2*S - 1
#define LP 1088         // P/PR rows actually used by attention (max read 1086)
#define BS (B*S)        // 4096

// ---------------------------------------------------------------------------
// Scratch (static device globals; no runtime allocation allowed)
// ---------------------------------------------------------------------------
__device__ float g_KR[BS * D];
__device__ float g_PR[L * D];
__device__ float g_ub[B * H * S];
__device__ float g_Bv[H * L];

// bf16 hi/lo splits (inputs to tensor-core GEMMs)
__device__ __nv_bfloat16 g_xh[BS * D], g_xl[BS * D];
__device__ __nv_bfloat16 g_Rh[L * D],  g_Rl[L * D];
__device__ __nv_bfloat16 g_Wsh[5 * D * D], g_Wsl[5 * D * D];   // q,k,v,r,o

// bf16 hi/lo GEMM outputs (attention inputs)
__device__ __nv_bfloat16 g_Qbh[BS * D], g_Qbl[BS * D];
__device__ __nv_bfloat16 g_Kbh[BS * D], g_Kbl[BS * D];
__device__ __nv_bfloat16 g_Vbh[BS * D], g_Vbl[BS * D];
__device__ __nv_bfloat16 g_Pbh[L * D],  g_Pbl[L * D];

// attention output (bf16 pairs; input to out-projection)
__device__ __nv_bfloat16 g_vh[BS * D], g_vl[BS * D];

// ---------------------------------------------------------------------------
// PTX helpers: portable sm_80+ (ldmatrix / mma.sync / cp.async).
// ---------------------------------------------------------------------------
__device__ __forceinline__ uint32_t smem_to_u32(const void* p) {
    uint32_t a;
    asm("{ .reg .u64 t; cvta.to.shared.u64 t, %1; cvt.u32.u64 %0, t; }"
        : "=r"(a) : "l"(p));
    return a;
}

__device__ __forceinline__ void ldsm4(uint32_t* r, uint32_t addr) {
    asm volatile("ldmatrix.sync.aligned.m8n8.x4.shared.b16 {%0,%1,%2,%3}, [%4];"
                 : "=r"(r[0]), "=r"(r[1]), "=r"(r[2]), "=r"(r[3]) : "r"(addr));
}
__device__ __forceinline__ void ldsm4t(uint32_t* r, uint32_t addr) {
    asm volatile("ldmatrix.sync.aligned.m8n8.x4.trans.shared.b16 {%0,%1,%2,%3}, [%4];"
                 : "=r"(r[0]), "=r"(r[1]), "=r"(r[2]), "=r"(r[3]) : "r"(addr));
}

__device__ __forceinline__ void mma16816(float* d, const uint32_t* a,
                                         const uint32_t* b) {
    asm volatile(
        "mma.sync.aligned.m16n8k16.row.col.f32.bf16.bf16.f32 "
        "{%0,%1,%2,%3}, {%4,%5,%6,%7}, {%8,%9}, {%0,%1,%2,%3};"
        : "+f"(d[0]), "+f"(d[1]), "+f"(d[2]), "+f"(d[3])
        : "r"(a[0]), "r"(a[1]), "r"(a[2]), "r"(a[3]), "r"(b[0]), "r"(b[1]));
}

__device__ __forceinline__ void cp16(uint32_t dst, const void* src, int sz) {
    asm volatile("cp.async.cg.shared.global [%0], [%1], 16, %2;\n"
                 :: "r"(dst), "l"(src), "r"(sz));
}
__device__ __forceinline__ void cp_commit() {
    asm volatile("cp.async.commit_group;\n" ::: "memory");
}
template <int N> __device__ __forceinline__ void cp_wait() {
    asm volatile("cp.async.wait_group %0;\n" :: "n"(N) : "memory");
}

// ---------------------------------------------------------------------------
// fp32 -> bf16 hi/lo splits
// ---------------------------------------------------------------------------
__global__ void split_kernel(const float* __restrict__ s,
                             __nv_bfloat16* __restrict__ hi,
                             __nv_bfloat16* __restrict__ lo, int n)
{
    int i = blockIdx.x * 256 + threadIdx.x;
    if (i < n) {
        float x = s[i];
        __nv_bfloat16 h = __float2bfloat16(x);
        float r = x - __bfloat162float(h);
        hi[i] = h;
        lo[i] = __float2bfloat16(r);
    }
}

struct SplitBatch { const float* src[5]; };

__global__ void splitW_kernel(const SplitBatch sb,
                              __nv_bfloat16* __restrict__ hi,
                              __nv_bfloat16* __restrict__ lo)
{
    int z = blockIdx.y;
    int i = blockIdx.x * 256 + threadIdx.x;
    size_t off = (size_t)z * D * D + i;
    float x = sb.src[z][i];
    __nv_bfloat16 h = __float2bfloat16(x);
    hi[off] = h;
    lo[off] = __float2bfloat16(x - __bfloat162float(h));
}

// ---------------------------------------------------------------------------
// HMMA GEMM: C[M,1024] = A[M,1024] @ W[1024,1024]^T + bias
// bf16x3 compensation. mode 0: fp32 C;  mode 1: bf16 hi/lo pair outputs.
// z < 4: A = (Ah1, Al1), M = M1.  z >= 4: A = (Ah2, Al2), M = M2.
// ---------------------------------------------------------------------------
struct GemmBatch {
    const __nv_bfloat16* Wh[6];
    const __nv_bfloat16* Wl[6];
    const float* bias[6];
    float* C[6];
    __nv_bfloat16* Ch[6];
    __nv_bfloat16* Cl[6];
    int mode[6];
};

#define RS      40                   // bf16 elems per smem row (80 bytes)
#define TILE_B  (128 * RS * 2)       // 10240 B
#define STAGE_B (4 * TILE_B)
#define GEMM_SMEM (2 * STAGE_B)      // 81920
#define NC      32

__device__ __forceinline__ void load_chunk(
    uint32_t sbase, int tid,
    const __nv_bfloat16* Ah, const __nv_bfloat16* Al,
    const __nv_bfloat16* Wh, const __nv_bfloat16* Wl,
    int bm, int bn, int M, int c, int st)
{
    const int kbase = c * 32;
    const uint32_t stoff = sbase + st * STAGE_B;
#pragma unroll
    for (int t = 0; t < 4; t++) {
        const __nv_bfloat16* base = (t == 0) ? Ah : (t == 1) ? Al : (t == 2) ? Wh : Wl;
        const int rb = (t < 2) ? bm : bn;
#pragma unroll
        for (int j = 0; j < 2; j++) {
            int idx = tid + j * 256;
            int row = idx >> 2, g = idx & 3;
            int gr = rb + row;
            int sz = (t >= 2 || gr < M) ? 16 : 0;
            const void* src = base + (size_t)gr * 1024 + kbase + g * 8;
            uint32_t dst = stoff + t * TILE_B + row * 80 + g * 16;
            cp16(dst, src, sz);
        }
    }
}

__global__ __launch_bounds__(256, 2)
void gemm_tc(const __nv_bfloat16* __restrict__ Ah1,
             const __nv_bfloat16* __restrict__ Al1,
             const __nv_bfloat16* __restrict__ Ah2,
             const __nv_bfloat16* __restrict__ Al2,
             const GemmBatch bat, int M1, int M2)
{
    extern __shared__ char smem[];
    const uint32_t sbase = smem_to_u32(smem);
    const int tid  = threadIdx.x;
    const int wid  = tid >> 5;
    const int lane = tid & 31;
    const int bn = blockIdx.x * 128;
    const int bm = blockIdx.y * 128;
    const int z  = blockIdx.z;

    const __nv_bfloat16* Ah = (z < 4) ? Ah1 : Ah2;
    const __nv_bfloat16* Al = (z < 4) ? Al1 : Al2;
    const int M = (z < 4) ? M1 : M2;
    if (bm >= M) return;               // early-exit tail tiles (P/PR trim)

    const __nv_bfloat16* Wh = bat.Wh[z];
    const __nv_bfloat16* Wl = bat.Wl[z];

    const int mb = (wid >> 2) * 64;
    const int nb = (wid & 3) * 32;

    const int li = lane >> 3, lr = lane & 7;
    const int a_off = ((li & 1) * 8 + lr) * 80 + (li >> 1) * 16;
    const int b_off = ((li >> 1) * 8 + lr) * 80 + (li & 1) * 16;

    float acc[4][4][4];
#pragma unroll
    for (int mf = 0; mf < 4; mf++)
#pragma unroll
        for (int nf = 0; nf < 4; nf++)
#pragma unroll
            for (int e = 0; e < 4; e++) acc[mf][nf][e] = 0.f;

    load_chunk(sbase, tid, Ah, Al, Wh, Wl, bm, bn, M, 0, 0);
    cp_commit();

    for (int c = 0; c < NC; c++) {
        const int st = c & 1;
        cp_wait<0>();
        __syncthreads();
        if (c + 1 < NC) {
            load_chunk(sbase, tid, Ah, Al, Wh, Wl, bm, bn, M, c + 1, st ^ 1);
            cp_commit();
        }

        const uint32_t aH = sbase + st * STAGE_B + 0 * TILE_B + (mb)*80 + a_off;
        const uint32_t aL = aH + TILE_B;
        const uint32_t wH = sbase + st * STAGE_B + 2 * TILE_B + (nb)*80 + b_off;
        const uint32_t wL = wH + TILE_B;

#pragma unroll
        for (int k16 = 0; k16 < 2; k16++) {
            const int ko = k16 * 32;
            uint32_t ah[4][4], al[4][4], bh[2][4], bl[2][4];
#pragma unroll
            for (int mf = 0; mf < 4; mf++) {
                ldsm4(ah[mf], aH + mf * 16 * 80 + ko);
                ldsm4(al[mf], aL + mf * 16 * 80 + ko);
            }
#pragma unroll
            for (int n2 = 0; n2 < 2; n2++) {
                ldsm4(bh[n2], wH + n2 * 16 * 80 + ko);
                ldsm4(bl[n2], wL + n2 * 16 * 80 + ko);
            }
#pragma unroll
            for (int mf = 0; mf < 4; mf++)
#pragma unroll
                for (int nf = 0; nf < 4; nf++) {
                    const uint32_t* bph = &bh[nf >> 1][(nf & 1) * 2];
                    const uint32_t* bpl = &bl[nf >> 1][(nf & 1) * 2];
                    mma16816(acc[mf][nf], ah[mf], bph);
                    mma16816(acc[mf][nf], ah[mf], bpl);
                    mma16816(acc[mf][nf], al[mf], bph);
                }
        }
    }

    const float* bias = bat.bias[z];
    const int lr4 = lane >> 2, lc2 = (lane & 3) * 2;
    if (bat.mode[z] == 0) {
        float* C = bat.C[z];
#pragma unroll
        for (int mf = 0; mf < 4; mf++)
#pragma unroll
            for (int nf = 0; nf < 4; nf++) {
                int gn = bn + nb + nf * 8 + lc2;
                float2 bi = *(const float2*)(bias + gn);
                int gm0 = bm + mb + mf * 16 + lr4;
                if (gm0 < M) {
                    float2 v = make_float2(acc[mf][nf][0] + bi.x, acc[mf][nf][1] + bi.y);
                    *(float2*)(C + (size_t)gm0 * 1024 + gn) = v;
                }
                int gm1 = gm0 + 8;
                if (gm1 < M) {
                    float2 v = make_float2(acc[mf][nf][2] + bi.x, acc[mf][nf][3] + bi.y);
                    *(float2*)(C + (size_t)gm1 * 1024 + gn) = v;
                }
            }
    } else {
        __nv_bfloat16* Ch = bat.Ch[z];
        __nv_bfloat16* Cl = bat.Cl[z];
#pragma unroll
        for (int mf = 0; mf < 4; mf++)
#pragma unroll
            for (int nf = 0; nf < 4; nf++) {
                int gn = bn + nb + nf * 8 + lc2;
                float2 bi = *(const float2*)(bias + gn);
#pragma unroll
                for (int half = 0; half < 2; half++) {
                    int gm = bm + mb + mf * 16 + lr4 + half * 8;
                    if (gm < M) {
                        float vx = acc[mf][nf][half * 2 + 0] + bi.x;
                        float vy = acc[mf][nf][half * 2 + 1] + bi.y;
                        __nv_bfloat16 hx = __float2bfloat16(vx);
                        __nv_bfloat16 hy = __float2bfloat16(vy);
                        __nv_bfloat162 hv; hv.x = hx; hv.y = hy;
                        __nv_bfloat162 lv;
                        lv.x = __float2bfloat16(vx - __bfloat162float(hx));
                        lv.y = __float2bfloat16(vy - __bfloat162float(hy));
                        *(__nv_bfloat162*)(Ch + (size_t)gm * 1024 + gn) = hv;
                        *(__nv_bfloat162*)(Cl + (size_t)gm * 1024 + gn) = lv;
                    }
                }
            }
    }
}

// ---------------------------------------------------------------------------
// ubias / Bv reductions (fp32 inputs)
// ---------------------------------------------------------------------------
__global__ void ubias_kernel(const float* __restrict__ KR,
                             const float* __restrict__ rel_u,
                             float* __restrict__ ub)
{
    int idx = blockIdx.x * 256 + threadIdx.x;
    if (idx >= B * H * S) return;
    int z = idx & (S - 1);
    int h = (idx >> 10) & (H - 1);
    int b = idx >> 14;
    const float* kr = KR + ((size_t)(b * S + z)) * D + h * DK;
    const float* ru = rel_u + h * DK;
    float s = 0.f;
#pragma unroll
    for (int d = 0; d < DK; d++) s = fmaf(kr[d], ru[d], s);
    ub[idx] = s;
}

__global__ void bv_kernel(const float* __restrict__ PR,
                          const float* __restrict__ rel_v,
                          float* __restrict__ Bv)
{
    int idx = blockIdx.x * 256 + threadIdx.x;
    if (idx >= H * LP) return;
    int l = idx % LP;
    int h = idx / LP;
    const float* pr = PR + (size_t)l * D + h * DK;
    const float* rv = rel_v + h * DK;
    float s = 0.f;
#pragma unroll
    for (int d = 0; d < DK; d++) s = fmaf(pr[d], rv[d], s);
    Bv[h * L + l] = s;
}

// ---------------------------------------------------------------------------
// Tensorized fused relative attention (flash-style, causal, bf16x3 MMA).
// CTA: 64 q-rows, 4 warps, 2 CTAs/SM (single-stage KVP buffer, Q in regs,
// probs overlaid on the QP-spill buffer). Heavy tiles scheduled first.
// ---------------------------------------------------------------------------
#define ATS      144                 // smem row stride bytes (72 bf16)
#define ST_KH    0
#define ST_KL    9216
#define ST_VH    18432
#define ST_VL    27648
#define ST_PH    36864               // 127 rows used
#define ST_PL    55296
#define ST_UB    73728               // 64 floats
#define ST_BV    73984               // 127 floats
#define ST_SIZE  74496
#define SM_QPS   74496               // fp32 64 x 132 = 33792; probs overlay here
#define ATTN_SMEM_BYTES (SM_QPS + 33792)   // 108288 -> 2 CTAs/SM

__device__ __forceinline__ void attn_load_stage(
    uint32_t stg, int tid,
    const __nv_bfloat16* Kh, const __nv_bfloat16* Kl,
    const __nv_bfloat16* Vh, const __nv_bfloat16* Vl,
    const __nv_bfloat16* Ph, const __nv_bfloat16* Pl)
{
#pragma unroll
    for (int j = 0; j < 4; j++) {
        int idx = tid + j * 128;
        int row = idx >> 3, g = idx & 7;
        const size_t go = (size_t)row * D + g * 8;
        uint32_t so = row * ATS + g * 16;
        cp16(stg + ST_KH + so, Kh + go, 16);
        cp16(stg + ST_KL + so, Kl + go, 16);
        cp16(stg + ST_VH + so, Vh + go, 16);
        cp16(stg + ST_VL + so, Vl + go, 16);
    }
#pragma unroll
    for (int j = 0; j < 8; j++) {
        int idx = tid + j * 128;
        if (idx < 1016) {                       // 127 rows x 8 segs
            int row = idx >> 3, g = idx & 7;
            const size_t go = (size_t)row * D + g * 8;
            uint32_t so = row * ATS + g * 16;
            cp16(stg + ST_PH + so, Ph + go, 16);
            cp16(stg + ST_PL + so, Pl + go, 16);
        }
    }
}

__global__ __launch_bounds__(128, 2) void attn_mma(
    const __nv_bfloat16* __restrict__ Qh, const __nv_bfloat16* __restrict__ Ql,
    const __nv_bfloat16* __restrict__ Kh, const __nv_bfloat16* __restrict__ Kl,
    const __nv_bfloat16* __restrict__ Vh, const __nv_bfloat16* __restrict__ Vl,
    const __nv_bfloat16* __restrict__ Ph, const __nv_bfloat16* __restrict__ Pl,
    const float* __restrict__ ubias, const float* __restrict__ Bv,
    __nv_bfloat16* __restrict__ Oh, __nv_bfloat16* __restrict__ Ol)
{
    extern __shared__ char smem[];
    const uint32_t sb = smem_to_u32(smem);
    const int tid  = threadIdx.x;
    const int wid  = tid >> 5;
    const int lane = tid & 31;
    const int st = (S / 64 - 1) - blockIdx.y;    // heavy tiles first
    const int b  = blockIdx.x >> 4;
    const int h  = blockIdx.x & 15;
    const int s0 = st * 64;

    const int li = lane >> 3, lr = lane & 7;
    const int a_off = ((li & 1) * 8 + lr) * ATS + (li >> 1) * 16;
    const int b_off = ((li >> 1) * 8 + lr) * ATS + (li & 1) * 16;

    const int r0 = wid * 16 + (lane >> 2);
    const int colbase = (lane & 3) * 2;

    // -------- prologue: stage Q once, lift fragments to registers --------
    uint32_t qfh[4][4], qfl[4][4];
    {
        const __nv_bfloat16* Qgh = Qh + (size_t)(b * S + s0) * D + h * DK;
        const __nv_bfloat16* Qgl = Ql + (size_t)(b * S + s0) * D + h * DK;
#pragma unroll
        for (int j = 0; j < 4; j++) {
            int idx = tid + j * 128;
            int row = idx >> 3, g = idx & 7;
            const size_t go = (size_t)row * D + g * 8;
            uint32_t so = row * ATS + g * 16;
            cp16(sb + ST_KH + so, Qgh + go, 16);
            cp16(sb + ST_KL + so, Qgl + go, 16);
        }
        cp_commit();
        cp_wait<0>();
        __syncthreads();
#pragma unroll
        for (int k16 = 0; k16 < 4; k16++) {
            ldsm4(qfh[k16], sb + ST_KH + wid * 2304 + a_off + k16 * 32);
            ldsm4(qfl[k16], sb + ST_KL + wid * 2304 + a_off + k16 * 32);
        }
    }

    float cO[8][4];
#pragma unroll
    for (int nf = 0; nf < 8; nf++)
#pragma unroll
        for (int e = 0; e < 4; e++) cO[nf][e] = 0.f;
    float mrow[2] = {-1e30f, -1e30f};
    float lsum[2] = {0.f, 0.f};

    for (int zt = 0; zt <= st; zt++) {
        // stage-reuse barrier: previous iteration's reads (and the Q ldsm on
        // the first iteration) must finish before overwriting the stage.
        __syncthreads();

        const int z0 = zt * 64;
        const int lbase = (zt - st) * 64 + 960;
        const size_t kvoff = (size_t)(b * S + z0) * D + h * DK;
        attn_load_stage(sb, tid,
                        Kh + kvoff, Kl + kvoff, Vh + kvoff, Vl + kvoff,
                        Ph + (size_t)lbase * D + h * DK,
                        Pl + (size_t)lbase * D + h * DK);
        {
            float* ubS = (float*)(smem + ST_UB);
            float* bvS = (float*)(smem + ST_BV);
            if (tid < 64)  ubS[tid] = ubias[(b * H + h) * S + z0 + tid];
            if (tid < 127) bvS[tid] = Bv[h * L + lbase + tid];
        }
        cp_commit();
        cp_wait<0>();
        __syncthreads();

        // -------- QP (64x128) and QK (64x64) MMA, bf16x3, Q from regs ----
        float cQP[16][4], cQK[8][4];
#pragma unroll
        for (int nf = 0; nf < 16; nf++)
#pragma unroll
            for (int e = 0; e < 4; e++) cQP[nf][e] = 0.f;
#pragma unroll
        for (int nf = 0; nf < 8; nf++)
#pragma unroll
            for (int e = 0; e < 4; e++) cQK[nf][e] = 0.f;

#pragma unroll
        for (int k16 = 0; k16 < 4; k16++) {
            const int ko = k16 * 32;
#pragma unroll
            for (int n16 = 0; n16 < 4; n16++) {
                uint32_t kb[4], kl2[4];
                ldsm4(kb,  sb + ST_KH + b_off + n16 * 2304 + ko);
                ldsm4(kl2, sb + ST_KL + b_off + n16 * 2304 + ko);
#pragma unroll
                for (int sub = 0; sub < 2; sub++) {
                    const int nf = n16 * 2 + sub;
                    mma16816(cQK[nf], qfh[k16], &kb[sub * 2]);
                    mma16816(cQK[nf], qfh[k16], &kl2[sub * 2]);
                    mma16816(cQK[nf], qfl[k16], &kb[sub * 2]);
                }
            }
#pragma unroll
            for (int n16 = 0; n16 < 8; n16++) {
                uint32_t pb[4], pl2[4];
                ldsm4(pb,  sb + ST_PH + b_off + n16 * 2304 + ko);
                ldsm4(pl2, sb + ST_PL + b_off + n16 * 2304 + ko);
#pragma unroll
                for (int sub = 0; sub < 2; sub++) {
                    const int nf = n16 * 2 + sub;
                    mma16816(cQP[nf], qfh[k16], &pb[sub * 2]);
                    mma16816(cQP[nf], qfh[k16], &pl2[sub * 2]);
                    mma16816(cQP[nf], qfl[k16], &pb[sub * 2]);
                }
            }
        }

        // spill QP to smem for the Toeplitz gather (warp-local rows)
        float* QPs = (float*)(smem + SM_QPS);
#pragma unroll
        for (int nf = 0; nf < 16; nf++) {
            int j0 = nf * 8 + colbase;
            *(float2*)&QPs[r0 * 132 + j0]       = make_float2(cQP[nf][0], cQP[nf][1]);
            *(float2*)&QPs[(r0 + 8) * 132 + j0] = make_float2(cQP[nf][2], cQP[nf][3]);
        }
        __syncwarp();

        // -------- logits + online softmax --------
        const float* ubS = (const float*)(smem + ST_UB);
        const float* bvS = (const float*)(smem + ST_BV);
        const int p0 = 63 - r0;
        const int p1 = 55 - r0;
        float tm0 = -1e30f, tm1 = -1e30f;
#pragma unroll
        for (int nf = 0; nf < 8; nf++) {
            int j0 = nf * 8 + colbase, j1 = j0 + 1;
            float v0 = (cQK[nf][0] + QPs[r0 * 132 + j0 + p0] + ubS[j0] + bvS[j0 + p0]) * 0.125f;
            float v1 = (cQK[nf][1] + QPs[r0 * 132 + j1 + p0] + ubS[j1] + bvS[j1 + p0]) * 0.125f;
            float v2 = (cQK[nf][2] + QPs[(r0 + 8) * 132 + j0 + p1] + ubS[j0] + bvS[j0 + p1]) * 0.125f;
            float v3 = (cQK[nf][3] + QPs[(r0 + 8) * 132 + j1 + p1] + ubS[j1] + bvS[j1 + p1]) * 0.125f;
            if (zt == st) {
                if (j0 > r0) v0 = -1e30f;
                if (j1 > r0) v1 = -1e30f;
                if (j0 > r0 + 8) v2 = -1e30f;
                if (j1 > r0 + 8) v3 = -1e30f;
            }
            cQK[nf][0] = v0; cQK[nf][1] = v1; cQK[nf][2] = v2; cQK[nf][3] = v3;
            tm0 = fmaxf(tm0, fmaxf(v0, v1));
            tm1 = fmaxf(tm1, fmaxf(v2, v3));
        }
        tm0 = fmaxf(tm0, __shfl_xor_sync(0xffffffffu, tm0, 1));
        tm0 = fmaxf(tm0, __shfl_xor_sync(0xffffffffu, tm0, 2));
        tm1 = fmaxf(tm1, __shfl_xor_sync(0xffffffffu, tm1, 1));
        tm1 = fmaxf(tm1, __shfl_xor_sync(0xffffffffu, tm1, 2));

        float nm0 = fmaxf(mrow[0], tm0), nm1 = fmaxf(mrow[1], tm1);
        float sc0 = __expf(mrow[0] - nm0), sc1 = __expf(mrow[1] - nm1);

        // overlay safety: all QPs reads (any warp) precede any probs write
        __syncthreads();

        __nv_bfloat16* phs = (__nv_bfloat16*)(smem + SM_QPS);
        __nv_bfloat16* pls = (__nv_bfloat16*)(smem + SM_QPS + 9216);
        float ps0 = 0.f, ps1 = 0.f;
#pragma unroll
        for (int nf = 0; nf < 8; nf++) {
            int j0 = nf * 8 + colbase;
            float e0 = __expf(cQK[nf][0] - nm0);
            float e1 = __expf(cQK[nf][1] - nm0);
            float e2 = __expf(cQK[nf][2] - nm1);
            float e3 = __expf(cQK[nf][3] - nm1);
            ps0 += e0 + e1;
            ps1 += e2 + e3;
            __nv_bfloat16 h0 = __float2bfloat16(e0), h1 = __float2bfloat16(e1);
            __nv_bfloat16 h2 = __float2bfloat16(e2), h3 = __float2bfloat16(e3);
            __nv_bfloat162 hv, lv;
            hv.x = h0; hv.y = h1;
            lv.x = __float2bfloat16(e0 - __bfloat162float(h0));
            lv.y = __float2bfloat16(e1 - __bfloat162float(h1));
            *(__nv_bfloat162*)&phs[r0 * 72 + j0] = hv;
            *(__nv_bfloat162*)&pls[r0 * 72 + j0] = lv;
            hv.x = h2; hv.y = h3;
            lv.x = __float2bfloat16(e2 - __bfloat162float(h2));
            lv.y = __float2bfloat16(e3 - __bfloat162float(h3));
            *(__nv_bfloat162*)&phs[(r0 + 8) * 72 + j0] = hv;
            *(__nv_bfloat162*)&pls[(r0 + 8) * 72 + j0] = lv;
        }
        ps0 += __shfl_xor_sync(0xffffffffu, ps0, 1);
        ps0 += __shfl_xor_sync(0xffffffffu, ps0, 2);
        ps1 += __shfl_xor_sync(0xffffffffu, ps1, 1);
        ps1 += __shfl_xor_sync(0xffffffffu, ps1, 2);
        lsum[0] = lsum[0] * sc0 + ps0;
        lsum[1] = lsum[1] * sc1 + ps1;
        mrow[0] = nm0; mrow[1] = nm1;

#pragma unroll
        for (int nf = 0; nf < 8; nf++) {
            cO[nf][0] *= sc0; cO[nf][1] *= sc0;
            cO[nf][2] *= sc1; cO[nf][3] *= sc1;
        }
        __syncwarp();

        // -------- PV MMA (probs x V), bf16x3 --------
#pragma unroll
        for (int k16 = 0; k16 < 4; k16++) {
            const int ko = k16 * 32;
            uint32_t aph[4], apl[4];
            ldsm4(aph, sb + SM_QPS + wid * 2304 + a_off + ko);
            ldsm4(apl, sb + SM_QPS + 9216 + wid * 2304 + a_off + ko);
#pragma unroll
            for (int n16 = 0; n16 < 4; n16++) {
                uint32_t vb[4], vl2[4];
                ldsm4t(vb,  sb + ST_VH + a_off + k16 * 2304 + n16 * 32);
                ldsm4t(vl2, sb + ST_VL + a_off + k16 * 2304 + n16 * 32);
#pragma unroll
                for (int sub = 0; sub < 2; sub++) {
                    const int nf = n16 * 2 + sub;
                    mma16816(cO[nf], aph, &vb[sub * 2]);
                    mma16816(cO[nf], aph, &vl2[sub * 2]);
                    mma16816(cO[nf], apl, &vb[sub * 2]);
                }
            }
        }
    }

    // -------- output: bf16 hi/lo pairs --------
    const float i0 = 1.f / lsum[0];
    const float i1 = 1.f / lsum[1];
    const size_t row0 = (size_t)(b * S + s0 + r0);
    const size_t row1 = row0 + 8;
#pragma unroll
    for (int nf = 0; nf < 8; nf++) {
        int col = h * DK + nf * 8 + colbase;
        float o0 = cO[nf][0] * i0, o1 = cO[nf][1] * i0;
        float o2 = cO[nf][2] * i1, o3 = cO[nf][3] * i1;
        __nv_bfloat16 h0 = __float2bfloat16(o0), h1 = __float2bfloat16(o1);
        __nv_bfloat16 h2 = __float2bfloat16(o2), h3 = __float2bfloat16(o3);
        __nv_bfloat162 hv, lv;
        hv.x = h0; hv.y = h1;
        lv.x = __float2bfloat16(o0 - __bfloat162float(h0));
        lv.y = __float2bfloat16(o1 - __bfloat162float(h1));
        *(__nv_bfloat162*)(Oh + row0 * D + col) = hv;
        *(__nv_bfloat162*)(Ol + row0 * D + col) = lv;
        hv.x = h2; hv.y = h3;
        lv.x = __float2bfloat16(o2 - __bfloat162float(h2));
        lv.y = __float2bfloat16(o3 - __bfloat162float(h3));
        *(__nv_bfloat162*)(Oh + row1 * D + col) = hv;
        *(__nv_bfloat162*)(Ol + row1 * D + col) = lv;
    }
}

// ---------------------------------------------------------------------------
// Launch
// ---------------------------------------------------------------------------
extern "C" void kernel_launch(void* const* d_in, const int* in_sizes, int n_in,
                              void* d_out, int out_size)
{
    const float* x      = (const float*)d_in[0];
    const float* Wq     = (const float*)d_in[1];
    const float* bq     = (const float*)d_in[2];
    const float* Wk     = (const float*)d_in[3];
    const float* bk     = (const float*)d_in[4];
    const float* Wv     = (const float*)d_in[5];
    const float* bv     = (const float*)d_in[6];
    const float* Wr     = (const float*)d_in[7];
    const float* br     = (const float*)d_in[8];
    const float* rel_u  = (const float*)d_in[9];
    const float* rel_v  = (const float*)d_in[10];
    const float* Wo     = (const float*)d_in[11];
    const float* bo     = (const float*)d_in[12];
    const float* relpos = (const float*)d_in[13];
    float* out = (float*)d_out;

    float *KRb, *PRb, *ubb, *bvb;
    cudaGetSymbolAddress((void**)&KRb, g_KR);
    cudaGetSymbolAddress((void**)&PRb, g_PR);
    cudaGetSymbolAddress((void**)&ubb, g_ub);
    cudaGetSymbolAddress((void**)&bvb, g_Bv);

    __nv_bfloat16 *xh, *xl, *Rh, *Rl, *Wsh, *Wsl, *vh, *vl;
    __nv_bfloat16 *Qbh, *Qbl, *Kbh, *Kbl, *Vbh, *Vbl, *Pbh, *Pbl;
    cudaGetSymbolAddress((void**)&xh,  g_xh);
    cudaGetSymbolAddress((void**)&xl,  g_xl);
    cudaGetSymbolAddress((void**)&Rh,  g_Rh);
    cudaGetSymbolAddress((void**)&Rl,  g_Rl);
    cudaGetSymbolAddress((void**)&Wsh, g_Wsh);
    cudaGetSymbolAddress((void**)&Wsl, g_Wsl);
    cudaGetSymbolAddress((void**)&vh,  g_vh);
    cudaGetSymbolAddress((void**)&vl,  g_vl);
    cudaGetSymbolAddress((void**)&Qbh, g_Qbh);
    cudaGetSymbolAddress((void**)&Qbl, g_Qbl);
    cudaGetSymbolAddress((void**)&Kbh, g_Kbh);
    cudaGetSymbolAddress((void**)&Kbl, g_Kbl);
    cudaGetSymbolAddress((void**)&Vbh, g_Vbh);
    cudaGetSymbolAddress((void**)&Vbl, g_Vbl);
    cudaGetSymbolAddress((void**)&Pbh, g_Pbh);
    cudaGetSymbolAddress((void**)&Pbl, g_Pbl);

    const float* R = relpos + (size_t)1 * D;   // rows [1, 2048)

    // --- splits ---
    split_kernel<<<(BS * D + 255) / 256, 256>>>(x, xh, xl, BS * D);
    SplitBatch sw;
    sw.src[0] = Wq; sw.src[1] = Wk; sw.src[2] = Wv; sw.src[3] = Wr; sw.src[4] = Wo;
    splitW_kernel<<<dim3(D * D / 256, 5), 256>>>(sw, Wsh, Wsl);
    split_kernel<<<(LP * D + 255) / 256, 256>>>(R, Rh, Rl, LP * D);

    cudaFuncSetAttribute(gemm_tc, cudaFuncAttributeMaxDynamicSharedMemorySize,
                         GEMM_SMEM);

    // --- Q/K/V/KR + P/PR projections (merged, grid.z = 6) ---
    GemmBatch b1 = {};
    b1.Wh[0] = Wsh + 0 * (size_t)D * D; b1.Wl[0] = Wsl + 0 * (size_t)D * D;
    b1.bias[0] = bq; b1.mode[0] = 1; b1.Ch[0] = Qbh; b1.Cl[0] = Qbl;
    b1.Wh[1] = Wsh + 1 * (size_t)D * D; b1.Wl[1] = Wsl + 1 * (size_t)D * D;
    b1.bias[1] = bk; b1.mode[1] = 1; b1.Ch[1] = Kbh; b1.Cl[1] = Kbl;
    b1.Wh[2] = Wsh + 2 * (size_t)D * D; b1.Wl[2] = Wsl + 2 * (size_t)D * D;
    b1.bias[2] = bv; b1.mode[2] = 1; b1.Ch[2] = Vbh; b1.Cl[2] = Vbl;
    b1.Wh[3] = Wsh + 3 * (size_t)D * D; b1.Wl[3] = Wsl + 3 * (size_t)D * D;
    b1.bias[3] = br; b1.mode[3] = 0; b1.C[3] = KRb;
    b1.Wh[4] = Wsh + 1 * (size_t)D * D; b1.Wl[4] = Wsl + 1 * (size_t)D * D;
    b1.bias[4] = bk; b1.mode[4] = 1; b1.Ch[4] = Pbh; b1.Cl[4] = Pbl;
    b1.Wh[5] = Wsh + 3 * (size_t)D * D; b1.Wl[5] = Wsl + 3 * (size_t)D * D;
    b1.bias[5] = br; b1.mode[5] = 0; b1.C[5] = PRb;
    gemm_tc<<<dim3(8, 32, 6), 256, GEMM_SMEM>>>(xh, xl, Rh, Rl, b1, BS, LP);

    ubias_kernel<<<(B * H * S + 255) / 256, 256>>>(KRb, rel_u, ubb);
    bv_kernel<<<(H * LP + 255) / 256, 256>>>(PRb, rel_v, bvb);

    // --- tensorized attention (2 CTAs/SM, heavy tiles first) ---
    cudaFuncSetAttribute(attn_mma, cudaFuncAttributeMaxDynamicSharedMemorySize,
                         ATTN_SMEM_BYTES);
    attn_mma<<<dim3(B * H, S / 64), 128, ATTN_SMEM_BYTES>>>(
        Qbh, Qbl, Kbh, Kbl, Vbh, Vbl, Pbh, Pbl, ubb, bvb, vh, vl);

    // --- output projection (fp32 out) ---
    GemmBatch b3 = {};
    b3.Wh[0] = Wsh + 4 * (size_t)D * D; b3.Wl[0] = Wsl + 4 * (size_t)D * D;
    b3.bias[0] = bo; b3.mode[0] = 0; b3.C[0] = out;
    gemm_tc<<<dim3(8, 32, 1), 256, GEMM_SMEM>>>(vh, vl, nullptr, nullptr, b3, BS, BS);
}

// round 12
// speedup vs baseline: 1.5401x; 1.1141x over previous
#include <cuda_runtime.h>
#include <cuda_bf16.h>
#include <cstdint>

// Problem constants
#define B 4
#define S 1024
#define D 1024
#define H 16
#define DK 64
#define L 2047          // 2*S - 1
#define LP 1088         // P rows actually used by attention (max read 1086)
#define BS (B*S)        // 4096

// ---------------------------------------------------------------------------
// Scratch (static device globals; no runtime allocation allowed)
// ---------------------------------------------------------------------------
__device__ float g_ub[B * H * S];
__device__ float g_Bv[H * L];
__device__ float g_uw[H * D];
__device__ float g_vw[H * D];
__device__ float g_cuv[32];

// bf16 hi/lo splits (inputs to tensor-core GEMMs)
__device__ __nv_bfloat16 g_xh[BS * D], g_xl[BS * D];
__device__ __nv_bfloat16 g_Rh[LP * D], g_Rl[LP * D];
__device__ __nv_bfloat16 g_Wsh[5 * D * D], g_Wsl[5 * D * D];   // q,k,v,r,o

// bf16 hi/lo GEMM outputs (attention inputs)
__device__ __nv_bfloat16 g_Qbh[BS * D], g_Qbl[BS * D];
__device__ __nv_bfloat16 g_Kbh[BS * D], g_Kbl[BS * D];
__device__ __nv_bfloat16 g_Vbh[BS * D], g_Vbl[BS * D];
__device__ __nv_bfloat16 g_Pbh[LP * D], g_Pbl[LP * D];

// attention output (bf16 pairs; input to out-projection)
__device__ __nv_bfloat16 g_vh[BS * D], g_vl[BS * D];

// ---------------------------------------------------------------------------
// PTX helpers: portable sm_80+ (ldmatrix / mma.sync / cp.async).
// ---------------------------------------------------------------------------
__device__ __forceinline__ uint32_t smem_to_u32(const void* p) {
    uint32_t a;
    asm("{ .reg .u64 t; cvta.to.shared.u64 t, %1; cvt.u32.u64 %0, t; }"
        : "=r"(a) : "l"(p));
    return a;
}

__device__ __forceinline__ void ldsm4(uint32_t* r, uint32_t addr) {
    asm volatile("ldmatrix.sync.aligned.m8n8.x4.shared.b16 {%0,%1,%2,%3}, [%4];"
                 : "=r"(r[0]), "=r"(r[1]), "=r"(r[2]), "=r"(r[3]) : "r"(addr));
}
__device__ __forceinline__ void ldsm4t(uint32_t* r, uint32_t addr) {
    asm volatile("ldmatrix.sync.aligned.m8n8.x4.trans.shared.b16 {%0,%1,%2,%3}, [%4];"
                 : "=r"(r[0]), "=r"(r[1]), "=r"(r[2]), "=r"(r[3]) : "r"(addr));
}

__device__ __forceinline__ void mma16816(float* d, const uint32_t* a,
                                         const uint32_t* b) {
    asm volatile(
        "mma.sync.aligned.m16n8k16.row.col.f32.bf16.bf16.f32 "
        "{%0,%1,%2,%3}, {%4,%5,%6,%7}, {%8,%9}, {%0,%1,%2,%3};"
        : "+f"(d[0]), "+f"(d[1]), "+f"(d[2]), "+f"(d[3])
        : "r"(a[0]), "r"(a[1]), "r"(a[2]), "r"(a[3]), "r"(b[0]), "r"(b[1]));
}

__device__ __forceinline__ void cp16(uint32_t dst, const void* src, int sz) {
    asm volatile("cp.async.cg.shared.global [%0], [%1], 16, %2;\n"
                 :: "r"(dst), "l"(src), "r"(sz));
}
__device__ __forceinline__ void cp_commit() {
    asm volatile("cp.async.commit_group;\n" ::: "memory");
}
template <int N> __device__ __forceinline__ void cp_wait() {
    asm volatile("cp.async.wait_group %0;\n" :: "n"(N) : "memory");
}

// ---------------------------------------------------------------------------
// fp32 -> bf16 hi/lo splits
// ---------------------------------------------------------------------------
__global__ void split_kernel(const float* __restrict__ s,
                             __nv_bfloat16* __restrict__ hi,
                             __nv_bfloat16* __restrict__ lo, int n)
{
    int i = blockIdx.x * 256 + threadIdx.x;
    if (i < n) {
        float x = s[i];
        __nv_bfloat16 h = __float2bfloat16(x);
        float r = x - __bfloat162float(h);
        hi[i] = h;
        lo[i] = __float2bfloat16(r);
    }
}

struct SplitBatch { const float* src[5]; };

__global__ void splitW_kernel(const SplitBatch sb,
                              __nv_bfloat16* __restrict__ hi,
                              __nv_bfloat16* __restrict__ lo)
{
    int z = blockIdx.y;
    int i = blockIdx.x * 256 + threadIdx.x;
    size_t off = (size_t)z * D * D + i;
    float x = sb.src[z][i];
    __nv_bfloat16 h = __float2bfloat16(x);
    hi[off] = h;
    lo[off] = __float2bfloat16(x - __bfloat162float(h));
}

// ---------------------------------------------------------------------------
// rel_u/rel_v pre-contraction (replaces the KR and PR full projections):
//   uw[h,e] = sum_d rel_u[h,d] * Wr[h*64+d, e]   (vw with rel_v)
//   cu[h]   = sum_d rel_u[h,d] * br[h*64+d]      (cv at cuv[16..31])
// Then ubias = x @ uw^T + cu  and  Bv = R @ vw^T + cv  (rank-16 GEMMs, fp32).
// ---------------------------------------------------------------------------
__global__ void contract_w(const float* __restrict__ Wr,
                           const float* __restrict__ rel_u,
                           const float* __restrict__ rel_v,
                           float* __restrict__ uw, float* __restrict__ vw)
{
    int idx = blockIdx.x * 256 + threadIdx.x;   // 0 .. 2*H*D-1
    int t  = idx >> 14;                          // 0: uw, 1: vw
    int he = idx & (H * D - 1);
    int h = he >> 10;
    int e = he & (D - 1);
    const float* rel = t ? rel_v : rel_u;
    float s = 0.f;
#pragma unroll 8
    for (int d = 0; d < DK; d++)
        s = fmaf(__ldg(&rel[h * DK + d]), Wr[(size_t)(h * DK + d) * D + e], s);
    (t ? vw : uw)[he] = s;
}

__global__ void contract_c(const float* __restrict__ br,
                           const float* __restrict__ rel_u,
                           const float* __restrict__ rel_v,
                           float* __restrict__ cuv)
{
    int t = threadIdx.x;
    if (t < 32) {
        int h = t & 15;
        const float* rel = (t < 16) ? rel_u : rel_v;
        float s = 0.f;
        for (int d = 0; d < DK; d++)
            s = fmaf(rel[h * DK + d], br[h * DK + d], s);
        cuv[t] = s;
    }
}

// warp-per-row rank-16 GEMM: out = A_row . w[h] + c[h]
// mode 0 (ubias): A = x [4096 rows], out[(b*H+h)*S + z], row = b*S + z
// mode 1 (Bv):    A = R [LP rows],   out[h*L + l],       row = l
__global__ __launch_bounds__(256) void rank16_kernel(
    const float* __restrict__ A, const float* __restrict__ w,
    const float* __restrict__ c, float* __restrict__ out,
    int nrows, int mode)
{
    int row  = blockIdx.x * 8 + (threadIdx.x >> 5);
    int lane = threadIdx.x & 31;
    if (row >= nrows) return;
    const float4* ar = (const float4*)(A + (size_t)row * D);
    float acc[16];
#pragma unroll
    for (int h = 0; h < 16; h++) acc[h] = 0.f;
#pragma unroll
    for (int j = 0; j < 8; j++) {
        float4 xv = ar[lane + j * 32];
#pragma unroll
        for (int h = 0; h < 16; h++) {
            float4 wv = ((const float4*)(w + h * D))[lane + j * 32];
            acc[h] += xv.x * wv.x + xv.y * wv.y + xv.z * wv.z + xv.w * wv.w;
        }
    }
    float mine = 0.f;
#pragma unroll
    for (int h = 0; h < 16; h++) {
        float v = acc[h];
        v += __shfl_xor_sync(0xffffffffu, v, 16);
        v += __shfl_xor_sync(0xffffffffu, v, 8);
        v += __shfl_xor_sync(0xffffffffu, v, 4);
        v += __shfl_xor_sync(0xffffffffu, v, 2);
        v += __shfl_xor_sync(0xffffffffu, v, 1);
        if (lane == h) mine = v;
    }
    if (lane < 16) {
        float val = mine + c[lane + (mode == 1 ? 16 : 0)];
        if (mode == 0) {
            int b = row >> 10, z = row & 1023;
            out[((b << 4) + lane) * S + z] = val;
        } else {
            out[lane * L + row] = val;
        }
    }
}

// ---------------------------------------------------------------------------
// HMMA GEMM: C[M,1024] = A[M,1024] @ W[1024,1024]^T + bias
// bf16x3 compensation. mode 0: fp32 C;  mode 1: bf16 hi/lo pair outputs.
// z < 3: A = (Ah1, Al1), M = M1.  z >= 3: A = (Ah2, Al2), M = M2.
// ---------------------------------------------------------------------------
struct GemmBatch {
    const __nv_bfloat16* Wh[4];
    const __nv_bfloat16* Wl[4];
    const float* bias[4];
    float* C[4];
    __nv_bfloat16* Ch[4];
    __nv_bfloat16* Cl[4];
    int mode[4];
};

#define RS      40                   // bf16 elems per smem row (80 bytes)
#define TILE_B  (128 * RS * 2)       // 10240 B
#define STAGE_B (4 * TILE_B)
#define GEMM_SMEM (2 * STAGE_B)      // 81920
#define NC      32

__device__ __forceinline__ void load_chunk(
    uint32_t sbase, int tid,
    const __nv_bfloat16* Ah, const __nv_bfloat16* Al,
    const __nv_bfloat16* Wh, const __nv_bfloat16* Wl,
    int bm, int bn, int M, int c, int st)
{
    const int kbase = c * 32;
    const uint32_t stoff = sbase + st * STAGE_B;
#pragma unroll
    for (int t = 0; t < 4; t++) {
        const __nv_bfloat16* base = (t == 0) ? Ah : (t == 1) ? Al : (t == 2) ? Wh : Wl;
        const int rb = (t < 2) ? bm : bn;
#pragma unroll
        for (int j = 0; j < 2; j++) {
            int idx = tid + j * 256;
            int row = idx >> 2, g = idx & 3;
            int gr = rb + row;
            int sz = (t >= 2 || gr < M) ? 16 : 0;
            const void* src = base + (size_t)gr * 1024 + kbase + g * 8;
            uint32_t dst = stoff + t * TILE_B + row * 80 + g * 16;
            cp16(dst, src, sz);
        }
    }
}

__global__ __launch_bounds__(256, 2)
void gemm_tc(const __nv_bfloat16* __restrict__ Ah1,
             const __nv_bfloat16* __restrict__ Al1,
             const __nv_bfloat16* __restrict__ Ah2,
             const __nv_bfloat16* __restrict__ Al2,
             const GemmBatch bat, int M1, int M2)
{
    extern __shared__ char smem[];
    const uint32_t sbase = smem_to_u32(smem);
    const int tid  = threadIdx.x;
    const int wid  = tid >> 5;
    const int lane = tid & 31;
    const int bn = blockIdx.x * 128;
    const int bm = blockIdx.y * 128;
    const int z  = blockIdx.z;

    const __nv_bfloat16* Ah = (z < 3) ? Ah1 : Ah2;
    const __nv_bfloat16* Al = (z < 3) ? Al1 : Al2;
    const int M = (z < 3) ? M1 : M2;
    if (bm >= M) return;               // early-exit tail tiles (P trim)

    const __nv_bfloat16* Wh = bat.Wh[z];
    const __nv_bfloat16* Wl = bat.Wl[z];

    const int mb = (wid >> 2) * 64;
    const int nb = (wid & 3) * 32;

    const int li = lane >> 3, lr = lane & 7;
    const int a_off = ((li & 1) * 8 + lr) * 80 + (li >> 1) * 16;
    const int b_off = ((li >> 1) * 8 + lr) * 80 + (li & 1) * 16;

    float acc[4][4][4];
#pragma unroll
    for (int mf = 0; mf < 4; mf++)
#pragma unroll
        for (int nf = 0; nf < 4; nf++)
#pragma unroll
            for (int e = 0; e < 4; e++) acc[mf][nf][e] = 0.f;

    load_chunk(sbase, tid, Ah, Al, Wh, Wl, bm, bn, M, 0, 0);
    cp_commit();

    for (int c = 0; c < NC; c++) {
        const int st = c & 1;
        cp_wait<0>();
        __syncthreads();
        if (c + 1 < NC) {
            load_chunk(sbase, tid, Ah, Al, Wh, Wl, bm, bn, M, c + 1, st ^ 1);
            cp_commit();
        }

        const uint32_t aH = sbase + st * STAGE_B + 0 * TILE_B + (mb)*80 + a_off;
        const uint32_t aL = aH + TILE_B;
        const uint32_t wH = sbase + st * STAGE_B + 2 * TILE_B + (nb)*80 + b_off;
        const uint32_t wL = wH + TILE_B;

#pragma unroll
        for (int k16 = 0; k16 < 2; k16++) {
            const int ko = k16 * 32;
            uint32_t ah[4][4], al[4][4], bh[2][4], bl[2][4];
#pragma unroll
            for (int mf = 0; mf < 4; mf++) {
                ldsm4(ah[mf], aH + mf * 16 * 80 + ko);
                ldsm4(al[mf], aL + mf * 16 * 80 + ko);
            }
#pragma unroll
            for (int n2 = 0; n2 < 2; n2++) {
                ldsm4(bh[n2], wH + n2 * 16 * 80 + ko);
                ldsm4(bl[n2], wL + n2 * 16 * 80 + ko);
            }
#pragma unroll
            for (int mf = 0; mf < 4; mf++)
#pragma unroll
                for (int nf = 0; nf < 4; nf++) {
                    const uint32_t* bph = &bh[nf >> 1][(nf & 1) * 2];
                    const uint32_t* bpl = &bl[nf >> 1][(nf & 1) * 2];
                    mma16816(acc[mf][nf], ah[mf], bph);
                    mma16816(acc[mf][nf], ah[mf], bpl);
                    mma16816(acc[mf][nf], al[mf], bph);
                }
        }
    }

    const float* bias = bat.bias[z];
    const int lr4 = lane >> 2, lc2 = (lane & 3) * 2;
    if (bat.mode[z] == 0) {
        float* C = bat.C[z];
#pragma unroll
        for (int mf = 0; mf < 4; mf++)
#pragma unroll
            for (int nf = 0; nf < 4; nf++) {
                int gn = bn + nb + nf * 8 + lc2;
                float2 bi = *(const float2*)(bias + gn);
                int gm0 = bm + mb + mf * 16 + lr4;
                if (gm0 < M) {
                    float2 v = make_float2(acc[mf][nf][0] + bi.x, acc[mf][nf][1] + bi.y);
                    *(float2*)(C + (size_t)gm0 * 1024 + gn) = v;
                }
                int gm1 = gm0 + 8;
                if (gm1 < M) {
                    float2 v = make_float2(acc[mf][nf][2] + bi.x, acc[mf][nf][3] + bi.y);
                    *(float2*)(C + (size_t)gm1 * 1024 + gn) = v;
                }
            }
    } else {
        __nv_bfloat16* Ch = bat.Ch[z];
        __nv_bfloat16* Cl = bat.Cl[z];
#pragma unroll
        for (int mf = 0; mf < 4; mf++)
#pragma unroll
            for (int nf = 0; nf < 4; nf++) {
                int gn = bn + nb + nf * 8 + lc2;
                float2 bi = *(const float2*)(bias + gn);
#pragma unroll
                for (int half = 0; half < 2; half++) {
                    int gm = bm + mb + mf * 16 + lr4 + half * 8;
                    if (gm < M) {
                        float vx = acc[mf][nf][half * 2 + 0] + bi.x;
                        float vy = acc[mf][nf][half * 2 + 1] + bi.y;
                        __nv_bfloat16 hx = __float2bfloat16(vx);
                        __nv_bfloat16 hy = __float2bfloat16(vy);
                        __nv_bfloat162 hv; hv.x = hx; hv.y = hy;
                        __nv_bfloat162 lv;
                        lv.x = __float2bfloat16(vx - __bfloat162float(hx));
                        lv.y = __float2bfloat16(vy - __bfloat162float(hy));
                        *(__nv_bfloat162*)(Ch + (size_t)gm * 1024 + gn) = hv;
                        *(__nv_bfloat162*)(Cl + (size_t)gm * 1024 + gn) = lv;
                    }
                }
            }
    }
}

// ---------------------------------------------------------------------------
// Tensorized fused relative attention (flash-style, causal, bf16x3 MMA).
// CTA: 64 q-rows, 4 warps, 2 CTAs/SM (single-stage KVP buffer, Q in regs,
// probs overlaid on the QP-spill buffer). Heavy tiles scheduled first.
// ---------------------------------------------------------------------------
#define ATS      144                 // smem row stride bytes (72 bf16)
#define ST_KH    0
#define ST_KL    9216
#define ST_VH    18432
#define ST_VL    27648
#define ST_PH    36864               // 127 rows used
#define ST_PL    55296
#define ST_UB    73728               // 64 floats
#define ST_BV    73984               // 127 floats
#define ST_SIZE  74496
#define SM_QPS   74496               // fp32 64 x 132 = 33792; probs overlay here
#define ATTN_SMEM_BYTES (SM_QPS + 33792)   // 108288 -> 2 CTAs/SM

__device__ __forceinline__ void attn_load_stage(
    uint32_t stg, int tid,
    const __nv_bfloat16* Kh, const __nv_bfloat16* Kl,
    const __nv_bfloat16* Vh, const __nv_bfloat16* Vl,
    const __nv_bfloat16* Ph, const __nv_bfloat16* Pl)
{
#pragma unroll
    for (int j = 0; j < 4; j++) {
        int idx = tid + j * 128;
        int row = idx >> 3, g = idx & 7;
        const size_t go = (size_t)row * D + g * 8;
        uint32_t so = row * ATS + g * 16;
        cp16(stg + ST_KH + so, Kh + go, 16);
        cp16(stg + ST_KL + so, Kl + go, 16);
        cp16(stg + ST_VH + so, Vh + go, 16);
        cp16(stg + ST_VL + so, Vl + go, 16);
    }
#pragma unroll
    for (int j = 0; j < 8; j++) {
        int idx = tid + j * 128;
        if (idx < 1016) {                       // 127 rows x 8 segs
            int row = idx >> 3, g = idx & 7;
            const size_t go = (size_t)row * D + g * 8;
            uint32_t so = row * ATS + g * 16;
            cp16(stg + ST_PH + so, Ph + go, 16);
            cp16(stg + ST_PL + so, Pl + go, 16);
        }
    }
}

__global__ __launch_bounds__(128, 2) void attn_mma(
    const __nv_bfloat16* __restrict__ Qh, const __nv_bfloat16* __restrict__ Ql,
    const __nv_bfloat16* __restrict__ Kh, const __nv_bfloat16* __restrict__ Kl,
    const __nv_bfloat16* __restrict__ Vh, const __nv_bfloat16* __restrict__ Vl,
    const __nv_bfloat16* __restrict__ Ph, const __nv_bfloat16* __restrict__ Pl,
    const float* __restrict__ ubias, const float* __restrict__ Bv,
    __nv_bfloat16* __restrict__ Oh, __nv_bfloat16* __restrict__ Ol)
{
    extern __shared__ char smem[];
    const uint32_t sb = smem_to_u32(smem);
    const int tid  = threadIdx.x;
    const int wid  = tid >> 5;
    const int lane = tid & 31;
    const int st = (S / 64 - 1) - blockIdx.y;    // heavy tiles first
    const int b  = blockIdx.x >> 4;
    const int h  = blockIdx.x & 15;
    const int s0 = st * 64;

    const int li = lane >> 3, lr = lane & 7;
    const int a_off = ((li & 1) * 8 + lr) * ATS + (li >> 1) * 16;
    const int b_off = ((li >> 1) * 8 + lr) * ATS + (li & 1) * 16;

    const int r0 = wid * 16 + (lane >> 2);
    const int colbase = (lane & 3) * 2;

    // -------- prologue: stage Q once, lift fragments to registers --------
    uint32_t qfh[4][4], qfl[4][4];
    {
        const __nv_bfloat16* Qgh = Qh + (size_t)(b * S + s0) * D + h * DK;
        const __nv_bfloat16* Qgl = Ql + (size_t)(b * S + s0) * D + h * DK;
#pragma unroll
        for (int j = 0; j < 4; j++) {
            int idx = tid + j * 128;
            int row = idx >> 3, g = idx & 7;
            const size_t go = (size_t)row * D + g * 8;
            uint32_t so = row * ATS + g * 16;
            cp16(sb + ST_KH + so, Qgh + go, 16);
            cp16(sb + ST_KL + so, Qgl + go, 16);
        }
        cp_commit();
        cp_wait<0>();
        __syncthreads();
#pragma unroll
        for (int k16 = 0; k16 < 4; k16++) {
            ldsm4(qfh[k16], sb + ST_KH + wid * 2304 + a_off + k16 * 32);
            ldsm4(qfl[k16], sb + ST_KL + wid * 2304 + a_off + k16 * 32);
        }
    }

    float cO[8][4];
#pragma unroll
    for (int nf = 0; nf < 8; nf++)
#pragma unroll
        for (int e = 0; e < 4; e++) cO[nf][e] = 0.f;
    float mrow[2] = {-1e30f, -1e30f};
    float lsum[2] = {0.f, 0.f};

    for (int zt = 0; zt <= st; zt++) {
        // stage-reuse barrier: previous iteration's reads (and the Q ldsm on
        // the first iteration) must finish before overwriting the stage.
        __syncthreads();

        const int z0 = zt * 64;
        const int lbase = (zt - st) * 64 + 960;
        const size_t kvoff = (size_t)(b * S + z0) * D + h * DK;
        attn_load_stage(sb, tid,
                        Kh + kvoff, Kl + kvoff, Vh + kvoff, Vl + kvoff,
                        Ph + (size_t)lbase * D + h * DK,
                        Pl + (size_t)lbase * D + h * DK);
        {
            float* ubS = (float*)(smem + ST_UB);
            float* bvS = (float*)(smem + ST_BV);
            if (tid < 64)  ubS[tid] = ubias[(b * H + h) * S + z0 + tid];
            if (tid < 127) bvS[tid] = Bv[h * L + lbase + tid];
        }
        cp_commit();
        cp_wait<0>();
        __syncthreads();

        // -------- QP (64x128) and QK (64x64) MMA, bf16x3, Q from regs ----
        float cQP[16][4], cQK[8][4];
#pragma unroll
        for (int nf = 0; nf < 16; nf++)
#pragma unroll
            for (int e = 0; e < 4; e++) cQP[nf][e] = 0.f;
#pragma unroll
        for (int nf = 0; nf < 8; nf++)
#pragma unroll
            for (int e = 0; e < 4; e++) cQK[nf][e] = 0.f;

#pragma unroll
        for (int k16 = 0; k16 < 4; k16++) {
            const int ko = k16 * 32;
#pragma unroll
            for (int n16 = 0; n16 < 4; n16++) {
                uint32_t kb[4], kl2[4];
                ldsm4(kb,  sb + ST_KH + b_off + n16 * 2304 + ko);
                ldsm4(kl2, sb + ST_KL + b_off + n16 * 2304 + ko);
#pragma unroll
                for (int sub = 0; sub < 2; sub++) {
                    const int nf = n16 * 2 + sub;
                    mma16816(cQK[nf], qfh[k16], &kb[sub * 2]);
                    mma16816(cQK[nf], qfh[k16], &kl2[sub * 2]);
                    mma16816(cQK[nf], qfl[k16], &kb[sub * 2]);
                }
            }
#pragma unroll
            for (int n16 = 0; n16 < 8; n16++) {
                uint32_t pb[4], pl2[4];
                ldsm4(pb,  sb + ST_PH + b_off + n16 * 2304 + ko);
                ldsm4(pl2, sb + ST_PL + b_off + n16 * 2304 + ko);
#pragma unroll
                for (int sub = 0; sub < 2; sub++) {
                    const int nf = n16 * 2 + sub;
                    mma16816(cQP[nf], qfh[k16], &pb[sub * 2]);
                    mma16816(cQP[nf], qfh[k16], &pl2[sub * 2]);
                    mma16816(cQP[nf], qfl[k16], &pb[sub * 2]);
                }
            }
        }

        // spill QP to smem for the Toeplitz gather (warp-local rows)
        float* QPs = (float*)(smem + SM_QPS);
#pragma unroll
        for (int nf = 0; nf < 16; nf++) {
            int j0 = nf * 8 + colbase;
            *(float2*)&QPs[r0 * 132 + j0]       = make_float2(cQP[nf][0], cQP[nf][1]);
            *(float2*)&QPs[(r0 + 8) * 132 + j0] = make_float2(cQP[nf][2], cQP[nf][3]);
        }
        __syncwarp();

        // -------- logits + online softmax --------
        const float* ubS = (const float*)(smem + ST_UB);
        const float* bvS = (const float*)(smem + ST_BV);
        const int p0 = 63 - r0;
        const int p1 = 55 - r0;
        float tm0 = -1e30f, tm1 = -1e30f;
#pragma unroll
        for (int nf = 0; nf < 8; nf++) {
            int j0 = nf * 8 + colbase, j1 = j0 + 1;
            float v0 = (cQK[nf][0] + QPs[r0 * 132 + j0 + p0] + ubS[j0] + bvS[j0 + p0]) * 0.125f;
            float v1 = (cQK[nf][1] + QPs[r0 * 132 + j1 + p0] + ubS[j1] + bvS[j1 + p0]) * 0.125f;
            float v2 = (cQK[nf][2] + QPs[(r0 + 8) * 132 + j0 + p1] + ubS[j0] + bvS[j0 + p1]) * 0.125f;
            float v3 = (cQK[nf][3] + QPs[(r0 + 8) * 132 + j1 + p1] + ubS[j1] + bvS[j1 + p1]) * 0.125f;
            if (zt == st) {
                if (j0 > r0) v0 = -1e30f;
                if (j1 > r0) v1 = -1e30f;
                if (j0 > r0 + 8) v2 = -1e30f;
                if (j1 > r0 + 8) v3 = -1e30f;
            }
            cQK[nf][0] = v0; cQK[nf][1] = v1; cQK[nf][2] = v2; cQK[nf][3] = v3;
            tm0 = fmaxf(tm0, fmaxf(v0, v1));
            tm1 = fmaxf(tm1, fmaxf(v2, v3));
        }
        tm0 = fmaxf(tm0, __shfl_xor_sync(0xffffffffu, tm0, 1));
        tm0 = fmaxf(tm0, __shfl_xor_sync(0xffffffffu, tm0, 2));
        tm1 = fmaxf(tm1, __shfl_xor_sync(0xffffffffu, tm1, 1));
        tm1 = fmaxf(tm1, __shfl_xor_sync(0xffffffffu, tm1, 2));

        float nm0 = fmaxf(mrow[0], tm0), nm1 = fmaxf(mrow[1], tm1);
        float sc0 = __expf(mrow[0] - nm0), sc1 = __expf(mrow[1] - nm1);

        // overlay safety: all QPs reads (any warp) precede any probs write
        __syncthreads();

        __nv_bfloat16* phs = (__nv_bfloat16*)(smem + SM_QPS);
        __nv_bfloat16* pls = (__nv_bfloat16*)(smem + SM_QPS + 9216);
        float ps0 = 0.f, ps1 = 0.f;
#pragma unroll
        for (int nf = 0; nf < 8; nf++) {
            int j0 = nf * 8 + colbase;
            float e0 = __expf(cQK[nf][0] - nm0);
            float e1 = __expf(cQK[nf][1] - nm0);
            float e2 = __expf(cQK[nf][2] - nm1);
            float e3 = __expf(cQK[nf][3] - nm1);
            ps0 += e0 + e1;
            ps1 += e2 + e3;
            __nv_bfloat16 h0 = __float2bfloat16(e0), h1 = __float2bfloat16(e1);
            __nv_bfloat16 h2 = __float2bfloat16(e2), h3 = __float2bfloat16(e3);
            __nv_bfloat162 hv, lv;
            hv.x = h0; hv.y = h1;
            lv.x = __float2bfloat16(e0 - __bfloat162float(h0));
            lv.y = __float2bfloat16(e1 - __bfloat162float(h1));
            *(__nv_bfloat162*)&phs[r0 * 72 + j0] = hv;
            *(__nv_bfloat162*)&pls[r0 * 72 + j0] = lv;
            hv.x = h2; hv.y = h3;
            lv.x = __float2bfloat16(e2 - __bfloat162float(h2));
            lv.y = __float2bfloat16(e3 - __bfloat162float(h3));
            *(__nv_bfloat162*)&phs[(r0 + 8) * 72 + j0] = hv;
            *(__nv_bfloat162*)&pls[(r0 + 8) * 72 + j0] = lv;
        }
        ps0 += __shfl_xor_sync(0xffffffffu, ps0, 1);
        ps0 += __shfl_xor_sync(0xffffffffu, ps0, 2);
        ps1 += __shfl_xor_sync(0xffffffffu, ps1, 1);
        ps1 += __shfl_xor_sync(0xffffffffu, ps1, 2);
        lsum[0] = lsum[0] * sc0 + ps0;
        lsum[1] = lsum[1] * sc1 + ps1;
        mrow[0] = nm0; mrow[1] = nm1;

#pragma unroll
        for (int nf = 0; nf < 8; nf++) {
            cO[nf][0] *= sc0; cO[nf][1] *= sc0;
            cO[nf][2] *= sc1; cO[nf][3] *= sc1;
        }
        __syncwarp();

        // -------- PV MMA (probs x V), bf16x3 --------
#pragma unroll
        for (int k16 = 0; k16 < 4; k16++) {
            const int ko = k16 * 32;
            uint32_t aph[4], apl[4];
            ldsm4(aph, sb + SM_QPS + wid * 2304 + a_off + ko);
            ldsm4(apl, sb + SM_QPS + 9216 + wid * 2304 + a_off + ko);
#pragma unroll
            for (int n16 = 0; n16 < 4; n16++) {
                uint32_t vb[4], vl2[4];
                ldsm4t(vb,  sb + ST_VH + a_off + k16 * 2304 + n16 * 32);
                ldsm4t(vl2, sb + ST_VL + a_off + k16 * 2304 + n16 * 32);
#pragma unroll
                for (int sub = 0; sub < 2; sub++) {
                    const int nf = n16 * 2 + sub;
                    mma16816(cO[nf], aph, &vb[sub * 2]);
                    mma16816(cO[nf], aph, &vl2[sub * 2]);
                    mma16816(cO[nf], apl, &vb[sub * 2]);
                }
            }
        }
    }

    // -------- output: bf16 hi/lo pairs --------
    const float i0 = 1.f / lsum[0];
    const float i1 = 1.f / lsum[1];
    const size_t row0 = (size_t)(b * S + s0 + r0);
    const size_t row1 = row0 + 8;
#pragma unroll
    for (int nf = 0; nf < 8; nf++) {
        int col = h * DK + nf * 8 + colbase;
        float o0 = cO[nf][0] * i0, o1 = cO[nf][1] * i0;
        float o2 = cO[nf][2] * i1, o3 = cO[nf][3] * i1;
        __nv_bfloat16 h0 = __float2bfloat16(o0), h1 = __float2bfloat16(o1);
        __nv_bfloat16 h2 = __float2bfloat16(o2), h3 = __float2bfloat16(o3);
        __nv_bfloat162 hv, lv;
        hv.x = h0; hv.y = h1;
        lv.x = __float2bfloat16(o0 - __bfloat162float(h0));
        lv.y = __float2bfloat16(o1 - __bfloat162float(h1));
        *(__nv_bfloat162*)(Oh + row0 * D + col) = hv;
        *(__nv_bfloat162*)(Ol + row0 * D + col) = lv;
        hv.x = h2; hv.y = h3;
        lv.x = __float2bfloat16(o2 - __bfloat162float(h2));
        lv.y = __float2bfloat16(o3 - __bfloat162float(h3));
        *(__nv_bfloat162*)(Oh + row1 * D + col) = hv;
        *(__nv_bfloat162*)(Ol + row1 * D + col) = lv;
    }
}

// ---------------------------------------------------------------------------
// Launch
// ---------------------------------------------------------------------------
extern "C" void kernel_launch(void* const* d_in, const int* in_sizes, int n_in,
                              void* d_out, int out_size)
{
    const float* x      = (const float*)d_in[0];
    const float* Wq     = (const float*)d_in[1];
    const float* bq     = (const float*)d_in[2];
    const float* Wk     = (const float*)d_in[3];
    const float* bk     = (const float*)d_in[4];
    const float* Wv     = (const float*)d_in[5];
    const float* bv     = (const float*)d_in[6];
    const float* Wr     = (const float*)d_in[7];
    const float* br     = (const float*)d_in[8];
    const float* rel_u  = (const float*)d_in[9];
    const float* rel_v  = (const float*)d_in[10];
    const float* Wo     = (const float*)d_in[11];
    const float* bo     = (const float*)d_in[12];
    const float* relpos = (const float*)d_in[13];
    float* out = (float*)d_out;

    float *ubb, *bvb, *uwb, *vwb, *cuvb;
    cudaGetSymbolAddress((void**)&ubb,  g_ub);
    cudaGetSymbolAddress((void**)&bvb,  g_Bv);
    cudaGetSymbolAddress((void**)&uwb,  g_uw);
    cudaGetSymbolAddress((void**)&vwb,  g_vw);
    cudaGetSymbolAddress((void**)&cuvb, g_cuv);

    __nv_bfloat16 *xh, *xl, *Rh, *Rl, *Wsh, *Wsl, *vh, *vl;
    __nv_bfloat16 *Qbh, *Qbl, *Kbh, *Kbl, *Vbh, *Vbl, *Pbh, *Pbl;
    cudaGetSymbolAddress((void**)&xh,  g_xh);
    cudaGetSymbolAddress((void**)&xl,  g_xl);
    cudaGetSymbolAddress((void**)&Rh,  g_Rh);
    cudaGetSymbolAddress((void**)&Rl,  g_Rl);
    cudaGetSymbolAddress((void**)&Wsh, g_Wsh);
    cudaGetSymbolAddress((void**)&Wsl, g_Wsl);
    cudaGetSymbolAddress((void**)&vh,  g_vh);
    cudaGetSymbolAddress((void**)&vl,  g_vl);
    cudaGetSymbolAddress((void**)&Qbh, g_Qbh);
    cudaGetSymbolAddress((void**)&Qbl, g_Qbl);
    cudaGetSymbolAddress((void**)&Kbh, g_Kbh);
    cudaGetSymbolAddress((void**)&Kbl, g_Kbl);
    cudaGetSymbolAddress((void**)&Vbh, g_Vbh);
    cudaGetSymbolAddress((void**)&Vbl, g_Vbl);
    cudaGetSymbolAddress((void**)&Pbh, g_Pbh);
    cudaGetSymbolAddress((void**)&Pbl, g_Pbl);

    const float* R = relpos + (size_t)1 * D;   // rows [1, 2048)

    // --- splits + rel contractions ---
    split_kernel<<<(BS * D + 255) / 256, 256>>>(x, xh, xl, BS * D);
    SplitBatch sw;
    sw.src[0] = Wq; sw.src[1] = Wk; sw.src[2] = Wv; sw.src[3] = Wr; sw.src[4] = Wo;
    splitW_kernel<<<dim3(D * D / 256, 5), 256>>>(sw, Wsh, Wsl);
    split_kernel<<<(LP * D + 255) / 256, 256>>>(R, Rh, Rl, LP * D);
    contract_w<<<2 * H * D / 256, 256>>>(Wr, rel_u, rel_v, uwb, vwb);
    contract_c<<<1, 32>>>(br, rel_u, rel_v, cuvb);

    // --- ubias / Bv via rank-16 GEMMs (exact fp32) ---
    rank16_kernel<<<(BS + 7) / 8, 256>>>(x, uwb, cuvb, ubb, BS, 0);
    rank16_kernel<<<(LP + 7) / 8, 256>>>(R, vwb, cuvb, bvb, LP, 1);

    cudaFuncSetAttribute(gemm_tc, cudaFuncAttributeMaxDynamicSharedMemorySize,
                         GEMM_SMEM);

    // --- Q/K/V + P projections (merged, grid.z = 4; z=3 is P from R) ---
    GemmBatch b1 = {};
    b1.Wh[0] = Wsh + 0 * (size_t)D * D; b1.Wl[0] = Wsl + 0 * (size_t)D * D;
    b1.bias[0] = bq; b1.mode[0] = 1; b1.Ch[0] = Qbh; b1.Cl[0] = Qbl;
    b1.Wh[1] = Wsh + 1 * (size_t)D * D; b1.Wl[1] = Wsl + 1 * (size_t)D * D;
    b1.bias[1] = bk; b1.mode[1] = 1; b1.Ch[1] = Kbh; b1.Cl[1] = Kbl;
    b1.Wh[2] = Wsh + 2 * (size_t)D * D; b1.Wl[2] = Wsl + 2 * (size_t)D * D;
    b1.bias[2] = bv; b1.mode[2] = 1; b1.Ch[2] = Vbh; b1.Cl[2] = Vbl;
    b1.Wh[3] = Wsh + 1 * (size_t)D * D; b1.Wl[3] = Wsl + 1 * (size_t)D * D;
    b1.bias[3] = bk; b1.mode[3] = 1; b1.Ch[3] = Pbh; b1.Cl[3] = Pbl;
    gemm_tc<<<dim3(8, 32, 4), 256, GEMM_SMEM>>>(xh, xl, Rh, Rl, b1, BS, LP);

    // --- tensorized attention (2 CTAs/SM, heavy tiles first) ---
    cudaFuncSetAttribute(attn_mma, cudaFuncAttributeMaxDynamicSharedMemorySize,
                         ATTN_SMEM_BYTES);
    attn_mma<<<dim3(B * H, S / 64), 128, ATTN_SMEM_BYTES>>>(
        Qbh, Qbl, Kbh, Kbl, Vbh, Vbl, Pbh, Pbl, ubb, bvb, vh, vl);

    // --- output projection (fp32 out) ---
    GemmBatch b3 = {};
    b3.Wh[0] = Wsh + 4 * (size_t)D * D; b3.Wl[0] = Wsl + 4 * (size_t)D * D;
    b3.bias[0] = bo; b3.mode[0] = 0; b3.C[0] = out;
    gemm_tc<<<dim3(8, 32, 1), 256, GEMM_SMEM>>>(vh, vl, nullptr, nullptr, b3, BS, BS);
}

// round 13
// speedup vs baseline: 1.6980x; 1.1026x over previous
#include <cuda_runtime.h>
#include <cuda_bf16.h>
#include <cstdint>

// Problem constants
#define B 4
#define S 1024
#define D 1024
#define H 16
#define DK 64
#define L 2047          // 2*S - 1
#define LP 1088         // P rows actually used by attention (max read 1087)
#define BS (B*S)        // 4096

// ---------------------------------------------------------------------------
// Scratch (static device globals; no runtime allocation allowed)
// ---------------------------------------------------------------------------
__device__ float g_ub[B * H * S];
__device__ float g_Bv[H * L];
__device__ float g_uw[H * D];
__device__ float g_vw[H * D];
__device__ float g_cuv[32];

// bf16 hi/lo splits (inputs to tensor-core GEMMs)
__device__ __nv_bfloat16 g_xh[BS * D], g_xl[BS * D];
__device__ __nv_bfloat16 g_Rh[LP * D], g_Rl[LP * D];
__device__ __nv_bfloat16 g_Wsh[5 * D * D], g_Wsl[5 * D * D];   // q,k,v,r,o

// bf16 hi/lo GEMM outputs (attention inputs)
__device__ __nv_bfloat16 g_Qbh[BS * D], g_Qbl[BS * D];
__device__ __nv_bfloat16 g_Kbh[BS * D], g_Kbl[BS * D];
__device__ __nv_bfloat16 g_Vbh[BS * D], g_Vbl[BS * D];
__device__ __nv_bfloat16 g_Pbh[LP * D], g_Pbl[LP * D];

// attention output (bf16 pairs; input to out-projection)
__device__ __nv_bfloat16 g_vh[BS * D], g_vl[BS * D];

// ---------------------------------------------------------------------------
// PTX helpers: portable sm_80+ (ldmatrix / mma.sync / cp.async).
// ---------------------------------------------------------------------------
__device__ __forceinline__ uint32_t smem_to_u32(const void* p) {
    uint32_t a;
    asm("{ .reg .u64 t; cvta.to.shared.u64 t, %1; cvt.u32.u64 %0, t; }"
        : "=r"(a) : "l"(p));
    return a;
}

__device__ __forceinline__ void ldsm4(uint32_t* r, uint32_t addr) {
    asm volatile("ldmatrix.sync.aligned.m8n8.x4.shared.b16 {%0,%1,%2,%3}, [%4];"
                 : "=r"(r[0]), "=r"(r[1]), "=r"(r[2]), "=r"(r[3]) : "r"(addr));
}
__device__ __forceinline__ void ldsm4t(uint32_t* r, uint32_t addr) {
    asm volatile("ldmatrix.sync.aligned.m8n8.x4.trans.shared.b16 {%0,%1,%2,%3}, [%4];"
                 : "=r"(r[0]), "=r"(r[1]), "=r"(r[2]), "=r"(r[3]) : "r"(addr));
}

__device__ __forceinline__ void mma16816(float* d, const uint32_t* a,
                                         const uint32_t* b) {
    asm volatile(
        "mma.sync.aligned.m16n8k16.row.col.f32.bf16.bf16.f32 "
        "{%0,%1,%2,%3}, {%4,%5,%6,%7}, {%8,%9}, {%0,%1,%2,%3};"
        : "+f"(d[0]), "+f"(d[1]), "+f"(d[2]), "+f"(d[3])
        : "r"(a[0]), "r"(a[1]), "r"(a[2]), "r"(a[3]), "r"(b[0]), "r"(b[1]));
}

__device__ __forceinline__ void cp16(uint32_t dst, const void* src, int sz) {
    asm volatile("cp.async.cg.shared.global [%0], [%1], 16, %2;\n"
                 :: "r"(dst), "l"(src), "r"(sz));
}
__device__ __forceinline__ void cp_commit() {
    asm volatile("cp.async.commit_group;\n" ::: "memory");
}
template <int N> __device__ __forceinline__ void cp_wait() {
    asm volatile("cp.async.wait_group %0;\n" :: "n"(N) : "memory");
}

// ---------------------------------------------------------------------------
// fp32 -> bf16 hi/lo splits
// ---------------------------------------------------------------------------
__global__ void split_kernel(const float* __restrict__ s,
                             __nv_bfloat16* __restrict__ hi,
                             __nv_bfloat16* __restrict__ lo, int n)
{
    int i = blockIdx.x * 256 + threadIdx.x;
    if (i < n) {
        float x = s[i];
        __nv_bfloat16 h = __float2bfloat16(x);
        float r = x - __bfloat162float(h);
        hi[i] = h;
        lo[i] = __float2bfloat16(r);
    }
}

struct SplitBatch { const float* src[5]; };

__global__ void splitW_kernel(const SplitBatch sb,
                              __nv_bfloat16* __restrict__ hi,
                              __nv_bfloat16* __restrict__ lo)
{
    int z = blockIdx.y;
    int i = blockIdx.x * 256 + threadIdx.x;
    size_t off = (size_t)z * D * D + i;
    float x = sb.src[z][i];
    __nv_bfloat16 h = __float2bfloat16(x);
    hi[off] = h;
    lo[off] = __float2bfloat16(x - __bfloat162float(h));
}

// ---------------------------------------------------------------------------
// rel_u/rel_v pre-contraction (replaces the KR and PR full projections)
// ---------------------------------------------------------------------------
__global__ void contract_w(const float* __restrict__ Wr,
                           const float* __restrict__ rel_u,
                           const float* __restrict__ rel_v,
                           float* __restrict__ uw, float* __restrict__ vw)
{
    int idx = blockIdx.x * 256 + threadIdx.x;   // 0 .. 2*H*D-1
    int t  = idx >> 14;                          // 0: uw, 1: vw
    int he = idx & (H * D - 1);
    int h = he >> 10;
    int e = he & (D - 1);
    const float* rel = t ? rel_v : rel_u;
    float s = 0.f;
#pragma unroll 8
    for (int d = 0; d < DK; d++)
        s = fmaf(__ldg(&rel[h * DK + d]), Wr[(size_t)(h * DK + d) * D + e], s);
    (t ? vw : uw)[he] = s;
}

__global__ void contract_c(const float* __restrict__ br,
                           const float* __restrict__ rel_u,
                           const float* __restrict__ rel_v,
                           float* __restrict__ cuv)
{
    int t = threadIdx.x;
    if (t < 32) {
        int h = t & 15;
        const float* rel = (t < 16) ? rel_u : rel_v;
        float s = 0.f;
        for (int d = 0; d < DK; d++)
            s = fmaf(rel[h * DK + d], br[h * DK + d], s);
        cuv[t] = s;
    }
}

// warp-per-row rank-16 GEMM: out = A_row . w[h] + c[h]
__global__ __launch_bounds__(256) void rank16_kernel(
    const float* __restrict__ A, const float* __restrict__ w,
    const float* __restrict__ c, float* __restrict__ out,
    int nrows, int mode)
{
    int row  = blockIdx.x * 8 + (threadIdx.x >> 5);
    int lane = threadIdx.x & 31;
    if (row >= nrows) return;
    const float4* ar = (const float4*)(A + (size_t)row * D);
    float acc[16];
#pragma unroll
    for (int h = 0; h < 16; h++) acc[h] = 0.f;
#pragma unroll
    for (int j = 0; j < 8; j++) {
        float4 xv = ar[lane + j * 32];
#pragma unroll
        for (int h = 0; h < 16; h++) {
            float4 wv = ((const float4*)(w + h * D))[lane + j * 32];
            acc[h] += xv.x * wv.x + xv.y * wv.y + xv.z * wv.z + xv.w * wv.w;
        }
    }
    float mine = 0.f;
#pragma unroll
    for (int h = 0; h < 16; h++) {
        float v = acc[h];
        v += __shfl_xor_sync(0xffffffffu, v, 16);
        v += __shfl_xor_sync(0xffffffffu, v, 8);
        v += __shfl_xor_sync(0xffffffffu, v, 4);
        v += __shfl_xor_sync(0xffffffffu, v, 2);
        v += __shfl_xor_sync(0xffffffffu, v, 1);
        if (lane == h) mine = v;
    }
    if (lane < 16) {
        float val = mine + c[lane + (mode == 1 ? 16 : 0)];
        if (mode == 0) {
            int b = row >> 10, z = row & 1023;
            out[((b << 4) + lane) * S + z] = val;
        } else {
            out[lane * L + row] = val;
        }
    }
}

// ---------------------------------------------------------------------------
// HMMA GEMM: C[M,1024] = A[M,1024] @ W[1024,1024]^T + bias
// bf16x3 compensation. mode 0: fp32 C;  mode 1: bf16 hi/lo pair outputs.
// z < 3: A = (Ah1, Al1), M = M1.  z >= 3: A = (Ah2, Al2), M = M2.
// ---------------------------------------------------------------------------
struct GemmBatch {
    const __nv_bfloat16* Wh[4];
    const __nv_bfloat16* Wl[4];
    const float* bias[4];
    float* C[4];
    __nv_bfloat16* Ch[4];
    __nv_bfloat16* Cl[4];
    int mode[4];
};

#define RS      40                   // bf16 elems per smem row (80 bytes)
#define TILE_B  (128 * RS * 2)       // 10240 B
#define STAGE_B (4 * TILE_B)
#define GEMM_SMEM (2 * STAGE_B)      // 81920
#define NC      32

__device__ __forceinline__ void load_chunk(
    uint32_t sbase, int tid,
    const __nv_bfloat16* Ah, const __nv_bfloat16* Al,
    const __nv_bfloat16* Wh, const __nv_bfloat16* Wl,
    int bm, int bn, int M, int c, int st)
{
    const int kbase = c * 32;
    const uint32_t stoff = sbase + st * STAGE_B;
#pragma unroll
    for (int t = 0; t < 4; t++) {
        const __nv_bfloat16* base = (t == 0) ? Ah : (t == 1) ? Al : (t == 2) ? Wh : Wl;
        const int rb = (t < 2) ? bm : bn;
#pragma unroll
        for (int j = 0; j < 2; j++) {
            int idx = tid + j * 256;
            int row = idx >> 2, g = idx & 3;
            int gr = rb + row;
            int sz = (t >= 2 || gr < M) ? 16 : 0;
            const void* src = base + (size_t)gr * 1024 + kbase + g * 8;
            uint32_t dst = stoff + t * TILE_B + row * 80 + g * 16;
            cp16(dst, src, sz);
        }
    }
}

__global__ __launch_bounds__(256, 2)
void gemm_tc(const __nv_bfloat16* __restrict__ Ah1,
             const __nv_bfloat16* __restrict__ Al1,
             const __nv_bfloat16* __restrict__ Ah2,
             const __nv_bfloat16* __restrict__ Al2,
             const GemmBatch bat, int M1, int M2)
{
    extern __shared__ char smem[];
    const uint32_t sbase = smem_to_u32(smem);
    const int tid  = threadIdx.x;
    const int wid  = tid >> 5;
    const int lane = tid & 31;
    const int bn = blockIdx.x * 128;
    const int bm = blockIdx.y * 128;
    const int z  = blockIdx.z;

    const __nv_bfloat16* Ah = (z < 3) ? Ah1 : Ah2;
    const __nv_bfloat16* Al = (z < 3) ? Al1 : Al2;
    const int M = (z < 3) ? M1 : M2;
    if (bm >= M) return;               // early-exit tail tiles (P trim)

    const __nv_bfloat16* Wh = bat.Wh[z];
    const __nv_bfloat16* Wl = bat.Wl[z];

    const int mb = (wid >> 2) * 64;
    const int nb = (wid & 3) * 32;

    const int li = lane >> 3, lr = lane & 7;
    const int a_off = ((li & 1) * 8 + lr) * 80 + (li >> 1) * 16;
    const int b_off = ((li >> 1) * 8 + lr) * 80 + (li & 1) * 16;

    float acc[4][4][4];
#pragma unroll
    for (int mf = 0; mf < 4; mf++)
#pragma unroll
        for (int nf = 0; nf < 4; nf++)
#pragma unroll
            for (int e = 0; e < 4; e++) acc[mf][nf][e] = 0.f;

    load_chunk(sbase, tid, Ah, Al, Wh, Wl, bm, bn, M, 0, 0);
    cp_commit();

    for (int c = 0; c < NC; c++) {
        const int st = c & 1;
        cp_wait<0>();
        __syncthreads();
        if (c + 1 < NC) {
            load_chunk(sbase, tid, Ah, Al, Wh, Wl, bm, bn, M, c + 1, st ^ 1);
            cp_commit();
        }

        const uint32_t aH = sbase + st * STAGE_B + 0 * TILE_B + (mb)*80 + a_off;
        const uint32_t aL = aH + TILE_B;
        const uint32_t wH = sbase + st * STAGE_B + 2 * TILE_B + (nb)*80 + b_off;
        const uint32_t wL = wH + TILE_B;

#pragma unroll
        for (int k16 = 0; k16 < 2; k16++) {
            const int ko = k16 * 32;
            uint32_t ah[4][4], al[4][4], bh[2][4], bl[2][4];
#pragma unroll
            for (int mf = 0; mf < 4; mf++) {
                ldsm4(ah[mf], aH + mf * 16 * 80 + ko);
                ldsm4(al[mf], aL + mf * 16 * 80 + ko);
            }
#pragma unroll
            for (int n2 = 0; n2 < 2; n2++) {
                ldsm4(bh[n2], wH + n2 * 16 * 80 + ko);
                ldsm4(bl[n2], wL + n2 * 16 * 80 + ko);
            }
#pragma unroll
            for (int mf = 0; mf < 4; mf++)
#pragma unroll
                for (int nf = 0; nf < 4; nf++) {
                    const uint32_t* bph = &bh[nf >> 1][(nf & 1) * 2];
                    const uint32_t* bpl = &bl[nf >> 1][(nf & 1) * 2];
                    mma16816(acc[mf][nf], ah[mf], bph);
                    mma16816(acc[mf][nf], ah[mf], bpl);
                    mma16816(acc[mf][nf], al[mf], bph);
                }
        }
    }

    const float* bias = bat.bias[z];
    const int lr4 = lane >> 2, lc2 = (lane & 3) * 2;
    if (bat.mode[z] == 0) {
        float* C = bat.C[z];
#pragma unroll
        for (int mf = 0; mf < 4; mf++)
#pragma unroll
            for (int nf = 0; nf < 4; nf++) {
                int gn = bn + nb + nf * 8 + lc2;
                float2 bi = *(const float2*)(bias + gn);
                int gm0 = bm + mb + mf * 16 + lr4;
                if (gm0 < M) {
                    float2 v = make_float2(acc[mf][nf][0] + bi.x, acc[mf][nf][1] + bi.y);
                    *(float2*)(C + (size_t)gm0 * 1024 + gn) = v;
                }
                int gm1 = gm0 + 8;
                if (gm1 < M) {
                    float2 v = make_float2(acc[mf][nf][2] + bi.x, acc[mf][nf][3] + bi.y);
                    *(float2*)(C + (size_t)gm1 * 1024 + gn) = v;
                }
            }
    } else {
        __nv_bfloat16* Ch = bat.Ch[z];
        __nv_bfloat16* Cl = bat.Cl[z];
#pragma unroll
        for (int mf = 0; mf < 4; mf++)
#pragma unroll
            for (int nf = 0; nf < 4; nf++) {
                int gn = bn + nb + nf * 8 + lc2;
                float2 bi = *(const float2*)(bias + gn);
#pragma unroll
                for (int half = 0; half < 2; half++) {
                    int gm = bm + mb + mf * 16 + lr4 + half * 8;
                    if (gm < M) {
                        float vx = acc[mf][nf][half * 2 + 0] + bi.x;
                        float vy = acc[mf][nf][half * 2 + 1] + bi.y;
                        __nv_bfloat16 hx = __float2bfloat16(vx);
                        __nv_bfloat16 hy = __float2bfloat16(vy);
                        __nv_bfloat162 hv; hv.x = hx; hv.y = hy;
                        __nv_bfloat162 lv;
                        lv.x = __float2bfloat16(vx - __bfloat162float(hx));
                        lv.y = __float2bfloat16(vy - __bfloat162float(hy));
                        *(__nv_bfloat162*)(Ch + (size_t)gm * 1024 + gn) = hv;
                        *(__nv_bfloat162*)(Cl + (size_t)gm * 1024 + gn) = lv;
                    }
                }
            }
    }
}

// ---------------------------------------------------------------------------
// Tensorized fused relative attention (flash-style, causal, bf16x3 MMA).
// Toeplitz-shift QP reuse: each iteration computes only the 64 NEW QP columns
// into a rotating 64x128 fp32 buffer (semantic col lp lives at physical
// (lp + 64*zt) & 127). P staging drops to 64 new rows per iteration.
// CTA: 64 q-rows, 4 warps, 2 CTAs/SM. Heavy tiles scheduled first.
// ---------------------------------------------------------------------------
#define ATS      144                 // smem row stride bytes (72 bf16)
#define ST_KH    0                   // 64 x ATS
#define ST_KL    9216
#define ST_VH    18432
#define ST_VL    27648
#define ST_PH    36864               // 64 rows (new P window half)
#define ST_PL    46080
#define ST_UB    55296               // 64 floats
#define ST_BV    55552               // 127 floats (pad to 512)
#define SM_QPS   56064               // fp32 64 x 132 rotating QP = 33792
#define SM_PRB   89856               // probs hi/lo 2 x 9216 = 18432
#define ATTN_SMEM_BYTES 108288       // 2 CTAs/SM

__device__ __forceinline__ void attn_load_kv(
    uint32_t sb, int tid,
    const __nv_bfloat16* Kh, const __nv_bfloat16* Kl,
    const __nv_bfloat16* Vh, const __nv_bfloat16* Vl)
{
#pragma unroll
    for (int j = 0; j < 4; j++) {
        int idx = tid + j * 128;
        int row = idx >> 3, g = idx & 7;
        const size_t go = (size_t)row * D + g * 8;
        uint32_t so = row * ATS + g * 16;
        cp16(sb + ST_KH + so, Kh + go, 16);
        cp16(sb + ST_KL + so, Kl + go, 16);
        cp16(sb + ST_VH + so, Vh + go, 16);
        cp16(sb + ST_VL + so, Vl + go, 16);
    }
}

__device__ __forceinline__ void attn_load_p(
    uint32_t sb, int tid,
    const __nv_bfloat16* Ph, const __nv_bfloat16* Pl)
{
#pragma unroll
    for (int j = 0; j < 4; j++) {
        int idx = tid + j * 128;
        int row = idx >> 3, g = idx & 7;
        const size_t go = (size_t)row * D + g * 8;
        uint32_t so = row * ATS + g * 16;
        cp16(sb + ST_PH + so, Ph + go, 16);
        cp16(sb + ST_PL + so, Pl + go, 16);
    }
}

__global__ __launch_bounds__(128, 2) void attn_mma(
    const __nv_bfloat16* __restrict__ Qh, const __nv_bfloat16* __restrict__ Ql,
    const __nv_bfloat16* __restrict__ Kh, const __nv_bfloat16* __restrict__ Kl,
    const __nv_bfloat16* __restrict__ Vh, const __nv_bfloat16* __restrict__ Vl,
    const __nv_bfloat16* __restrict__ Ph, const __nv_bfloat16* __restrict__ Pl,
    const float* __restrict__ ubias, const float* __restrict__ Bv,
    __nv_bfloat16* __restrict__ Oh, __nv_bfloat16* __restrict__ Ol)
{
    extern __shared__ char smem[];
    const uint32_t sb = smem_to_u32(smem);
    const int tid  = threadIdx.x;
    const int wid  = tid >> 5;
    const int lane = tid & 31;
    const int st = (S / 64 - 1) - blockIdx.y;    // heavy tiles first
    const int b  = blockIdx.x >> 4;
    const int h  = blockIdx.x & 15;
    const int s0 = st * 64;

    const int li = lane >> 3, lr = lane & 7;
    const int a_off = ((li & 1) * 8 + lr) * ATS + (li >> 1) * 16;
    const int b_off = ((li >> 1) * 8 + lr) * ATS + (li & 1) * 16;

    const int r0 = wid * 16 + (lane >> 2);
    const int colbase = (lane & 3) * 2;

    float* QPs = (float*)(smem + SM_QPS);

    // -------- prologue: stage Q once, lift fragments to registers --------
    uint32_t qfh[4][4], qfl[4][4];
    {
        const __nv_bfloat16* Qgh = Qh + (size_t)(b * S + s0) * D + h * DK;
        const __nv_bfloat16* Qgl = Ql + (size_t)(b * S + s0) * D + h * DK;
#pragma unroll
        for (int j = 0; j < 4; j++) {
            int idx = tid + j * 128;
            int row = idx >> 3, g = idx & 7;
            const size_t go = (size_t)row * D + g * 8;
            uint32_t so = row * ATS + g * 16;
            cp16(sb + ST_KH + so, Qgh + go, 16);
            cp16(sb + ST_KL + so, Qgl + go, 16);
        }
        cp_commit();
        cp_wait<0>();
        __syncthreads();
#pragma unroll
        for (int k16 = 0; k16 < 4; k16++) {
            ldsm4(qfh[k16], sb + ST_KH + wid * 2304 + a_off + k16 * 32);
            ldsm4(qfl[k16], sb + ST_KL + wid * 2304 + a_off + k16 * 32);
        }
    }

    // -------- QP prologue (zt = -1): seed physical half 0 --------
    // P rows (0 - st)*64 + 960 + [0,64) = window 0's lower semantic half.
    {
        const int prow0 = 960 - st * 64;
        __syncthreads();   // Q ldsm done before reusing ST_KH/KL region? (P uses its own region; barrier orders Q stage reads anyway)
        attn_load_p(sb, tid,
                    Ph + (size_t)prow0 * D + h * DK,
                    Pl + (size_t)prow0 * D + h * DK);
        cp_commit();
        cp_wait<0>();
        __syncthreads();

        float cQPn[8][4];
#pragma unroll
        for (int nf = 0; nf < 8; nf++)
#pragma unroll
            for (int e = 0; e < 4; e++) cQPn[nf][e] = 0.f;
#pragma unroll
        for (int k16 = 0; k16 < 4; k16++) {
            const int ko = k16 * 32;
#pragma unroll
            for (int n16 = 0; n16 < 4; n16++) {
                uint32_t pb[4], pl2[4];
                ldsm4(pb,  sb + ST_PH + b_off + n16 * 2304 + ko);
                ldsm4(pl2, sb + ST_PL + b_off + n16 * 2304 + ko);
#pragma unroll
                for (int sub = 0; sub < 2; sub++) {
                    const int nf = n16 * 2 + sub;
                    mma16816(cQPn[nf], qfh[k16], &pb[sub * 2]);
                    mma16816(cQPn[nf], qfh[k16], &pl2[sub * 2]);
                    mma16816(cQPn[nf], qfl[k16], &pb[sub * 2]);
                }
            }
        }
#pragma unroll
        for (int nf = 0; nf < 8; nf++) {
            int j0 = nf * 8 + colbase;       // physical half 0
            *(float2*)&QPs[r0 * 132 + j0]       = make_float2(cQPn[nf][0], cQPn[nf][1]);
            *(float2*)&QPs[(r0 + 8) * 132 + j0] = make_float2(cQPn[nf][2], cQPn[nf][3]);
        }
        __syncwarp();
    }

    float cO[8][4];
#pragma unroll
    for (int nf = 0; nf < 8; nf++)
#pragma unroll
        for (int e = 0; e < 4; e++) cO[nf][e] = 0.f;
    float mrow[2] = {-1e30f, -1e30f};
    float lsum[2] = {0.f, 0.f};

    for (int zt = 0; zt <= st; zt++) {
        // stage-reuse barrier: previous iteration's K/V/P reads complete.
        __syncthreads();

        const int z0 = zt * 64;
        const int lbase = (zt - st) * 64 + 960;
        const int prow0 = lbase + 64;            // new 64 P rows
        const size_t kvoff = (size_t)(b * S + z0) * D + h * DK;
        attn_load_kv(sb, tid, Kh + kvoff, Kl + kvoff, Vh + kvoff, Vl + kvoff);
        attn_load_p(sb, tid,
                    Ph + (size_t)prow0 * D + h * DK,
                    Pl + (size_t)prow0 * D + h * DK);
        {
            float* ubS = (float*)(smem + ST_UB);
            float* bvS = (float*)(smem + ST_BV);
            if (tid < 64)  ubS[tid] = ubias[(b * H + h) * S + z0 + tid];
            if (tid < 127) bvS[tid] = Bv[h * L + lbase + tid];
        }
        cp_commit();
        cp_wait<0>();
        __syncthreads();

        // -------- QK (64x64) + QP-new (64x64) MMA, bf16x3, Q from regs ----
        float cQK[8][4], cQPn[8][4];
#pragma unroll
        for (int nf = 0; nf < 8; nf++)
#pragma unroll
            for (int e = 0; e < 4; e++) { cQK[nf][e] = 0.f; cQPn[nf][e] = 0.f; }

#pragma unroll
        for (int k16 = 0; k16 < 4; k16++) {
            const int ko = k16 * 32;
#pragma unroll
            for (int n16 = 0; n16 < 4; n16++) {
                uint32_t kb[4], kl2[4];
                ldsm4(kb,  sb + ST_KH + b_off + n16 * 2304 + ko);
                ldsm4(kl2, sb + ST_KL + b_off + n16 * 2304 + ko);
#pragma unroll
                for (int sub = 0; sub < 2; sub++) {
                    const int nf = n16 * 2 + sub;
                    mma16816(cQK[nf], qfh[k16], &kb[sub * 2]);
                    mma16816(cQK[nf], qfh[k16], &kl2[sub * 2]);
                    mma16816(cQK[nf], qfl[k16], &kb[sub * 2]);
                }
            }
#pragma unroll
            for (int n16 = 0; n16 < 4; n16++) {
                uint32_t pb[4], pl2[4];
                ldsm4(pb,  sb + ST_PH + b_off + n16 * 2304 + ko);
                ldsm4(pl2, sb + ST_PL + b_off + n16 * 2304 + ko);
#pragma unroll
                for (int sub = 0; sub < 2; sub++) {
                    const int nf = n16 * 2 + sub;
                    mma16816(cQPn[nf], qfh[k16], &pb[sub * 2]);
                    mma16816(cQPn[nf], qfh[k16], &pl2[sub * 2]);
                    mma16816(cQPn[nf], qfl[k16], &pb[sub * 2]);
                }
            }
        }

        // spill new QP columns into the rotating buffer's target half
        const int hb = ((zt + 1) & 1) << 6;
#pragma unroll
        for (int nf = 0; nf < 8; nf++) {
            int j0 = hb + nf * 8 + colbase;
            *(float2*)&QPs[r0 * 132 + j0]       = make_float2(cQPn[nf][0], cQPn[nf][1]);
            *(float2*)&QPs[(r0 + 8) * 132 + j0] = make_float2(cQPn[nf][2], cQPn[nf][3]);
        }
        __syncwarp();

        // -------- logits + online softmax (rotating-gather) --------
        const float* ubS = (const float*)(smem + ST_UB);
        const float* bvS = (const float*)(smem + ST_BV);
        const int p0 = 63 - r0;
        const int p1 = 55 - r0;
        const int off = (zt & 1) << 6;           // rotation offset
        const float* row0p = &QPs[r0 * 132];
        const float* row1p = &QPs[(r0 + 8) * 132];
        float tm0 = -1e30f, tm1 = -1e30f;
#pragma unroll
        for (int nf = 0; nf < 8; nf++) {
            int j0 = nf * 8 + colbase, j1 = j0 + 1;
            float v0 = (cQK[nf][0] + row0p[(j0 + p0 + off) & 127] + ubS[j0] + bvS[j0 + p0]) * 0.125f;
            float v1 = (cQK[nf][1] + row0p[(j1 + p0 + off) & 127] + ubS[j1] + bvS[j1 + p0]) * 0.125f;
            float v2 = (cQK[nf][2] + row1p[(j0 + p1 + off) & 127] + ubS[j0] + bvS[j0 + p1]) * 0.125f;
            float v3 = (cQK[nf][3] + row1p[(j1 + p1 + off) & 127] + ubS[j1] + bvS[j1 + p1]) * 0.125f;
            if (zt == st) {
                if (j0 > r0) v0 = -1e30f;
                if (j1 > r0) v1 = -1e30f;
                if (j0 > r0 + 8) v2 = -1e30f;
                if (j1 > r0 + 8) v3 = -1e30f;
            }
            cQK[nf][0] = v0; cQK[nf][1] = v1; cQK[nf][2] = v2; cQK[nf][3] = v3;
            tm0 = fmaxf(tm0, fmaxf(v0, v1));
            tm1 = fmaxf(tm1, fmaxf(v2, v3));
        }
        tm0 = fmaxf(tm0, __shfl_xor_sync(0xffffffffu, tm0, 1));
        tm0 = fmaxf(tm0, __shfl_xor_sync(0xffffffffu, tm0, 2));
        tm1 = fmaxf(tm1, __shfl_xor_sync(0xffffffffu, tm1, 1));
        tm1 = fmaxf(tm1, __shfl_xor_sync(0xffffffffu, tm1, 2));

        float nm0 = fmaxf(mrow[0], tm0), nm1 = fmaxf(mrow[1], tm1);
        float sc0 = __expf(mrow[0] - nm0), sc1 = __expf(mrow[1] - nm1);

        __nv_bfloat16* phs = (__nv_bfloat16*)(smem + SM_PRB);
        __nv_bfloat16* pls = (__nv_bfloat16*)(smem + SM_PRB + 9216);
        float ps0 = 0.f, ps1 = 0.f;
#pragma unroll
        for (int nf = 0; nf < 8; nf++) {
            int j0 = nf * 8 + colbase;
            float e0 = __expf(cQK[nf][0] - nm0);
            float e1 = __expf(cQK[nf][1] - nm0);
            float e2 = __expf(cQK[nf][2] - nm1);
            float e3 = __expf(cQK[nf][3] - nm1);
            ps0 += e0 + e1;
            ps1 += e2 + e3;
            __nv_bfloat16 h0 = __float2bfloat16(e0), h1 = __float2bfloat16(e1);
            __nv_bfloat16 h2 = __float2bfloat16(e2), h3 = __float2bfloat16(e3);
            __nv_bfloat162 hv, lv;
            hv.x = h0; hv.y = h1;
            lv.x = __float2bfloat16(e0 - __bfloat162float(h0));
            lv.y = __float2bfloat16(e1 - __bfloat162float(h1));
            *(__nv_bfloat162*)&phs[r0 * 72 + j0] = hv;
            *(__nv_bfloat162*)&pls[r0 * 72 + j0] = lv;
            hv.x = h2; hv.y = h3;
            lv.x = __float2bfloat16(e2 - __bfloat162float(h2));
            lv.y = __float2bfloat16(e3 - __bfloat162float(h3));
            *(__nv_bfloat162*)&phs[(r0 + 8) * 72 + j0] = hv;
            *(__nv_bfloat162*)&pls[(r0 + 8) * 72 + j0] = lv;
        }
        ps0 += __shfl_xor_sync(0xffffffffu, ps0, 1);
        ps0 += __shfl_xor_sync(0xffffffffu, ps0, 2);
        ps1 += __shfl_xor_sync(0xffffffffu, ps1, 1);
        ps1 += __shfl_xor_sync(0xffffffffu, ps1, 2);
        lsum[0] = lsum[0] * sc0 + ps0;
        lsum[1] = lsum[1] * sc1 + ps1;
        mrow[0] = nm0; mrow[1] = nm1;

#pragma unroll
        for (int nf = 0; nf < 8; nf++) {
            cO[nf][0] *= sc0; cO[nf][1] *= sc0;
            cO[nf][2] *= sc1; cO[nf][3] *= sc1;
        }
        __syncwarp();

        // -------- PV MMA (probs x V), bf16x3 --------
#pragma unroll
        for (int k16 = 0; k16 < 4; k16++) {
            const int ko = k16 * 32;
            uint32_t aph[4], apl[4];
            ldsm4(aph, sb + SM_PRB + wid * 2304 + a_off + ko);
            ldsm4(apl, sb + SM_PRB + 9216 + wid * 2304 + a_off + ko);
#pragma unroll
            for (int n16 = 0; n16 < 4; n16++) {
                uint32_t vb[4], vl2[4];
                ldsm4t(vb,  sb + ST_VH + a_off + k16 * 2304 + n16 * 32);
                ldsm4t(vl2, sb + ST_VL + a_off + k16 * 2304 + n16 * 32);
#pragma unroll
                for (int sub = 0; sub < 2; sub++) {
                    const int nf = n16 * 2 + sub;
                    mma16816(cO[nf], aph, &vb[sub * 2]);
                    mma16816(cO[nf], aph, &vl2[sub * 2]);
                    mma16816(cO[nf], apl, &vb[sub * 2]);
                }
            }
        }
    }

    // -------- output: bf16 hi/lo pairs --------
    const float i0 = 1.f / lsum[0];
    const float i1 = 1.f / lsum[1];
    const size_t row0 = (size_t)(b * S + s0 + r0);
    const size_t row1 = row0 + 8;
#pragma unroll
    for (int nf = 0; nf < 8; nf++) {
        int col = h * DK + nf * 8 + colbase;
        float o0 = cO[nf][0] * i0, o1 = cO[nf][1] * i0;
        float o2 = cO[nf][2] * i1, o3 = cO[nf][3] * i1;
        __nv_bfloat16 h0 = __float2bfloat16(o0), h1 = __float2bfloat16(o1);
        __nv_bfloat16 h2 = __float2bfloat16(o2), h3 = __float2bfloat16(o3);
        __nv_bfloat162 hv, lv;
        hv.x = h0; hv.y = h1;
        lv.x = __float2bfloat16(o0 - __bfloat162float(h0));
        lv.y = __float2bfloat16(o1 - __bfloat162float(h1));
        *(__nv_bfloat162*)(Oh + row0 * D + col) = hv;
        *(__nv_bfloat162*)(Ol + row0 * D + col) = lv;
        hv.x = h2; hv.y = h3;
        lv.x = __float2bfloat16(o2 - __bfloat162float(h2));
        lv.y = __float2bfloat16(o3 - __bfloat162float(h3));
        *(__nv_bfloat162*)(Oh + row1 * D + col) = hv;
        *(__nv_bfloat162*)(Ol + row1 * D + col) = lv;
    }
}

// ---------------------------------------------------------------------------
// Launch
// ---------------------------------------------------------------------------
extern "C" void kernel_launch(void* const* d_in, const int* in_sizes, int n_in,
                              void* d_out, int out_size)
{
    const float* x      = (const float*)d_in[0];
    const float* Wq     = (const float*)d_in[1];
    const float* bq     = (const float*)d_in[2];
    const float* Wk     = (const float*)d_in[3];
    const float* bk     = (const float*)d_in[4];
    const float* Wv     = (const float*)d_in[5];
    const float* bv     = (const float*)d_in[6];
    const float* Wr     = (const float*)d_in[7];
    const float* br     = (const float*)d_in[8];
    const float* rel_u  = (const float*)d_in[9];
    const float* rel_v  = (const float*)d_in[10];
    const float* Wo     = (const float*)d_in[11];
    const float* bo     = (const float*)d_in[12];
    const float* relpos = (const float*)d_in[13];
    float* out = (float*)d_out;

    float *ubb, *bvb, *uwb, *vwb, *cuvb;
    cudaGetSymbolAddress((void**)&ubb,  g_ub);
    cudaGetSymbolAddress((void**)&bvb,  g_Bv);
    cudaGetSymbolAddress((void**)&uwb,  g_uw);
    cudaGetSymbolAddress((void**)&vwb,  g_vw);
    cudaGetSymbolAddress((void**)&cuvb, g_cuv);

    __nv_bfloat16 *xh, *xl, *Rh, *Rl, *Wsh, *Wsl, *vh, *vl;
    __nv_bfloat16 *Qbh, *Qbl, *Kbh, *Kbl, *Vbh, *Vbl, *Pbh, *Pbl;
    cudaGetSymbolAddress((void**)&xh,  g_xh);
    cudaGetSymbolAddress((void**)&xl,  g_xl);
    cudaGetSymbolAddress((void**)&Rh,  g_Rh);
    cudaGetSymbolAddress((void**)&Rl,  g_Rl);
    cudaGetSymbolAddress((void**)&Wsh, g_Wsh);
    cudaGetSymbolAddress((void**)&Wsl, g_Wsl);
    cudaGetSymbolAddress((void**)&vh,  g_vh);
    cudaGetSymbolAddress((void**)&vl,  g_vl);
    cudaGetSymbolAddress((void**)&Qbh, g_Qbh);
    cudaGetSymbolAddress((void**)&Qbl, g_Qbl);
    cudaGetSymbolAddress((void**)&Kbh, g_Kbh);
    cudaGetSymbolAddress((void**)&Kbl, g_Kbl);
    cudaGetSymbolAddress((void**)&Vbh, g_Vbh);
    cudaGetSymbolAddress((void**)&Vbl, g_Vbl);
    cudaGetSymbolAddress((void**)&Pbh, g_Pbh);
    cudaGetSymbolAddress((void**)&Pbl, g_Pbl);

    const float* R = relpos + (size_t)1 * D;   // rows [1, 2048)

    // --- splits + rel contractions ---
    split_kernel<<<(BS * D + 255) / 256, 256>>>(x, xh, xl, BS * D);
    SplitBatch sw;
    sw.src[0] = Wq; sw.src[1] = Wk; sw.src[2] = Wv; sw.src[3] = Wr; sw.src[4] = Wo;
    splitW_kernel<<<dim3(D * D / 256, 5), 256>>>(sw, Wsh, Wsl);
    split_kernel<<<(LP * D + 255) / 256, 256>>>(R, Rh, Rl, LP * D);
    contract_w<<<2 * H * D / 256, 256>>>(Wr, rel_u, rel_v, uwb, vwb);
    contract_c<<<1, 32>>>(br, rel_u, rel_v, cuvb);

    // --- ubias / Bv via rank-16 GEMMs (exact fp32) ---
    rank16_kernel<<<(BS + 7) / 8, 256>>>(x, uwb, cuvb, ubb, BS, 0);
    rank16_kernel<<<(LP + 7) / 8, 256>>>(R, vwb, cuvb, bvb, LP, 1);

    cudaFuncSetAttribute(gemm_tc, cudaFuncAttributeMaxDynamicSharedMemorySize,
                         GEMM_SMEM);

    // --- Q/K/V + P projections (merged, grid.z = 4; z=3 is P from R) ---
    GemmBatch b1 = {};
    b1.Wh[0] = Wsh + 0 * (size_t)D * D; b1.Wl[0] = Wsl + 0 * (size_t)D * D;
    b1.bias[0] = bq; b1.mode[0] = 1; b1.Ch[0] = Qbh; b1.Cl[0] = Qbl;
    b1.Wh[1] = Wsh + 1 * (size_t)D * D; b1.Wl[1] = Wsl + 1 * (size_t)D * D;
    b1.bias[1] = bk; b1.mode[1] = 1; b1.Ch[1] = Kbh; b1.Cl[1] = Kbl;
    b1.Wh[2] = Wsh + 2 * (size_t)D * D; b1.Wl[2] = Wsl + 2 * (size_t)D * D;
    b1.bias[2] = bv; b1.mode[2] = 1; b1.Ch[2] = Vbh; b1.Cl[2] = Vbl;
    b1.Wh[3] = Wsh + 1 * (size_t)D * D; b1.Wl[3] = Wsl + 1 * (size_t)D * D;
    b1.bias[3] = bk; b1.mode[3] = 1; b1.Ch[3] = Pbh; b1.Cl[3] = Pbl;
    gemm_tc<<<dim3(8, 32, 4), 256, GEMM_SMEM>>>(xh, xl, Rh, Rl, b1, BS, LP);

    // --- tensorized attention (2 CTAs/SM, QP shift-reuse) ---
    cudaFuncSetAttribute(attn_mma, cudaFuncAttributeMaxDynamicSharedMemorySize,
                         ATTN_SMEM_BYTES);
    attn_mma<<<dim3(B * H, S / 64), 128, ATTN_SMEM_BYTES>>>(
        Qbh, Qbl, Kbh, Kbl, Vbh, Vbl, Pbh, Pbl, ubb, bvb, vh, vl);

    // --- output projection (fp32 out) ---
    GemmBatch b3 = {};
    b3.Wh[0] = Wsh + 4 * (size_t)D * D; b3.Wl[0] = Wsl + 4 * (size_t)D * D;
    b3.bias[0] = bo; b3.mode[0] = 0; b3.C[0] = out;
    gemm_tc<<<dim3(8, 32, 1), 256, GEMM_SMEM>>>(vh, vl, nullptr, nullptr, b3, BS, BS);
}

// round 14
// speedup vs baseline: 2.1800x; 1.2839x over previous
#include <cuda_runtime.h>
#include <cuda_fp16.h>
#include <cstdint>

// Problem constants
#define B 4
#define S 1024
#define D 1024
#define H 16
#define DK 64
#define L 2047          // 2*S - 1
#define LP 1088         // P rows actually used by attention (max read 1087)
#define BS (B*S)        // 4096

// ---------------------------------------------------------------------------
// Scratch (static device globals; no runtime allocation allowed)
// ---------------------------------------------------------------------------
__device__ float g_ub[B * H * S];
__device__ float g_Bv[H * L];
__device__ float g_uw[H * D];
__device__ float g_vw[H * D];
__device__ float g_cuv[32];

// fp16 operands. A-side tensors: single fp16. B-side tensors: hi+lo pair.
__device__ __half g_xh[BS * D];                      // A of projections
__device__ __half g_Rh[LP * D];                      // A of P projection
__device__ __half g_Wsh[5 * D * D], g_Wsl[5 * D * D];// q,k,v,r,o (B side)

__device__ __half g_Qbh[BS * D];                     // A of QK/QP
__device__ __half g_Kbh[BS * D], g_Kbl[BS * D];      // B of QK
__device__ __half g_Vbh[BS * D], g_Vbl[BS * D];      // B of PV
__device__ __half g_Pbh[LP * D], g_Pbl[LP * D];      // B of QP

__device__ __half g_vh[BS * D];                      // attn out = A of out-proj

// ---------------------------------------------------------------------------
// PTX helpers: portable sm_80+ (ldmatrix / mma.sync / cp.async).
// ---------------------------------------------------------------------------
__device__ __forceinline__ uint32_t smem_to_u32(const void* p) {
    uint32_t a;
    asm("{ .reg .u64 t; cvta.to.shared.u64 t, %1; cvt.u32.u64 %0, t; }"
        : "=r"(a) : "l"(p));
    return a;
}

__device__ __forceinline__ void ldsm4(uint32_t* r, uint32_t addr) {
    asm volatile("ldmatrix.sync.aligned.m8n8.x4.shared.b16 {%0,%1,%2,%3}, [%4];"
                 : "=r"(r[0]), "=r"(r[1]), "=r"(r[2]), "=r"(r[3]) : "r"(addr));
}
__device__ __forceinline__ void ldsm4t(uint32_t* r, uint32_t addr) {
    asm volatile("ldmatrix.sync.aligned.m8n8.x4.trans.shared.b16 {%0,%1,%2,%3}, [%4];"
                 : "=r"(r[0]), "=r"(r[1]), "=r"(r[2]), "=r"(r[3]) : "r"(addr));
}

__device__ __forceinline__ void mma16816(float* d, const uint32_t* a,
                                         const uint32_t* b) {
    asm volatile(
        "mma.sync.aligned.m16n8k16.row.col.f32.f16.f16.f32 "
        "{%0,%1,%2,%3}, {%4,%5,%6,%7}, {%8,%9}, {%0,%1,%2,%3};"
        : "+f"(d[0]), "+f"(d[1]), "+f"(d[2]), "+f"(d[3])
        : "r"(a[0]), "r"(a[1]), "r"(a[2]), "r"(a[3]), "r"(b[0]), "r"(b[1]));
}

__device__ __forceinline__ void cp16(uint32_t dst, const void* src, int sz) {
    asm volatile("cp.async.cg.shared.global [%0], [%1], 16, %2;\n"
                 :: "r"(dst), "l"(src), "r"(sz));
}
__device__ __forceinline__ void cp_commit() {
    asm volatile("cp.async.commit_group;\n" ::: "memory");
}
template <int N> __device__ __forceinline__ void cp_wait() {
    asm volatile("cp.async.wait_group %0;\n" :: "n"(N) : "memory");
}

// ---------------------------------------------------------------------------
// fp32 -> fp16 conversions
// ---------------------------------------------------------------------------
__global__ void cvt_kernel(const float* __restrict__ s,
                           __half* __restrict__ h16, int n)
{
    int i = blockIdx.x * 256 + threadIdx.x;
    if (i < n) h16[i] = __float2half_rn(s[i]);
}

struct SplitBatch { const float* src[5]; };

__global__ void splitW_kernel(const SplitBatch sb,
                              __half* __restrict__ hi,
                              __half* __restrict__ lo)
{
    int z = blockIdx.y;
    int i = blockIdx.x * 256 + threadIdx.x;
    size_t off = (size_t)z * D * D + i;
    float x = sb.src[z][i];
    __half h = __float2half_rn(x);
    hi[off] = h;
    lo[off] = __float2half_rn(x - __half2float(h));
}

// ---------------------------------------------------------------------------
// rel_u/rel_v pre-contraction (replaces the KR and PR full projections)
// ---------------------------------------------------------------------------
__global__ void contract_w(const float* __restrict__ Wr,
                           const float* __restrict__ rel_u,
                           const float* __restrict__ rel_v,
                           float* __restrict__ uw, float* __restrict__ vw)
{
    int idx = blockIdx.x * 256 + threadIdx.x;   // 0 .. 2*H*D-1
    int t  = idx >> 14;                          // 0: uw, 1: vw
    int he = idx & (H * D - 1);
    int h = he >> 10;
    int e = he & (D - 1);
    const float* rel = t ? rel_v : rel_u;
    float s = 0.f;
#pragma unroll 8
    for (int d = 0; d < DK; d++)
        s = fmaf(__ldg(&rel[h * DK + d]), Wr[(size_t)(h * DK + d) * D + e], s);
    (t ? vw : uw)[he] = s;
}

__global__ void contract_c(const float* __restrict__ br,
                           const float* __restrict__ rel_u,
                           const float* __restrict__ rel_v,
                           float* __restrict__ cuv)
{
    int t = threadIdx.x;
    if (t < 32) {
        int h = t & 15;
        const float* rel = (t < 16) ? rel_u : rel_v;
        float s = 0.f;
        for (int d = 0; d < DK; d++)
            s = fmaf(rel[h * DK + d], br[h * DK + d], s);
        cuv[t] = s;
    }
}

// warp-per-row rank-16 GEMM: out = A_row . w[h] + c[h]
__global__ __launch_bounds__(256) void rank16_kernel(
    const float* __restrict__ A, const float* __restrict__ w,
    const float* __restrict__ c, float* __restrict__ out,
    int nrows, int mode)
{
    int row  = blockIdx.x * 8 + (threadIdx.x >> 5);
    int lane = threadIdx.x & 31;
    if (row >= nrows) return;
    const float4* ar = (const float4*)(A + (size_t)row * D);
    float acc[16];
#pragma unroll
    for (int h = 0; h < 16; h++) acc[h] = 0.f;
#pragma unroll
    for (int j = 0; j < 8; j++) {
        float4 xv = ar[lane + j * 32];
#pragma unroll
        for (int h = 0; h < 16; h++) {
            float4 wv = ((const float4*)(w + h * D))[lane + j * 32];
            acc[h] += xv.x * wv.x + xv.y * wv.y + xv.z * wv.z + xv.w * wv.w;
        }
    }
    float mine = 0.f;
#pragma unroll
    for (int h = 0; h < 16; h++) {
        float v = acc[h];
        v += __shfl_xor_sync(0xffffffffu, v, 16);
        v += __shfl_xor_sync(0xffffffffu, v, 8);
        v += __shfl_xor_sync(0xffffffffu, v, 4);
        v += __shfl_xor_sync(0xffffffffu, v, 2);
        v += __shfl_xor_sync(0xffffffffu, v, 1);
        if (lane == h) mine = v;
    }
    if (lane < 16) {
        float val = mine + c[lane + (mode == 1 ? 16 : 0)];
        if (mode == 0) {
            int b = row >> 10, z = row & 1023;
            out[((b << 4) + lane) * S + z] = val;
        } else {
            out[lane * L + row] = val;
        }
    }
}

// ---------------------------------------------------------------------------
// HMMA GEMM: C[M,1024] = A[M,1024] @ W[1024,1024]^T + bias
// fp16x2: A single fp16, W hi+lo fp16 -> 2 MMA passes.
// mode 0: fp32 C.  mode 1: fp16 hi+lo outputs.  mode 2: fp16 hi only.
// z < 3: A = Ah1, M = M1.  z >= 3: A = Ah2, M = M2.
// ---------------------------------------------------------------------------
struct GemmBatch {
    const __half* Wh[4];
    const __half* Wl[4];
    const float* bias[4];
    float* C[4];
    __half* Ch[4];
    __half* Cl[4];
    int mode[4];
};

#define RS      40                   // fp16 elems per smem row slot (80 bytes)
#define TILE_B  (128 * RS * 2)       // 10240 B
#define STAGE_B (3 * TILE_B)         // A, Wh, Wl
#define GEMM_SMEM (2 * STAGE_B)      // 61440
#define NC      32

__device__ __forceinline__ void load_chunk(
    uint32_t sbase, int tid,
    const __half* Ah, const __half* Wh, const __half* Wl,
    int bm, int bn, int M, int c, int st)
{
    const int kbase = c * 32;
    const uint32_t stoff = sbase + st * STAGE_B;
#pragma unroll
    for (int t = 0; t < 3; t++) {
        const __half* base = (t == 0) ? Ah : (t == 1) ? Wh : Wl;
        const int rb = (t == 0) ? bm : bn;
#pragma unroll
        for (int j = 0; j < 2; j++) {
            int idx = tid + j * 256;          // 0..511
            int row = idx >> 2, g = idx & 3;
            int gr = rb + row;
            int sz = (t >= 1 || gr < M) ? 16 : 0;
            const void* src = base + (size_t)gr * 1024 + kbase + g * 8;
            uint32_t dst = stoff + t * TILE_B + row * 80 + g * 16;
            cp16(dst, src, sz);
        }
    }
}

__global__ __launch_bounds__(256, 2)
void gemm_tc(const __half* __restrict__ Ah1,
             const __half* __restrict__ Ah2,
             const GemmBatch bat, int M1, int M2)
{
    extern __shared__ char smem[];
    const uint32_t sbase = smem_to_u32(smem);
    const int tid  = threadIdx.x;
    const int wid  = tid >> 5;
    const int lane = tid & 31;
    const int bn = blockIdx.x * 128;
    const int bm = blockIdx.y * 128;
    const int z  = blockIdx.z;

    const __half* Ah = (z < 3) ? Ah1 : Ah2;
    const int M = (z < 3) ? M1 : M2;
    if (bm >= M) return;               // early-exit tail tiles (P trim)

    const __half* Wh = bat.Wh[z];
    const __half* Wl = bat.Wl[z];

    const int mb = (wid >> 2) * 64;
    const int nb = (wid & 3) * 32;

    const int li = lane >> 3, lr = lane & 7;
    const int a_off = ((li & 1) * 8 + lr) * 80 + (li >> 1) * 16;
    const int b_off = ((li >> 1) * 8 + lr) * 80 + (li & 1) * 16;

    float acc[4][4][4];
#pragma unroll
    for (int mf = 0; mf < 4; mf++)
#pragma unroll
        for (int nf = 0; nf < 4; nf++)
#pragma unroll
            for (int e = 0; e < 4; e++) acc[mf][nf][e] = 0.f;

    load_chunk(sbase, tid, Ah, Wh, Wl, bm, bn, M, 0, 0);
    cp_commit();

    for (int c = 0; c < NC; c++) {
        const int st = c & 1;
        cp_wait<0>();
        __syncthreads();
        if (c + 1 < NC) {
            load_chunk(sbase, tid, Ah, Wh, Wl, bm, bn, M, c + 1, st ^ 1);
            cp_commit();
        }

        const uint32_t aT = sbase + st * STAGE_B + 0 * TILE_B + (mb)*80 + a_off;
        const uint32_t wH = sbase + st * STAGE_B + 1 * TILE_B + (nb)*80 + b_off;
        const uint32_t wL = wH + TILE_B;

#pragma unroll
        for (int k16 = 0; k16 < 2; k16++) {
            const int ko = k16 * 32;
            uint32_t ah[4][4], bh[2][4], bl[2][4];
#pragma unroll
            for (int mf = 0; mf < 4; mf++)
                ldsm4(ah[mf], aT + mf * 16 * 80 + ko);
#pragma unroll
            for (int n2 = 0; n2 < 2; n2++) {
                ldsm4(bh[n2], wH + n2 * 16 * 80 + ko);
                ldsm4(bl[n2], wL + n2 * 16 * 80 + ko);
            }
#pragma unroll
            for (int mf = 0; mf < 4; mf++)
#pragma unroll
                for (int nf = 0; nf < 4; nf++) {
                    const uint32_t* bph = &bh[nf >> 1][(nf & 1) * 2];
                    const uint32_t* bpl = &bl[nf >> 1][(nf & 1) * 2];
                    mma16816(acc[mf][nf], ah[mf], bph);
                    mma16816(acc[mf][nf], ah[mf], bpl);
                }
        }
    }

    const float* bias = bat.bias[z];
    const int lr4 = lane >> 2, lc2 = (lane & 3) * 2;
    const int mode = bat.mode[z];
    if (mode == 0) {
        float* C = bat.C[z];
#pragma unroll
        for (int mf = 0; mf < 4; mf++)
#pragma unroll
            for (int nf = 0; nf < 4; nf++) {
                int gn = bn + nb + nf * 8 + lc2;
                float2 bi = *(const float2*)(bias + gn);
                int gm0 = bm + mb + mf * 16 + lr4;
                if (gm0 < M) {
                    float2 v = make_float2(acc[mf][nf][0] + bi.x, acc[mf][nf][1] + bi.y);
                    *(float2*)(C + (size_t)gm0 * 1024 + gn) = v;
                }
                int gm1 = gm0 + 8;
                if (gm1 < M) {
                    float2 v = make_float2(acc[mf][nf][2] + bi.x, acc[mf][nf][3] + bi.y);
                    *(float2*)(C + (size_t)gm1 * 1024 + gn) = v;
                }
            }
    } else if (mode == 1) {
        __half* Ch = bat.Ch[z];
        __half* Cl = bat.Cl[z];
#pragma unroll
        for (int mf = 0; mf < 4; mf++)
#pragma unroll
            for (int nf = 0; nf < 4; nf++) {
                int gn = bn + nb + nf * 8 + lc2;
                float2 bi = *(const float2*)(bias + gn);
#pragma unroll
                for (int half_i = 0; half_i < 2; half_i++) {
                    int gm = bm + mb + mf * 16 + lr4 + half_i * 8;
                    if (gm < M) {
                        float vx = acc[mf][nf][half_i * 2 + 0] + bi.x;
                        float vy = acc[mf][nf][half_i * 2 + 1] + bi.y;
                        __half hx = __float2half_rn(vx);
                        __half hy = __float2half_rn(vy);
                        __half2 hv; hv.x = hx; hv.y = hy;
                        __half2 lv;
                        lv.x = __float2half_rn(vx - __half2float(hx));
                        lv.y = __float2half_rn(vy - __half2float(hy));
                        *(__half2*)(Ch + (size_t)gm * 1024 + gn) = hv;
                        *(__half2*)(Cl + (size_t)gm * 1024 + gn) = lv;
                    }
                }
            }
    } else {
        __half* Ch = bat.Ch[z];
#pragma unroll
        for (int mf = 0; mf < 4; mf++)
#pragma unroll
            for (int nf = 0; nf < 4; nf++) {
                int gn = bn + nb + nf * 8 + lc2;
                float2 bi = *(const float2*)(bias + gn);
#pragma unroll
                for (int half_i = 0; half_i < 2; half_i++) {
                    int gm = bm + mb + mf * 16 + lr4 + half_i * 8;
                    if (gm < M) {
                        __half2 hv;
                        hv.x = __float2half_rn(acc[mf][nf][half_i * 2 + 0] + bi.x);
                        hv.y = __float2half_rn(acc[mf][nf][half_i * 2 + 1] + bi.y);
                        *(__half2*)(Ch + (size_t)gm * 1024 + gn) = hv;
                    }
                }
            }
    }
}

// ---------------------------------------------------------------------------
// Tensorized fused relative attention (flash-style, causal, fp16x2 MMA).
// Toeplitz-shift QP reuse (rotating 64x128 fp32 buffer); Q single fp16 in
// registers; probs single fp16. CTA: 64 q-rows, 4 warps, 2 CTAs/SM.
// ---------------------------------------------------------------------------
#define ATS      144                 // smem row stride bytes (72 fp16)
#define ST_KH    0                   // 64 x ATS
#define ST_KL    9216
#define ST_VH    18432
#define ST_VL    27648
#define ST_PH    36864               // 64 rows (new P window half)
#define ST_PL    46080
#define ST_UB    55296               // 64 floats
#define ST_BV    55552               // 127 floats (pad to 512)
#define SM_QPS   56064               // fp32 64 x 132 rotating QP = 33792
#define SM_PRB   89856               // probs fp16 single = 9216
#define ATTN_SMEM_BYTES 99072        // 2 CTAs/SM

__device__ __forceinline__ void attn_load_kv(
    uint32_t sb, int tid,
    const __half* Kh, const __half* Kl,
    const __half* Vh, const __half* Vl)
{
#pragma unroll
    for (int j = 0; j < 4; j++) {
        int idx = tid + j * 128;
        int row = idx >> 3, g = idx & 7;
        const size_t go = (size_t)row * D + g * 8;
        uint32_t so = row * ATS + g * 16;
        cp16(sb + ST_KH + so, Kh + go, 16);
        cp16(sb + ST_KL + so, Kl + go, 16);
        cp16(sb + ST_VH + so, Vh + go, 16);
        cp16(sb + ST_VL + so, Vl + go, 16);
    }
}

__device__ __forceinline__ void attn_load_p(
    uint32_t sb, int tid,
    const __half* Ph, const __half* Pl)
{
#pragma unroll
    for (int j = 0; j < 4; j++) {
        int idx = tid + j * 128;
        int row = idx >> 3, g = idx & 7;
        const size_t go = (size_t)row * D + g * 8;
        uint32_t so = row * ATS + g * 16;
        cp16(sb + ST_PH + so, Ph + go, 16);
        cp16(sb + ST_PL + so, Pl + go, 16);
    }
}

__global__ __launch_bounds__(128, 2) void attn_mma(
    const __half* __restrict__ Qh,
    const __half* __restrict__ Kh, const __half* __restrict__ Kl,
    const __half* __restrict__ Vh, const __half* __restrict__ Vl,
    const __half* __restrict__ Ph, const __half* __restrict__ Pl,
    const float* __restrict__ ubias, const float* __restrict__ Bv,
    __half* __restrict__ Oh)
{
    extern __shared__ char smem[];
    const uint32_t sb = smem_to_u32(smem);
    const int tid  = threadIdx.x;
    const int wid  = tid >> 5;
    const int lane = tid & 31;
    const int st = (S / 64 - 1) - blockIdx.y;    // heavy tiles first
    const int b  = blockIdx.x >> 4;
    const int h  = blockIdx.x & 15;
    const int s0 = st * 64;

    const int li = lane >> 3, lr = lane & 7;
    const int a_off = ((li & 1) * 8 + lr) * ATS + (li >> 1) * 16;
    const int b_off = ((li >> 1) * 8 + lr) * ATS + (li & 1) * 16;

    const int r0 = wid * 16 + (lane >> 2);
    const int colbase = (lane & 3) * 2;

    float* QPs = (float*)(smem + SM_QPS);

    // -------- prologue: stage Q once (single fp16), lift to registers ----
    uint32_t qf[4][4];
    {
        const __half* Qg = Qh + (size_t)(b * S + s0) * D + h * DK;
#pragma unroll
        for (int j = 0; j < 4; j++) {
            int idx = tid + j * 128;
            int row = idx >> 3, g = idx & 7;
            cp16(sb + ST_KH + row * ATS + g * 16, Qg + (size_t)row * D + g * 8, 16);
        }
        cp_commit();
        cp_wait<0>();
        __syncthreads();
#pragma unroll
        for (int k16 = 0; k16 < 4; k16++)
            ldsm4(qf[k16], sb + ST_KH + wid * 2304 + a_off + k16 * 32);
    }

    // -------- QP prologue (zt = -1): seed physical half 0 --------
    {
        const int prow0 = 960 - st * 64;
        __syncthreads();
        attn_load_p(sb, tid,
                    Ph + (size_t)prow0 * D + h * DK,
                    Pl + (size_t)prow0 * D + h * DK);
        cp_commit();
        cp_wait<0>();
        __syncthreads();

        float cQPn[8][4];
#pragma unroll
        for (int nf = 0; nf < 8; nf++)
#pragma unroll
            for (int e = 0; e < 4; e++) cQPn[nf][e] = 0.f;
#pragma unroll
        for (int k16 = 0; k16 < 4; k16++) {
            const int ko = k16 * 32;
#pragma unroll
            for (int n16 = 0; n16 < 4; n16++) {
                uint32_t pb[4], pl2[4];
                ldsm4(pb,  sb + ST_PH + b_off + n16 * 2304 + ko);
                ldsm4(pl2, sb + ST_PL + b_off + n16 * 2304 + ko);
#pragma unroll
                for (int sub = 0; sub < 2; sub++) {
                    const int nf = n16 * 2 + sub;
                    mma16816(cQPn[nf], qf[k16], &pb[sub * 2]);
                    mma16816(cQPn[nf], qf[k16], &pl2[sub * 2]);
                }
            }
        }
#pragma unroll
        for (int nf = 0; nf < 8; nf++) {
            int j0 = nf * 8 + colbase;       // physical half 0
            *(float2*)&QPs[r0 * 132 + j0]       = make_float2(cQPn[nf][0], cQPn[nf][1]);
            *(float2*)&QPs[(r0 + 8) * 132 + j0] = make_float2(cQPn[nf][2], cQPn[nf][3]);
        }
        __syncwarp();
    }

    float cO[8][4];
#pragma unroll
    for (int nf = 0; nf < 8; nf++)
#pragma unroll
        for (int e = 0; e < 4; e++) cO[nf][e] = 0.f;
    float mrow[2] = {-1e30f, -1e30f};
    float lsum[2] = {0.f, 0.f};

    for (int zt = 0; zt <= st; zt++) {
        __syncthreads();   // previous iteration's K/V/P reads complete

        const int z0 = zt * 64;
        const int lbase = (zt - st) * 64 + 960;
        const int prow0 = lbase + 64;            // new 64 P rows
        const size_t kvoff = (size_t)(b * S + z0) * D + h * DK;
        attn_load_kv(sb, tid, Kh + kvoff, Kl + kvoff, Vh + kvoff, Vl + kvoff);
        attn_load_p(sb, tid,
                    Ph + (size_t)prow0 * D + h * DK,
                    Pl + (size_t)prow0 * D + h * DK);
        {
            float* ubS = (float*)(smem + ST_UB);
            float* bvS = (float*)(smem + ST_BV);
            if (tid < 64)  ubS[tid] = ubias[(b * H + h) * S + z0 + tid];
            if (tid < 127) bvS[tid] = Bv[h * L + lbase + tid];
        }
        cp_commit();
        cp_wait<0>();
        __syncthreads();

        // -------- QK (64x64) + QP-new (64x64), fp16x2, Q from regs ----
        float cQK[8][4], cQPn[8][4];
#pragma unroll
        for (int nf = 0; nf < 8; nf++)
#pragma unroll
            for (int e = 0; e < 4; e++) { cQK[nf][e] = 0.f; cQPn[nf][e] = 0.f; }

#pragma unroll
        for (int k16 = 0; k16 < 4; k16++) {
            const int ko = k16 * 32;
#pragma unroll
            for (int n16 = 0; n16 < 4; n16++) {
                uint32_t kb[4], kl2[4];
                ldsm4(kb,  sb + ST_KH + b_off + n16 * 2304 + ko);
                ldsm4(kl2, sb + ST_KL + b_off + n16 * 2304 + ko);
#pragma unroll
                for (int sub = 0; sub < 2; sub++) {
                    const int nf = n16 * 2 + sub;
                    mma16816(cQK[nf], qf[k16], &kb[sub * 2]);
                    mma16816(cQK[nf], qf[k16], &kl2[sub * 2]);
                }
            }
#pragma unroll
            for (int n16 = 0; n16 < 4; n16++) {
                uint32_t pb[4], pl2[4];
                ldsm4(pb,  sb + ST_PH + b_off + n16 * 2304 + ko);
                ldsm4(pl2, sb + ST_PL + b_off + n16 * 2304 + ko);
#pragma unroll
                for (int sub = 0; sub < 2; sub++) {
                    const int nf = n16 * 2 + sub;
                    mma16816(cQPn[nf], qf[k16], &pb[sub * 2]);
                    mma16816(cQPn[nf], qf[k16], &pl2[sub * 2]);
                }
            }
        }

        // spill new QP columns into the rotating buffer's target half
        const int hb = ((zt + 1) & 1) << 6;
#pragma unroll
        for (int nf = 0; nf < 8; nf++) {
            int j0 = hb + nf * 8 + colbase;
            *(float2*)&QPs[r0 * 132 + j0]       = make_float2(cQPn[nf][0], cQPn[nf][1]);
            *(float2*)&QPs[(r0 + 8) * 132 + j0] = make_float2(cQPn[nf][2], cQPn[nf][3]);
        }
        __syncwarp();

        // -------- logits + online softmax (rotating-gather) --------
        const float* ubS = (const float*)(smem + ST_UB);
        const float* bvS = (const float*)(smem + ST_BV);
        const int p0 = 63 - r0;
        const int p1 = 55 - r0;
        const int off = (zt & 1) << 6;           // rotation offset
        const float* row0p = &QPs[r0 * 132];
        const float* row1p = &QPs[(r0 + 8) * 132];
        float tm0 = -1e30f, tm1 = -1e30f;
#pragma unroll
        for (int nf = 0; nf < 8; nf++) {
            int j0 = nf * 8 + colbase, j1 = j0 + 1;
            float v0 = (cQK[nf][0] + row0p[(j0 + p0 + off) & 127] + ubS[j0] + bvS[j0 + p0]) * 0.125f;
            float v1 = (cQK[nf][1] + row0p[(j1 + p0 + off) & 127] + ubS[j1] + bvS[j1 + p0]) * 0.125f;
            float v2 = (cQK[nf][2] + row1p[(j0 + p1 + off) & 127] + ubS[j0] + bvS[j0 + p1]) * 0.125f;
            float v3 = (cQK[nf][3] + row1p[(j1 + p1 + off) & 127] + ubS[j1] + bvS[j1 + p1]) * 0.125f;
            if (zt == st) {
                if (j0 > r0) v0 = -1e30f;
                if (j1 > r0) v1 = -1e30f;
                if (j0 > r0 + 8) v2 = -1e30f;
                if (j1 > r0 + 8) v3 = -1e30f;
            }
            cQK[nf][0] = v0; cQK[nf][1] = v1; cQK[nf][2] = v2; cQK[nf][3] = v3;
            tm0 = fmaxf(tm0, fmaxf(v0, v1));
            tm1 = fmaxf(tm1, fmaxf(v2, v3));
        }
        tm0 = fmaxf(tm0, __shfl_xor_sync(0xffffffffu, tm0, 1));
        tm0 = fmaxf(tm0, __shfl_xor_sync(0xffffffffu, tm0, 2));
        tm1 = fmaxf(tm1, __shfl_xor_sync(0xffffffffu, tm1, 1));
        tm1 = fmaxf(tm1, __shfl_xor_sync(0xffffffffu, tm1, 2));

        float nm0 = fmaxf(mrow[0], tm0), nm1 = fmaxf(mrow[1], tm1);
        float sc0 = __expf(mrow[0] - nm0), sc1 = __expf(mrow[1] - nm1);

        __half* phs = (__half*)(smem + SM_PRB);
        float ps0 = 0.f, ps1 = 0.f;
#pragma unroll
        for (int nf = 0; nf < 8; nf++) {
            int j0 = nf * 8 + colbase;
            float e0 = __expf(cQK[nf][0] - nm0);
            float e1 = __expf(cQK[nf][1] - nm0);
            float e2 = __expf(cQK[nf][2] - nm1);
            float e3 = __expf(cQK[nf][3] - nm1);
            ps0 += e0 + e1;
            ps1 += e2 + e3;
            __half2 hv;
            hv.x = __float2half_rn(e0); hv.y = __float2half_rn(e1);
            *(__half2*)&phs[r0 * 72 + j0] = hv;
            hv.x = __float2half_rn(e2); hv.y = __float2half_rn(e3);
            *(__half2*)&phs[(r0 + 8) * 72 + j0] = hv;
        }
        ps0 += __shfl_xor_sync(0xffffffffu, ps0, 1);
        ps0 += __shfl_xor_sync(0xffffffffu, ps0, 2);
        ps1 += __shfl_xor_sync(0xffffffffu, ps1, 1);
        ps1 += __shfl_xor_sync(0xffffffffu, ps1, 2);
        lsum[0] = lsum[0] * sc0 + ps0;
        lsum[1] = lsum[1] * sc1 + ps1;
        mrow[0] = nm0; mrow[1] = nm1;

#pragma unroll
        for (int nf = 0; nf < 8; nf++) {
            cO[nf][0] *= sc0; cO[nf][1] *= sc0;
            cO[nf][2] *= sc1; cO[nf][3] *= sc1;
        }
        __syncwarp();

        // -------- PV MMA (probs x V), fp16x2 --------
#pragma unroll
        for (int k16 = 0; k16 < 4; k16++) {
            const int ko = k16 * 32;
            uint32_t aph[4];
            ldsm4(aph, sb + SM_PRB + wid * 2304 + a_off + ko);
#pragma unroll
            for (int n16 = 0; n16 < 4; n16++) {
                uint32_t vb[4], vl2[4];
                ldsm4t(vb,  sb + ST_VH + a_off + k16 * 2304 + n16 * 32);
                ldsm4t(vl2, sb + ST_VL + a_off + k16 * 2304 + n16 * 32);
#pragma unroll
                for (int sub = 0; sub < 2; sub++) {
                    const int nf = n16 * 2 + sub;
                    mma16816(cO[nf], aph, &vb[sub * 2]);
                    mma16816(cO[nf], aph, &vl2[sub * 2]);
                }
            }
        }
    }

    // -------- output: fp16 single --------
    const float i0 = 1.f / lsum[0];
    const float i1 = 1.f / lsum[1];
    const size_t row0 = (size_t)(b * S + s0 + r0);
    const size_t row1 = row0 + 8;
#pragma unroll
    for (int nf = 0; nf < 8; nf++) {
        int col = h * DK + nf * 8 + colbase;
        __half2 hv;
        hv.x = __float2half_rn(cO[nf][0] * i0);
        hv.y = __float2half_rn(cO[nf][1] * i0);
        *(__half2*)(Oh + row0 * D + col) = hv;
        hv.x = __float2half_rn(cO[nf][2] * i1);
        hv.y = __float2half_rn(cO[nf][3] * i1);
        *(__half2*)(Oh + row1 * D + col) = hv;
    }
}

// ---------------------------------------------------------------------------
// Launch
// ---------------------------------------------------------------------------
extern "C" void kernel_launch(void* const* d_in, const int* in_sizes, int n_in,
                              void* d_out, int out_size)
{
    const float* x      = (const float*)d_in[0];
    const float* Wq     = (const float*)d_in[1];
    const float* bq     = (const float*)d_in[2];
    const float* Wk     = (const float*)d_in[3];
    const float* bk     = (const float*)d_in[4];
    const float* Wv     = (const float*)d_in[5];
    const float* bv     = (const float*)d_in[6];
    const float* Wr     = (const float*)d_in[7];
    const float* br     = (const float*)d_in[8];
    const float* rel_u  = (const float*)d_in[9];
    const float* rel_v  = (const float*)d_in[10];
    const float* Wo     = (const float*)d_in[11];
    const float* bo     = (const float*)d_in[12];
    const float* relpos = (const float*)d_in[13];
    float* out = (float*)d_out;

    float *ubb, *bvb, *uwb, *vwb, *cuvb;
    cudaGetSymbolAddress((void**)&ubb,  g_ub);
    cudaGetSymbolAddress((void**)&bvb,  g_Bv);
    cudaGetSymbolAddress((void**)&uwb,  g_uw);
    cudaGetSymbolAddress((void**)&vwb,  g_vw);
    cudaGetSymbolAddress((void**)&cuvb, g_cuv);

    __half *xh, *Rh, *Wsh, *Wsl, *vh;
    __half *Qbh, *Kbh, *Kbl, *Vbh, *Vbl, *Pbh, *Pbl;
    cudaGetSymbolAddress((void**)&xh,  g_xh);
    cudaGetSymbolAddress((void**)&Rh,  g_Rh);
    cudaGetSymbolAddress((void**)&Wsh, g_Wsh);
    cudaGetSymbolAddress((void**)&Wsl, g_Wsl);
    cudaGetSymbolAddress((void**)&vh,  g_vh);
    cudaGetSymbolAddress((void**)&Qbh, g_Qbh);
    cudaGetSymbolAddress((void**)&Kbh, g_Kbh);
    cudaGetSymbolAddress((void**)&Kbl, g_Kbl);
    cudaGetSymbolAddress((void**)&Vbh, g_Vbh);
    cudaGetSymbolAddress((void**)&Vbl, g_Vbl);
    cudaGetSymbolAddress((void**)&Pbh, g_Pbh);
    cudaGetSymbolAddress((void**)&Pbl, g_Pbl);

    const float* R = relpos + (size_t)1 * D;   // rows [1, 2048)

    // --- conversions + rel contractions ---
    cvt_kernel<<<(BS * D + 255) / 256, 256>>>(x, xh, BS * D);
    SplitBatch sw;
    sw.src[0] = Wq; sw.src[1] = Wk; sw.src[2] = Wv; sw.src[3] = Wr; sw.src[4] = Wo;
    splitW_kernel<<<dim3(D * D / 256, 5), 256>>>(sw, Wsh, Wsl);
    cvt_kernel<<<(LP * D + 255) / 256, 256>>>(R, Rh, LP * D);
    contract_w<<<2 * H * D / 256, 256>>>(Wr, rel_u, rel_v, uwb, vwb);
    contract_c<<<1, 32>>>(br, rel_u, rel_v, cuvb);

    // --- ubias / Bv via rank-16 GEMMs (exact fp32) ---
    rank16_kernel<<<(BS + 7) / 8, 256>>>(x, uwb, cuvb, ubb, BS, 0);
    rank16_kernel<<<(LP + 7) / 8, 256>>>(R, vwb, cuvb, bvb, LP, 1);

    cudaFuncSetAttribute(gemm_tc, cudaFuncAttributeMaxDynamicSharedMemorySize,
                         GEMM_SMEM);

    // --- Q/K/V + P projections (merged, grid.z = 4; z=3 is P from R) ---
    GemmBatch b1 = {};
    b1.Wh[0] = Wsh + 0 * (size_t)D * D; b1.Wl[0] = Wsl + 0 * (size_t)D * D;
    b1.bias[0] = bq; b1.mode[0] = 2; b1.Ch[0] = Qbh;                 // Q: single
    b1.Wh[1] = Wsh + 1 * (size_t)D * D; b1.Wl[1] = Wsl + 1 * (size_t)D * D;
    b1.bias[1] = bk; b1.mode[1] = 1; b1.Ch[1] = Kbh; b1.Cl[1] = Kbl; // K: hi+lo
    b1.Wh[2] = Wsh + 2 * (size_t)D * D; b1.Wl[2] = Wsl + 2 * (size_t)D * D;
    b1.bias[2] = bv; b1.mode[2] = 1; b1.Ch[2] = Vbh; b1.Cl[2] = Vbl; // V: hi+lo
    b1.Wh[3] = Wsh + 1 * (size_t)D * D; b1.Wl[3] = Wsl + 1 * (size_t)D * D;
    b1.bias[3] = bk; b1.mode[3] = 1; b1.Ch[3] = Pbh; b1.Cl[3] = Pbl; // P: hi+lo
    gemm_tc<<<dim3(8, 32, 4), 256, GEMM_SMEM>>>(xh, Rh, b1, BS, LP);

    // --- tensorized attention (2 CTAs/SM, QP shift-reuse) ---
    cudaFuncSetAttribute(attn_mma, cudaFuncAttributeMaxDynamicSharedMemorySize,
                         ATTN_SMEM_BYTES);
    attn_mma<<<dim3(B * H, S / 64), 128, ATTN_SMEM_BYTES>>>(
        Qbh, Kbh, Kbl, Vbh, Vbl, Pbh, Pbl, ubb, bvb, vh);

    // --- output projection (fp32 out) ---
    GemmBatch b3 = {};
    b3.Wh[0] = Wsh + 4 * (size_t)D * D; b3.Wl[0] = Wsl + 4 * (size_t)D * D;
    b3.bias[0] = bo; b3.mode[0] = 0; b3.C[0] = out;
    gemm_tc<<<dim3(8, 32, 1), 256, GEMM_SMEM>>>(vh, nullptr, b3, BS, BS);
}

// round 15
// speedup vs baseline: 2.2528x; 1.0334x over previous
#include <cuda_runtime.h>
#include <cuda_fp16.h>
#include <cstdint>

// Problem constants
#define B 4
#define S 1024
#define D 1024
#define H 16
#define DK 64
#define L 2047          // 2*S - 1
#define LP 1088         // P rows actually used by attention (max read 1087)
#define BS (B*S)        // 4096

// ---------------------------------------------------------------------------
// Scratch (static device globals; no runtime allocation allowed)
// ---------------------------------------------------------------------------
__device__ float g_ub[B * H * S];
__device__ float g_Bv[H * L];
__device__ float g_uw[H * D];
__device__ float g_vw[H * D];
__device__ float g_cuv[32];

// fp16 operands. A-side tensors: single fp16. B-side tensors: hi+lo pair.
__device__ __half g_xh[BS * D];                      // A of projections
__device__ __half g_Rh[LP * D];                      // A of P projection
__device__ __half g_Wsh[5 * D * D], g_Wsl[5 * D * D];// q,k,v,r,o (B side)

__device__ __half g_Qbh[BS * D];                     // A of QK/QP
__device__ __half g_Kbh[BS * D], g_Kbl[BS * D];      // B of QK
__device__ __half g_Vbh[BS * D], g_Vbl[BS * D];      // B of PV
__device__ __half g_Pbh[LP * D], g_Pbl[LP * D];      // B of QP

__device__ __half g_vh[BS * D];                      // attn out = A of out-proj

// ---------------------------------------------------------------------------
// PTX helpers: portable sm_80+ (ldmatrix / mma.sync / cp.async).
// ---------------------------------------------------------------------------
__device__ __forceinline__ uint32_t smem_to_u32(const void* p) {
    uint32_t a;
    asm("{ .reg .u64 t; cvta.to.shared.u64 t, %1; cvt.u32.u64 %0, t; }"
        : "=r"(a) : "l"(p));
    return a;
}

__device__ __forceinline__ void ldsm4(uint32_t* r, uint32_t addr) {
    asm volatile("ldmatrix.sync.aligned.m8n8.x4.shared.b16 {%0,%1,%2,%3}, [%4];"
                 : "=r"(r[0]), "=r"(r[1]), "=r"(r[2]), "=r"(r[3]) : "r"(addr));
}
__device__ __forceinline__ void ldsm4t(uint32_t* r, uint32_t addr) {
    asm volatile("ldmatrix.sync.aligned.m8n8.x4.trans.shared.b16 {%0,%1,%2,%3}, [%4];"
                 : "=r"(r[0]), "=r"(r[1]), "=r"(r[2]), "=r"(r[3]) : "r"(addr));
}

__device__ __forceinline__ void mma16816(float* d, const uint32_t* a,
                                         const uint32_t* b) {
    asm volatile(
        "mma.sync.aligned.m16n8k16.row.col.f32.f16.f16.f32 "
        "{%0,%1,%2,%3}, {%4,%5,%6,%7}, {%8,%9}, {%0,%1,%2,%3};"
        : "+f"(d[0]), "+f"(d[1]), "+f"(d[2]), "+f"(d[3])
        : "r"(a[0]), "r"(a[1]), "r"(a[2]), "r"(a[3]), "r"(b[0]), "r"(b[1]));
}

__device__ __forceinline__ void cp16(uint32_t dst, const void* src, int sz) {
    asm volatile("cp.async.cg.shared.global [%0], [%1], 16, %2;\n"
                 :: "r"(dst), "l"(src), "r"(sz));
}
__device__ __forceinline__ void cp_commit() {
    asm volatile("cp.async.commit_group;\n" ::: "memory");
}
template <int N> __device__ __forceinline__ void cp_wait() {
    asm volatile("cp.async.wait_group %0;\n" :: "n"(N) : "memory");
}

// ---------------------------------------------------------------------------
// Weight split: fp32 -> fp16 hi + lo
// ---------------------------------------------------------------------------
struct SplitBatch { const float* src[5]; };

__global__ void splitW_kernel(const SplitBatch sb,
                              __half* __restrict__ hi,
                              __half* __restrict__ lo)
{
    int z = blockIdx.y;
    int i = blockIdx.x * 256 + threadIdx.x;
    size_t off = (size_t)z * D * D + i;
    float x = sb.src[z][i];
    __half h = __float2half_rn(x);
    hi[off] = h;
    lo[off] = __float2half_rn(x - __half2float(h));
}

// ---------------------------------------------------------------------------
// rel_u/rel_v pre-contraction (replaces the KR and PR full projections)
// contract_c fused into block 0.
// ---------------------------------------------------------------------------
__global__ void contract_w(const float* __restrict__ Wr,
                           const float* __restrict__ br,
                           const float* __restrict__ rel_u,
                           const float* __restrict__ rel_v,
                           float* __restrict__ uw, float* __restrict__ vw,
                           float* __restrict__ cuv)
{
    if (blockIdx.x == 0 && threadIdx.x < 32) {
        int t = threadIdx.x;
        int h = t & 15;
        const float* rel = (t < 16) ? rel_u : rel_v;
        float s = 0.f;
        for (int d = 0; d < DK; d++)
            s = fmaf(rel[h * DK + d], br[h * DK + d], s);
        cuv[t] = s;
    }
    int idx = blockIdx.x * 256 + threadIdx.x;   // 0 .. 2*H*D-1
    int t  = idx >> 14;                          // 0: uw, 1: vw
    int he = idx & (H * D - 1);
    int h = he >> 10;
    int e = he & (D - 1);
    const float* rel = t ? rel_v : rel_u;
    float s = 0.f;
#pragma unroll 8
    for (int d = 0; d < DK; d++)
        s = fmaf(__ldg(&rel[h * DK + d]), Wr[(size_t)(h * DK + d) * D + e], s);
    (t ? vw : uw)[he] = s;
}

// warp-per-row rank-16 GEMM: out = A_row . w[h] + c[h]; ALSO emits the
// fp16 copy of A (fuses the old cvt_kernel — A is read fully anyway).
// mode 0 (ubias): A = x [4096 rows], out[(b*H+h)*S + z]
// mode 1 (Bv):    A = R [LP rows],   out[h*L + l]
__global__ __launch_bounds__(256) void rank16_cvt_kernel(
    const float* __restrict__ A, const float* __restrict__ w,
    const float* __restrict__ c, float* __restrict__ out,
    __half* __restrict__ A16, int nrows, int mode)
{
    int row  = blockIdx.x * 8 + (threadIdx.x >> 5);
    int lane = threadIdx.x & 31;
    if (row >= nrows) return;
    const float4* ar = (const float4*)(A + (size_t)row * D);
    __half* a16r = A16 + (size_t)row * D;
    float acc[16];
#pragma unroll
    for (int h = 0; h < 16; h++) acc[h] = 0.f;
#pragma unroll
    for (int j = 0; j < 8; j++) {
        float4 xv = ar[lane + j * 32];
        __half2 h01, h23;
        h01.x = __float2half_rn(xv.x); h01.y = __float2half_rn(xv.y);
        h23.x = __float2half_rn(xv.z); h23.y = __float2half_rn(xv.w);
        *(__half2*)(a16r + 4 * (lane + j * 32))     = h01;
        *(__half2*)(a16r + 4 * (lane + j * 32) + 2) = h23;
#pragma unroll
        for (int h = 0; h < 16; h++) {
            float4 wv = ((const float4*)(w + h * D))[lane + j * 32];
            acc[h] += xv.x * wv.x + xv.y * wv.y + xv.z * wv.z + xv.w * wv.w;
        }
    }
    float mine = 0.f;
#pragma unroll
    for (int h = 0; h < 16; h++) {
        float v = acc[h];
        v += __shfl_xor_sync(0xffffffffu, v, 16);
        v += __shfl_xor_sync(0xffffffffu, v, 8);
        v += __shfl_xor_sync(0xffffffffu, v, 4);
        v += __shfl_xor_sync(0xffffffffu, v, 2);
        v += __shfl_xor_sync(0xffffffffu, v, 1);
        if (lane == h) mine = v;
    }
    if (lane < 16) {
        float val = mine + c[lane + (mode == 1 ? 16 : 0)];
        if (mode == 0) {
            int b = row >> 10, z = row & 1023;
            out[((b << 4) + lane) * S + z] = val;
        } else {
            out[lane * L + row] = val;
        }
    }
}

// ---------------------------------------------------------------------------
// HMMA GEMM: C[M,1024] = A[M,1024] @ W[1024,1024]^T + bias
// fp16x2: A single fp16, W hi+lo fp16 -> 2 MMA passes. 3-stage cp.async
// pipeline. mode 0: fp32 C.  mode 1: fp16 hi+lo outputs.  mode 2: fp16 hi.
// z < 3: A = Ah1, M = M1.  z >= 3: A = Ah2, M = M2.
// ---------------------------------------------------------------------------
struct GemmBatch {
    const __half* Wh[4];
    const __half* Wl[4];
    const float* bias[4];
    float* C[4];
    __half* Ch[4];
    __half* Cl[4];
    int mode[4];
};

#define RS      40                   // fp16 elems per smem row slot (80 bytes)
#define TILE_B  (128 * RS * 2)       // 10240 B
#define STAGE_B (3 * TILE_B)         // A, Wh, Wl  (30720 B)
#define NSTAGE  3
#define GEMM_SMEM (NSTAGE * STAGE_B) // 92160
#define NC      32

__device__ __forceinline__ void load_chunk(
    uint32_t sbase, int tid,
    const __half* Ah, const __half* Wh, const __half* Wl,
    int bm, int bn, int M, int c, int st)
{
    const int kbase = c * 32;
    const uint32_t stoff = sbase + st * STAGE_B;
#pragma unroll
    for (int t = 0; t < 3; t++) {
        const __half* base = (t == 0) ? Ah : (t == 1) ? Wh : Wl;
        const int rb = (t == 0) ? bm : bn;
#pragma unroll
        for (int j = 0; j < 2; j++) {
            int idx = tid + j * 256;          // 0..511
            int row = idx >> 2, g = idx & 3;
            int gr = rb + row;
            int sz = (t >= 1 || gr < M) ? 16 : 0;
            const void* src = base + (size_t)gr * 1024 + kbase + g * 8;
            uint32_t dst = stoff + t * TILE_B + row * 80 + g * 16;
            cp16(dst, src, sz);
        }
    }
}

__global__ __launch_bounds__(256, 2)
void gemm_tc(const __half* __restrict__ Ah1,
             const __half* __restrict__ Ah2,
             const GemmBatch bat, int M1, int M2)
{
    extern __shared__ char smem[];
    const uint32_t sbase = smem_to_u32(smem);
    const int tid  = threadIdx.x;
    const int wid  = tid >> 5;
    const int lane = tid & 31;
    const int bn = blockIdx.x * 128;
    const int bm = blockIdx.y * 128;
    const int z  = blockIdx.z;

    const __half* Ah = (z < 3) ? Ah1 : Ah2;
    const int M = (z < 3) ? M1 : M2;
    if (bm >= M) return;               // early-exit tail tiles (P trim)

    const __half* Wh = bat.Wh[z];
    const __half* Wl = bat.Wl[z];

    const int mb = (wid >> 2) * 64;
    const int nb = (wid & 3) * 32;

    const int li = lane >> 3, lr = lane & 7;
    const int a_off = ((li & 1) * 8 + lr) * 80 + (li >> 1) * 16;
    const int b_off = ((li >> 1) * 8 + lr) * 80 + (li & 1) * 16;

    float acc[4][4][4];
#pragma unroll
    for (int mf = 0; mf < 4; mf++)
#pragma unroll
        for (int nf = 0; nf < 4; nf++)
#pragma unroll
            for (int e = 0; e < 4; e++) acc[mf][nf][e] = 0.f;

    // 3-stage prologue: chunks 0 and 1 in flight
    load_chunk(sbase, tid, Ah, Wh, Wl, bm, bn, M, 0, 0);
    cp_commit();
    load_chunk(sbase, tid, Ah, Wh, Wl, bm, bn, M, 1, 1);
    cp_commit();

    int st = 0;
    for (int c = 0; c < NC; c++) {
        if (c + 1 < NC) cp_wait<1>();   // chunk c resident, c+1 may be in flight
        else            cp_wait<0>();
        __syncthreads();                // all warps done with buffer st's prior use
        if (c + 2 < NC) {
            int st2 = st + 2; if (st2 >= NSTAGE) st2 -= NSTAGE;
            load_chunk(sbase, tid, Ah, Wh, Wl, bm, bn, M, c + 2, st2);
            cp_commit();
        }

        const uint32_t aT = sbase + st * STAGE_B + 0 * TILE_B + (mb)*80 + a_off;
        const uint32_t wH = sbase + st * STAGE_B + 1 * TILE_B + (nb)*80 + b_off;
        const uint32_t wL = wH + TILE_B;

#pragma unroll
        for (int k16 = 0; k16 < 2; k16++) {
            const int ko = k16 * 32;
            uint32_t ah[4][4], bh[2][4], bl[2][4];
#pragma unroll
            for (int mf = 0; mf < 4; mf++)
                ldsm4(ah[mf], aT + mf * 16 * 80 + ko);
#pragma unroll
            for (int n2 = 0; n2 < 2; n2++) {
                ldsm4(bh[n2], wH + n2 * 16 * 80 + ko);
                ldsm4(bl[n2], wL + n2 * 16 * 80 + ko);
            }
#pragma unroll
            for (int mf = 0; mf < 4; mf++)
#pragma unroll
                for (int nf = 0; nf < 4; nf++) {
                    const uint32_t* bph = &bh[nf >> 1][(nf & 1) * 2];
                    const uint32_t* bpl = &bl[nf >> 1][(nf & 1) * 2];
                    mma16816(acc[mf][nf], ah[mf], bph);
                    mma16816(acc[mf][nf], ah[mf], bpl);
                }
        }
        if (++st >= NSTAGE) st = 0;
    }

    const float* bias = bat.bias[z];
    const int lr4 = lane >> 2, lc2 = (lane & 3) * 2;
    const int mode = bat.mode[z];
    if (mode == 0) {
        float* C = bat.C[z];
#pragma unroll
        for (int mf = 0; mf < 4; mf++)
#pragma unroll
            for (int nf = 0; nf < 4; nf++) {
                int gn = bn + nb + nf * 8 + lc2;
                float2 bi = *(const float2*)(bias + gn);
                int gm0 = bm + mb + mf * 16 + lr4;
                if (gm0 < M) {
                    float2 v = make_float2(acc[mf][nf][0] + bi.x, acc[mf][nf][1] + bi.y);
                    *(float2*)(C + (size_t)gm0 * 1024 + gn) = v;
                }
                int gm1 = gm0 + 8;
                if (gm1 < M) {
                    float2 v = make_float2(acc[mf][nf][2] + bi.x, acc[mf][nf][3] + bi.y);
                    *(float2*)(C + (size_t)gm1 * 1024 + gn) = v;
                }
            }
    } else if (mode == 1) {
        __half* Ch = bat.Ch[z];
        __half* Cl = bat.Cl[z];
#pragma unroll
        for (int mf = 0; mf < 4; mf++)
#pragma unroll
            for (int nf = 0; nf < 4; nf++) {
                int gn = bn + nb + nf * 8 + lc2;
                float2 bi = *(const float2*)(bias + gn);
#pragma unroll
                for (int half_i = 0; half_i < 2; half_i++) {
                    int gm = bm + mb + mf * 16 + lr4 + half_i * 8;
                    if (gm < M) {
                        float vx = acc[mf][nf][half_i * 2 + 0] + bi.x;
                        float vy = acc[mf][nf][half_i * 2 + 1] + bi.y;
                        __half hx = __float2half_rn(vx);
                        __half hy = __float2half_rn(vy);
                        __half2 hv; hv.x = hx; hv.y = hy;
                        __half2 lv;
                        lv.x = __float2half_rn(vx - __half2float(hx));
                        lv.y = __float2half_rn(vy - __half2float(hy));
                        *(__half2*)(Ch + (size_t)gm * 1024 + gn) = hv;
                        *(__half2*)(Cl + (size_t)gm * 1024 + gn) = lv;
                    }
                }
            }
    } else {
        __half* Ch = bat.Ch[z];
#pragma unroll
        for (int mf = 0; mf < 4; mf++)
#pragma unroll
            for (int nf = 0; nf < 4; nf++) {
                int gn = bn + nb + nf * 8 + lc2;
                float2 bi = *(const float2*)(bias + gn);
#pragma unroll
                for (int half_i = 0; half_i < 2; half_i++) {
                    int gm = bm + mb + mf * 16 + lr4 + half_i * 8;
                    if (gm < M) {
                        __half2 hv;
                        hv.x = __float2half_rn(acc[mf][nf][half_i * 2 + 0] + bi.x);
                        hv.y = __float2half_rn(acc[mf][nf][half_i * 2 + 1] + bi.y);
                        *(__half2*)(Ch + (size_t)gm * 1024 + gn) = hv;
                    }
                }
            }
    }
}

// ---------------------------------------------------------------------------
// Tensorized fused relative attention (flash-style, causal, fp16x2 MMA).
// Toeplitz-shift QP reuse (rotating 64x128 fp32 buffer); Q single fp16 in
// registers; probs single fp16. CTA: 64 q-rows, 4 warps, 2 CTAs/SM.
// ---------------------------------------------------------------------------
#define ATS      144                 // smem row stride bytes (72 fp16)
#define ST_KH    0                   // 64 x ATS
#define ST_KL    9216
#define ST_VH    18432
#define ST_VL    27648
#define ST_PH    36864               // 64 rows (new P window half)
#define ST_PL    46080
#define ST_UB    55296               // 64 floats
#define ST_BV    55552               // 127 floats (pad to 512)
#define SM_QPS   56064               // fp32 64 x 132 rotating QP = 33792
#define SM_PRB   89856               // probs fp16 single = 9216
#define ATTN_SMEM_BYTES 99072        // 2 CTAs/SM

__device__ __forceinline__ void attn_load_kv(
    uint32_t sb, int tid,
    const __half* Kh, const __half* Kl,
    const __half* Vh, const __half* Vl)
{
#pragma unroll
    for (int j = 0; j < 4; j++) {
        int idx = tid + j * 128;
        int row = idx >> 3, g = idx & 7;
        const size_t go = (size_t)row * D + g * 8;
        uint32_t so = row * ATS + g * 16;
        cp16(sb + ST_KH + so, Kh + go, 16);
        cp16(sb + ST_KL + so, Kl + go, 16);
        cp16(sb + ST_VH + so, Vh + go, 16);
        cp16(sb + ST_VL + so, Vl + go, 16);
    }
}

__device__ __forceinline__ void attn_load_p(
    uint32_t sb, int tid,
    const __half* Ph, const __half* Pl)
{
#pragma unroll
    for (int j = 0; j < 4; j++) {
        int idx = tid + j * 128;
        int row = idx >> 3, g = idx & 7;
        const size_t go = (size_t)row * D + g * 8;
        uint32_t so = row * ATS + g * 16;
        cp16(sb + ST_PH + so, Ph + go, 16);
        cp16(sb + ST_PL + so, Pl + go, 16);
    }
}

__global__ __launch_bounds__(128, 2) void attn_mma(
    const __half* __restrict__ Qh,
    const __half* __restrict__ Kh, const __half* __restrict__ Kl,
    const __half* __restrict__ Vh, const __half* __restrict__ Vl,
    const __half* __restrict__ Ph, const __half* __restrict__ Pl,
    const float* __restrict__ ubias, const float* __restrict__ Bv,
    __half* __restrict__ Oh)
{
    extern __shared__ char smem[];
    const uint32_t sb = smem_to_u32(smem);
    const int tid  = threadIdx.x;
    const int wid  = tid >> 5;
    const int lane = tid & 31;
    const int st = (S / 64 - 1) - blockIdx.y;    // heavy tiles first
    const int b  = blockIdx.x >> 4;
    const int h  = blockIdx.x & 15;
    const int s0 = st * 64;

    const int li = lane >> 3, lr = lane & 7;
    const int a_off = ((li & 1) * 8 + lr) * ATS + (li >> 1) * 16;
    const int b_off = ((li >> 1) * 8 + lr) * ATS + (li & 1) * 16;

    const int r0 = wid * 16 + (lane >> 2);
    const int colbase = (lane & 3) * 2;

    float* QPs = (float*)(smem + SM_QPS);

    // -------- prologue: stage Q once (single fp16), lift to registers ----
    uint32_t qf[4][4];
    {
        const __half* Qg = Qh + (size_t)(b * S + s0) * D + h * DK;
#pragma unroll
        for (int j = 0; j < 4; j++) {
            int idx = tid + j * 128;
            int row = idx >> 3, g = idx & 7;
            cp16(sb + ST_KH + row * ATS + g * 16, Qg + (size_t)row * D + g * 8, 16);
        }
        cp_commit();
        cp_wait<0>();
        __syncthreads();
#pragma unroll
        for (int k16 = 0; k16 < 4; k16++)
            ldsm4(qf[k16], sb + ST_KH + wid * 2304 + a_off + k16 * 32);
    }

    // -------- QP prologue (zt = -1): seed physical half 0 --------
    {
        const int prow0 = 960 - st * 64;
        __syncthreads();
        attn_load_p(sb, tid,
                    Ph + (size_t)prow0 * D + h * DK,
                    Pl + (size_t)prow0 * D + h * DK);
        cp_commit();
        cp_wait<0>();
        __syncthreads();

        float cQPn[8][4];
#pragma unroll
        for (int nf = 0; nf < 8; nf++)
#pragma unroll
            for (int e = 0; e < 4; e++) cQPn[nf][e] = 0.f;
#pragma unroll
        for (int k16 = 0; k16 < 4; k16++) {
            const int ko = k16 * 32;
#pragma unroll
            for (int n16 = 0; n16 < 4; n16++) {
                uint32_t pb[4], pl2[4];
                ldsm4(pb,  sb + ST_PH + b_off + n16 * 2304 + ko);
                ldsm4(pl2, sb + ST_PL + b_off + n16 * 2304 + ko);
#pragma unroll
                for (int sub = 0; sub < 2; sub++) {
                    const int nf = n16 * 2 + sub;
                    mma16816(cQPn[nf], qf[k16], &pb[sub * 2]);
                    mma16816(cQPn[nf], qf[k16], &pl2[sub * 2]);
                }
            }
        }
#pragma unroll
        for (int nf = 0; nf < 8; nf++) {
            int j0 = nf * 8 + colbase;       // physical half 0
            *(float2*)&QPs[r0 * 132 + j0]       = make_float2(cQPn[nf][0], cQPn[nf][1]);
            *(float2*)&QPs[(r0 + 8) * 132 + j0] = make_float2(cQPn[nf][2], cQPn[nf][3]);
        }
        __syncwarp();
    }

    float cO[8][4];
#pragma unroll
    for (int nf = 0; nf < 8; nf++)
#pragma unroll
        for (int e = 0; e < 4; e++) cO[nf][e] = 0.f;
    float mrow[2] = {-1e30f, -1e30f};
    float lsum[2] = {0.f, 0.f};

    for (int zt = 0; zt <= st; zt++) {
        __syncthreads();   // previous iteration's K/V/P reads complete

        const int z0 = zt * 64;
        const int lbase = (zt - st) * 64 + 960;
        const int prow0 = lbase + 64;            // new 64 P rows
        const size_t kvoff = (size_t)(b * S + z0) * D + h * DK;
        attn_load_kv(sb, tid, Kh + kvoff, Kl + kvoff, Vh + kvoff, Vl + kvoff);
        attn_load_p(sb, tid,
                    Ph + (size_t)prow0 * D + h * DK,
                    Pl + (size_t)prow0 * D + h * DK);
        {
            float* ubS = (float*)(smem + ST_UB);
            float* bvS = (float*)(smem + ST_BV);
            if (tid < 64)  ubS[tid] = ubias[(b * H + h) * S + z0 + tid];
            if (tid < 127) bvS[tid] = Bv[h * L + lbase + tid];
        }
        cp_commit();
        cp_wait<0>();
        __syncthreads();

        // -------- QK (64x64) + QP-new (64x64), fp16x2, Q from regs ----
        float cQK[8][4], cQPn[8][4];
#pragma unroll
        for (int nf = 0; nf < 8; nf++)
#pragma unroll
            for (int e = 0; e < 4; e++) { cQK[nf][e] = 0.f; cQPn[nf][e] = 0.f; }

#pragma unroll
        for (int k16 = 0; k16 < 4; k16++) {
            const int ko = k16 * 32;
#pragma unroll
            for (int n16 = 0; n16 < 4; n16++) {
                uint32_t kb[4], kl2[4];
                ldsm4(kb,  sb + ST_KH + b_off + n16 * 2304 + ko);
                ldsm4(kl2, sb + ST_KL + b_off + n16 * 2304 + ko);
#pragma unroll
                for (int sub = 0; sub < 2; sub++) {
                    const int nf = n16 * 2 + sub;
                    mma16816(cQK[nf], qf[k16], &kb[sub * 2]);
                    mma16816(cQK[nf], qf[k16], &kl2[sub * 2]);
                }
            }
#pragma unroll
            for (int n16 = 0; n16 < 4; n16++) {
                uint32_t pb[4], pl2[4];
                ldsm4(pb,  sb + ST_PH + b_off + n16 * 2304 + ko);
                ldsm4(pl2, sb + ST_PL + b_off + n16 * 2304 + ko);
#pragma unroll
                for (int sub = 0; sub < 2; sub++) {
                    const int nf = n16 * 2 + sub;
                    mma16816(cQPn[nf], qf[k16], &pb[sub * 2]);
                    mma16816(cQPn[nf], qf[k16], &pl2[sub * 2]);
                }
            }
        }

        // spill new QP columns into the rotating buffer's target half
        const int hb = ((zt + 1) & 1) << 6;
#pragma unroll
        for (int nf = 0; nf < 8; nf++) {
            int j0 = hb + nf * 8 + colbase;
            *(float2*)&QPs[r0 * 132 + j0]       = make_float2(cQPn[nf][0], cQPn[nf][1]);
            *(float2*)&QPs[(r0 + 8) * 132 + j0] = make_float2(cQPn[nf][2], cQPn[nf][3]);
        }
        __syncwarp();

        // -------- logits + online softmax (rotating-gather) --------
        const float* ubS = (const float*)(smem + ST_UB);
        const float* bvS = (const float*)(smem + ST_BV);
        const int p0 = 63 - r0;
        const int p1 = 55 - r0;
        const int off = (zt & 1) << 6;           // rotation offset
        const float* row0p = &QPs[r0 * 132];
        const float* row1p = &QPs[(r0 + 8) * 132];
        float tm0 = -1e30f, tm1 = -1e30f;
#pragma unroll
        for (int nf = 0; nf < 8; nf++) {
            int j0 = nf * 8 + colbase, j1 = j0 + 1;
            float v0 = (cQK[nf][0] + row0p[(j0 + p0 + off) & 127] + ubS[j0] + bvS[j0 + p0]) * 0.125f;
            float v1 = (cQK[nf][1] + row0p[(j1 + p0 + off) & 127] + ubS[j1] + bvS[j1 + p0]) * 0.125f;
            float v2 = (cQK[nf][2] + row1p[(j0 + p1 + off) & 127] + ubS[j0] + bvS[j0 + p1]) * 0.125f;
            float v3 = (cQK[nf][3] + row1p[(j1 + p1 + off) & 127] + ubS[j1] + bvS[j1 + p1]) * 0.125f;
            if (zt == st) {
                if (j0 > r0) v0 = -1e30f;
                if (j1 > r0) v1 = -1e30f;
                if (j0 > r0 + 8) v2 = -1e30f;
                if (j1 > r0 + 8) v3 = -1e30f;
            }
            cQK[nf][0] = v0; cQK[nf][1] = v1; cQK[nf][2] = v2; cQK[nf][3] = v3;
            tm0 = fmaxf(tm0, fmaxf(v0, v1));
            tm1 = fmaxf(tm1, fmaxf(v2, v3));
        }
        tm0 = fmaxf(tm0, __shfl_xor_sync(0xffffffffu, tm0, 1));
        tm0 = fmaxf(tm0, __shfl_xor_sync(0xffffffffu, tm0, 2));
        tm1 = fmaxf(tm1, __shfl_xor_sync(0xffffffffu, tm1, 1));
        tm1 = fmaxf(tm1, __shfl_xor_sync(0xffffffffu, tm1, 2));

        float nm0 = fmaxf(mrow[0], tm0), nm1 = fmaxf(mrow[1], tm1);
        float sc0 = __expf(mrow[0] - nm0), sc1 = __expf(mrow[1] - nm1);

        __half* phs = (__half*)(smem + SM_PRB);
        float ps0 = 0.f, ps1 = 0.f;
#pragma unroll
        for (int nf = 0; nf < 8; nf++) {
            int j0 = nf * 8 + colbase;
            float e0 = __expf(cQK[nf][0] - nm0);
            float e1 = __expf(cQK[nf][1] - nm0);
            float e2 = __expf(cQK[nf][2] - nm1);
            float e3 = __expf(cQK[nf][3] - nm1);
            ps0 += e0 + e1;
            ps1 += e2 + e3;
            __half2 hv;
            hv.x = __float2half_rn(e0); hv.y = __float2half_rn(e1);
            *(__half2*)&phs[r0 * 72 + j0] = hv;
            hv.x = __float2half_rn(e2); hv.y = __float2half_rn(e3);
            *(__half2*)&phs[(r0 + 8) * 72 + j0] = hv;
        }
        ps0 += __shfl_xor_sync(0xffffffffu, ps0, 1);
        ps0 += __shfl_xor_sync(0xffffffffu, ps0, 2);
        ps1 += __shfl_xor_sync(0xffffffffu, ps1, 1);
        ps1 += __shfl_xor_sync(0xffffffffu, ps1, 2);
        lsum[0] = lsum[0] * sc0 + ps0;
        lsum[1] = lsum[1] * sc1 + ps1;
        mrow[0] = nm0; mrow[1] = nm1;

#pragma unroll
        for (int nf = 0; nf < 8; nf++) {
            cO[nf][0] *= sc0; cO[nf][1] *= sc0;
            cO[nf][2] *= sc1; cO[nf][3] *= sc1;
        }
        __syncwarp();

        // -------- PV MMA (probs x V), fp16x2 --------
#pragma unroll
        for (int k16 = 0; k16 < 4; k16++) {
            const int ko = k16 * 32;
            uint32_t aph[4];
            ldsm4(aph, sb + SM_PRB + wid * 2304 + a_off + ko);
#pragma unroll
            for (int n16 = 0; n16 < 4; n16++) {
                uint32_t vb[4], vl2[4];
                ldsm4t(vb,  sb + ST_VH + a_off + k16 * 2304 + n16 * 32);
                ldsm4t(vl2, sb + ST_VL + a_off + k16 * 2304 + n16 * 32);
#pragma unroll
                for (int sub = 0; sub < 2; sub++) {
                    const int nf = n16 * 2 + sub;
                    mma16816(cO[nf], aph, &vb[sub * 2]);
                    mma16816(cO[nf], aph, &vl2[sub * 2]);
                }
            }
        }
    }

    // -------- output: fp16 single --------
    const float i0 = 1.f / lsum[0];
    const float i1 = 1.f / lsum[1];
    const size_t row0 = (size_t)(b * S + s0 + r0);
    const size_t row1 = row0 + 8;
#pragma unroll
    for (int nf = 0; nf < 8; nf++) {
        int col = h * DK + nf * 8 + colbase;
        __half2 hv;
        hv.x = __float2half_rn(cO[nf][0] * i0);
        hv.y = __float2half_rn(cO[nf][1] * i0);
        *(__half2*)(Oh + row0 * D + col) = hv;
        hv.x = __float2half_rn(cO[nf][2] * i1);
        hv.y = __float2half_rn(cO[nf][3] * i1);
        *(__half2*)(Oh + row1 * D + col) = hv;
    }
}

// ---------------------------------------------------------------------------
// Launch
// ---------------------------------------------------------------------------
extern "C" void kernel_launch(void* const* d_in, const int* in_sizes, int n_in,
                              void* d_out, int out_size)
{
    const float* x      = (const float*)d_in[0];
    const float* Wq     = (const float*)d_in[1];
    const float* bq     = (const float*)d_in[2];
    const float* Wk     = (const float*)d_in[3];
    const float* bk     = (const float*)d_in[4];
    const float* Wv     = (const float*)d_in[5];
    const float* bv     = (const float*)d_in[6];
    const float* Wr     = (const float*)d_in[7];
    const float* br     = (const float*)d_in[8];
    const float* rel_u  = (const float*)d_in[9];
    const float* rel_v  = (const float*)d_in[10];
    const float* Wo     = (const float*)d_in[11];
    const float* bo     = (const float*)d_in[12];
    const float* relpos = (const float*)d_in[13];
    float* out = (float*)d_out;

    float *ubb, *bvb, *uwb, *vwb, *cuvb;
    cudaGetSymbolAddress((void**)&ubb,  g_ub);
    cudaGetSymbolAddress((void**)&bvb,  g_Bv);
    cudaGetSymbolAddress((void**)&uwb,  g_uw);
    cudaGetSymbolAddress((void**)&vwb,  g_vw);
    cudaGetSymbolAddress((void**)&cuvb, g_cuv);

    __half *xh, *Rh, *Wsh, *Wsl, *vh;
    __half *Qbh, *Kbh, *Kbl, *Vbh, *Vbl, *Pbh, *Pbl;
    cudaGetSymbolAddress((void**)&xh,  g_xh);
    cudaGetSymbolAddress((void**)&Rh,  g_Rh);
    cudaGetSymbolAddress((void**)&Wsh, g_Wsh);
    cudaGetSymbolAddress((void**)&Wsl, g_Wsl);
    cudaGetSymbolAddress((void**)&vh,  g_vh);
    cudaGetSymbolAddress((void**)&Qbh, g_Qbh);
    cudaGetSymbolAddress((void**)&Kbh, g_Kbh);
    cudaGetSymbolAddress((void**)&Kbl, g_Kbl);
    cudaGetSymbolAddress((void**)&Vbh, g_Vbh);
    cudaGetSymbolAddress((void**)&Vbl, g_Vbl);
    cudaGetSymbolAddress((void**)&Pbh, g_Pbh);
    cudaGetSymbolAddress((void**)&Pbl, g_Pbl);

    const float* R = relpos + (size_t)1 * D;   // rows [1, 2048)

    // --- weight splits + rel contractions (contract_c fused) ---
    SplitBatch sw;
    sw.src[0] = Wq; sw.src[1] = Wk; sw.src[2] = Wv; sw.src[3] = Wr; sw.src[4] = Wo;
    splitW_kernel<<<dim3(D * D / 256, 5), 256>>>(sw, Wsh, Wsl);
    contract_w<<<2 * H * D / 256, 256>>>(Wr, br, rel_u, rel_v, uwb, vwb, cuvb);

    // --- ubias / Bv rank-16 GEMMs (exact fp32), fused with fp16 conversion ---
    rank16_cvt_kernel<<<(BS + 7) / 8, 256>>>(x, uwb, cuvb, ubb, xh, BS, 0);
    rank16_cvt_kernel<<<(LP + 7) / 8, 256>>>(R, vwb, cuvb, bvb, Rh, LP, 1);

    cudaFuncSetAttribute(gemm_tc, cudaFuncAttributeMaxDynamicSharedMemorySize,
                         GEMM_SMEM);

    // --- Q/K/V + P projections (merged, grid.z = 4; z=3 is P from R) ---
    GemmBatch b1 = {};
    b1.Wh[0] = Wsh + 0 * (size_t)D * D; b1.Wl[0] = Wsl + 0 * (size_t)D * D;
    b1.bias[0] = bq; b1.mode[0] = 2; b1.Ch[0] = Qbh;                 // Q: single
    b1.Wh[1] = Wsh + 1 * (size_t)D * D; b1.Wl[1] = Wsl + 1 * (size_t)D * D;
    b1.bias[1] = bk; b1.mode[1] = 1; b1.Ch[1] = Kbh; b1.Cl[1] = Kbl; // K: hi+lo
    b1.Wh[2] = Wsh + 2 * (size_t)D * D; b1.Wl[2] = Wsl + 2 * (size_t)D * D;
    b1.bias[2] = bv; b1.mode[2] = 1; b1.Ch[2] = Vbh; b1.Cl[2] = Vbl; // V: hi+lo
    b1.Wh[3] = Wsh + 1 * (size_t)D * D; b1.Wl[3] = Wsl + 1 * (size_t)D * D;
    b1.bias[3] = bk; b1.mode[3] = 1; b1.Ch[3] = Pbh; b1.Cl[3] = Pbl; // P: hi+lo
    gemm_tc<<<dim3(8, 32, 4), 256, GEMM_SMEM>>>(xh, Rh, b1, BS, LP);

    // --- tensorized attention (2 CTAs/SM, QP shift-reuse) ---
    cudaFuncSetAttribute(attn_mma, cudaFuncAttributeMaxDynamicSharedMemorySize,
                         ATTN_SMEM_BYTES);
    attn_mma<<<dim3(B * H, S / 64), 128, ATTN_SMEM_BYTES>>>(
        Qbh, Kbh, Kbl, Vbh, Vbl, Pbh, Pbl, ubb, bvb, vh);

    // --- output projection (fp32 out) ---
    GemmBatch b3 = {};
    b3.Wh[0] = Wsh + 4 * (size_t)D * D; b3.Wl[0] = Wsl + 4 * (size_t)D * D;
    b3.bias[0] = bo; b3.mode[0] = 0; b3.C[0] = out;
    gemm_tc<<<dim3(8, 32, 1), 256, GEMM_SMEM>>>(vh, nullptr, b3, BS, BS);
}

// round 16
// speedup vs baseline: 2.2779x; 1.0111x over previous
#include <cuda_runtime.h>
#include <cuda_fp16.h>
#include <cstdint>

// Problem constants
#define B 4
#define S 1024
#define D 1024
#define H 16
#define DK 64
#define L 2047          // 2*S - 1
#define LP 1088         // P rows actually used by attention (max read 1087)
#define BS (B*S)        // 4096

// ---------------------------------------------------------------------------
// Scratch (static device globals; no runtime allocation allowed)
// ---------------------------------------------------------------------------
__device__ float g_ub[B * H * S];
__device__ float g_Bv[H * L];
__device__ float g_uw[H * D];
__device__ float g_vw[H * D];
__device__ float g_cuv[32];

// fp16 operands. A-side tensors: single fp16. B-side tensors: hi+lo pair.
__device__ __half g_xh[BS * D];                      // A of projections
__device__ __half g_Rh[LP * D];                      // A of P projection
__device__ __half g_Wsh[5 * D * D], g_Wsl[5 * D * D];// q,k,v,r,o (B side)

__device__ __half g_Qbh[BS * D];                     // A of QK/QP
__device__ __half g_Kbh[BS * D], g_Kbl[BS * D];      // B of QK
__device__ __half g_Vbh[BS * D], g_Vbl[BS * D];      // B of PV
__device__ __half g_Pbh[LP * D], g_Pbl[LP * D];      // B of QP

__device__ __half g_vh[BS * D];                      // attn out = A of out-proj

// ---------------------------------------------------------------------------
// PTX helpers: portable sm_80+ (ldmatrix / mma.sync / cp.async).
// ---------------------------------------------------------------------------
__device__ __forceinline__ uint32_t smem_to_u32(const void* p) {
    uint32_t a;
    asm("{ .reg .u64 t; cvta.to.shared.u64 t, %1; cvt.u32.u64 %0, t; }"
        : "=r"(a) : "l"(p));
    return a;
}

__device__ __forceinline__ void ldsm4(uint32_t* r, uint32_t addr) {
    asm volatile("ldmatrix.sync.aligned.m8n8.x4.shared.b16 {%0,%1,%2,%3}, [%4];"
                 : "=r"(r[0]), "=r"(r[1]), "=r"(r[2]), "=r"(r[3]) : "r"(addr));
}
__device__ __forceinline__ void ldsm4t(uint32_t* r, uint32_t addr) {
    asm volatile("ldmatrix.sync.aligned.m8n8.x4.trans.shared.b16 {%0,%1,%2,%3}, [%4];"
                 : "=r"(r[0]), "=r"(r[1]), "=r"(r[2]), "=r"(r[3]) : "r"(addr));
}

__device__ __forceinline__ void mma16816(float* d, const uint32_t* a,
                                         const uint32_t* b) {
    asm volatile(
        "mma.sync.aligned.m16n8k16.row.col.f32.f16.f16.f32 "
        "{%0,%1,%2,%3}, {%4,%5,%6,%7}, {%8,%9}, {%0,%1,%2,%3};"
        : "+f"(d[0]), "+f"(d[1]), "+f"(d[2]), "+f"(d[3])
        : "r"(a[0]), "r"(a[1]), "r"(a[2]), "r"(a[3]), "r"(b[0]), "r"(b[1]));
}

__device__ __forceinline__ void cp16(uint32_t dst, const void* src, int sz) {
    asm volatile("cp.async.cg.shared.global [%0], [%1], 16, %2;\n"
                 :: "r"(dst), "l"(src), "r"(sz));
}
__device__ __forceinline__ void cp_commit() {
    asm volatile("cp.async.commit_group;\n" ::: "memory");
}
template <int N> __device__ __forceinline__ void cp_wait() {
    asm volatile("cp.async.wait_group %0;\n" :: "n"(N) : "memory");
}

// ---------------------------------------------------------------------------
// Weight split: fp32 -> fp16 hi + lo (float4-vectorized)
// ---------------------------------------------------------------------------
struct SplitBatch { const float* src[5]; };

__global__ void splitW_kernel(const SplitBatch sb,
                              __half* __restrict__ hi,
                              __half* __restrict__ lo)
{
    int z = blockIdx.y;
    int i = (blockIdx.x * 256 + threadIdx.x) * 4;
    size_t off = (size_t)z * D * D + i;
    float4 x4 = *(const float4*)(sb.src[z] + i);
    __half2 h01, h23, l01, l23;
    h01.x = __float2half_rn(x4.x); h01.y = __float2half_rn(x4.y);
    h23.x = __float2half_rn(x4.z); h23.y = __float2half_rn(x4.w);
    l01.x = __float2half_rn(x4.x - __half2float(h01.x));
    l01.y = __float2half_rn(x4.y - __half2float(h01.y));
    l23.x = __float2half_rn(x4.z - __half2float(h23.x));
    l23.y = __float2half_rn(x4.w - __half2float(h23.y));
    *(__half2*)(hi + off)     = h01;
    *(__half2*)(hi + off + 2) = h23;
    *(__half2*)(lo + off)     = l01;
    *(__half2*)(lo + off + 2) = l23;
}

// ---------------------------------------------------------------------------
// rel_u/rel_v pre-contraction (replaces the KR and PR full projections)
// float4-vectorized over e; contract_c fused into block 0.
// ---------------------------------------------------------------------------
__global__ void contract_w(const float* __restrict__ Wr,
                           const float* __restrict__ br,
                           const float* __restrict__ rel_u,
                           const float* __restrict__ rel_v,
                           float* __restrict__ uw, float* __restrict__ vw,
                           float* __restrict__ cuv)
{
    if (blockIdx.x == 0 && threadIdx.x < 32) {
        int t = threadIdx.x;
        int h = t & 15;
        const float* rel = (t < 16) ? rel_u : rel_v;
        float s = 0.f;
        for (int d = 0; d < DK; d++)
            s = fmaf(rel[h * DK + d], br[h * DK + d], s);
        cuv[t] = s;
    }
    int idx = blockIdx.x * 256 + threadIdx.x;   // 0 .. 2*H*D/4 - 1 (8192)
    int t   = idx >> 12;                         // 0: uw, 1: vw
    int he4 = idx & 4095;
    int h  = he4 >> 8;
    int e4 = (he4 & 255) * 4;
    const float* rel = t ? rel_v : rel_u;
    float4 s = make_float4(0.f, 0.f, 0.f, 0.f);
#pragma unroll 8
    for (int d = 0; d < DK; d++) {
        float r = __ldg(&rel[h * DK + d]);
        float4 wv = *(const float4*)&Wr[(size_t)(h * DK + d) * D + e4];
        s.x = fmaf(r, wv.x, s.x); s.y = fmaf(r, wv.y, s.y);
        s.z = fmaf(r, wv.z, s.z); s.w = fmaf(r, wv.w, s.w);
    }
    *(float4*)&(t ? vw : uw)[h * D + e4] = s;
}

// ---------------------------------------------------------------------------
// Merged rank-16 GEMMs (ubias and Bv), 4 rows per warp (w-fragment reuse +
// ILP), fused fp16 conversion of A. One launch:
//   blocks [0, BS/32)           : ubias = x @ uw^T + cu ; also emit x16
//   blocks [BS/32, BS/32+LP/32) : Bv    = R @ vw^T + cv ; also emit R16
// ---------------------------------------------------------------------------
__global__ __launch_bounds__(256) void rank16_cvt_kernel(
    const float* __restrict__ A0, const float* __restrict__ w0,
    const float* __restrict__ A1, const float* __restrict__ w1,
    const float* __restrict__ c,
    float* __restrict__ out0, float* __restrict__ out1,
    __half* __restrict__ A160, __half* __restrict__ A161)
{
    const int mode = (blockIdx.x >= BS / 32) ? 1 : 0;
    const int blk  = mode ? blockIdx.x - BS / 32 : blockIdx.x;
    const float* A  = mode ? A1 : A0;
    const float* w  = mode ? w1 : w0;
    __half* A16     = mode ? A161 : A160;
    const int warp = threadIdx.x >> 5;
    const int lane = threadIdx.x & 31;
    const int row0 = blk * 32 + warp * 4;

    float acc[4][16];
#pragma unroll
    for (int r = 0; r < 4; r++)
#pragma unroll
        for (int h = 0; h < 16; h++) acc[r][h] = 0.f;

#pragma unroll 2
    for (int j = 0; j < 8; j++) {
        const int col = lane + j * 32;            // float4 index within row
        float4 xv[4];
#pragma unroll
        for (int r = 0; r < 4; r++) {
            xv[r] = ((const float4*)(A + (size_t)(row0 + r) * D))[col];
            __half2 h01, h23;
            h01.x = __float2half_rn(xv[r].x); h01.y = __float2half_rn(xv[r].y);
            h23.x = __float2half_rn(xv[r].z); h23.y = __float2half_rn(xv[r].w);
            __half* a16r = A16 + (size_t)(row0 + r) * D + 4 * col;
            *(__half2*)(a16r)     = h01;
            *(__half2*)(a16r + 2) = h23;
        }
#pragma unroll
        for (int h = 0; h < 16; h++) {
            float4 wv = ((const float4*)(w + h * D))[col];
#pragma unroll
            for (int r = 0; r < 4; r++)
                acc[r][h] += xv[r].x * wv.x + xv[r].y * wv.y +
                             xv[r].z * wv.z + xv[r].w * wv.w;
        }
    }

#pragma unroll
    for (int r = 0; r < 4; r++) {
        float mine = 0.f;
#pragma unroll
        for (int h = 0; h < 16; h++) {
            float v = acc[r][h];
            v += __shfl_xor_sync(0xffffffffu, v, 16);
            v += __shfl_xor_sync(0xffffffffu, v, 8);
            v += __shfl_xor_sync(0xffffffffu, v, 4);
            v += __shfl_xor_sync(0xffffffffu, v, 2);
            v += __shfl_xor_sync(0xffffffffu, v, 1);
            if (lane == h) mine = v;
        }
        if (lane < 16) {
            int row = row0 + r;
            float val = mine + c[lane + (mode ? 16 : 0)];
            if (mode == 0) {
                int b = row >> 10, z = row & 1023;
                out0[((b << 4) + lane) * S + z] = val;
            } else {
                out1[lane * L + row] = val;
            }
        }
    }
}

// ---------------------------------------------------------------------------
// HMMA GEMM: C[M,1024] = A[M,1024] @ W[1024,1024]^T + bias
// fp16x2: A single fp16, W hi+lo fp16 -> 2 MMA passes. 3-stage cp.async
// pipeline. mode 0: fp32 C.  mode 1: fp16 hi+lo outputs.  mode 2: fp16 hi.
// z < 3: A = Ah1, M = M1.  z >= 3: A = Ah2, M = M2.
// ---------------------------------------------------------------------------
struct GemmBatch {
    const __half* Wh[4];
    const __half* Wl[4];
    const float* bias[4];
    float* C[4];
    __half* Ch[4];
    __half* Cl[4];
    int mode[4];
};

#define RS      40                   // fp16 elems per smem row slot (80 bytes)
#define TILE_B  (128 * RS * 2)       // 10240 B
#define STAGE_B (3 * TILE_B)         // A, Wh, Wl  (30720 B)
#define NSTAGE  3
#define GEMM_SMEM (NSTAGE * STAGE_B) // 92160
#define NC      32

__device__ __forceinline__ void load_chunk(
    uint32_t sbase, int tid,
    const __half* Ah, const __half* Wh, const __half* Wl,
    int bm, int bn, int M, int c, int st)
{
    const int kbase = c * 32;
    const uint32_t stoff = sbase + st * STAGE_B;
#pragma unroll
    for (int t = 0; t < 3; t++) {
        const __half* base = (t == 0) ? Ah : (t == 1) ? Wh : Wl;
        const int rb = (t == 0) ? bm : bn;
#pragma unroll
        for (int j = 0; j < 2; j++) {
            int idx = tid + j * 256;          // 0..511
            int row = idx >> 2, g = idx & 3;
            int gr = rb + row;
            int sz = (t >= 1 || gr < M) ? 16 : 0;
            const void* src = base + (size_t)gr * 1024 + kbase + g * 8;
            uint32_t dst = stoff + t * TILE_B + row * 80 + g * 16;
            cp16(dst, src, sz);
        }
    }
}

__global__ __launch_bounds__(256, 2)
void gemm_tc(const __half* __restrict__ Ah1,
             const __half* __restrict__ Ah2,
             const GemmBatch bat, int M1, int M2)
{
    extern __shared__ char smem[];
    const uint32_t sbase = smem_to_u32(smem);
    const int tid  = threadIdx.x;
    const int wid  = tid >> 5;
    const int lane = tid & 31;
    const int bn = blockIdx.x * 128;
    const int bm = blockIdx.y * 128;
    const int z  = blockIdx.z;

    const __half* Ah = (z < 3) ? Ah1 : Ah2;
    const int M = (z < 3) ? M1 : M2;
    if (bm >= M) return;               // early-exit tail tiles (P trim)

    const __half* Wh = bat.Wh[z];
    const __half* Wl = bat.Wl[z];

    const int mb = (wid >> 2) * 64;
    const int nb = (wid & 3) * 32;

    const int li = lane >> 3, lr = lane & 7;
    const int a_off = ((li & 1) * 8 + lr) * 80 + (li >> 1) * 16;
    const int b_off = ((li >> 1) * 8 + lr) * 80 + (li & 1) * 16;

    float acc[4][4][4];
#pragma unroll
    for (int mf = 0; mf < 4; mf++)
#pragma unroll
        for (int nf = 0; nf < 4; nf++)
#pragma unroll
            for (int e = 0; e < 4; e++) acc[mf][nf][e] = 0.f;

    // 3-stage prologue: chunks 0 and 1 in flight
    load_chunk(sbase, tid, Ah, Wh, Wl, bm, bn, M, 0, 0);
    cp_commit();
    load_chunk(sbase, tid, Ah, Wh, Wl, bm, bn, M, 1, 1);
    cp_commit();

    int st = 0;
    for (int c = 0; c < NC; c++) {
        if (c + 1 < NC) cp_wait<1>();   // chunk c resident, c+1 may be in flight
        else            cp_wait<0>();
        __syncthreads();                // all warps done with buffer st's prior use
        if (c + 2 < NC) {
            int st2 = st + 2; if (st2 >= NSTAGE) st2 -= NSTAGE;
            load_chunk(sbase, tid, Ah, Wh, Wl, bm, bn, M, c + 2, st2);
            cp_commit();
        }

        const uint32_t aT = sbase + st * STAGE_B + 0 * TILE_B + (mb)*80 + a_off;
        const uint32_t wH = sbase + st * STAGE_B + 1 * TILE_B + (nb)*80 + b_off;
        const uint32_t wL = wH + TILE_B;

#pragma unroll
        for (int k16 = 0; k16 < 2; k16++) {
            const int ko = k16 * 32;
            uint32_t ah[4][4], bh[2][4], bl[2][4];
#pragma unroll
            for (int mf = 0; mf < 4; mf++)
                ldsm4(ah[mf], aT + mf * 16 * 80 + ko);
#pragma unroll
            for (int n2 = 0; n2 < 2; n2++) {
                ldsm4(bh[n2], wH + n2 * 16 * 80 + ko);
                ldsm4(bl[n2], wL + n2 * 16 * 80 + ko);
            }
#pragma unroll
            for (int mf = 0; mf < 4; mf++)
#pragma unroll
                for (int nf = 0; nf < 4; nf++) {
                    const uint32_t* bph = &bh[nf >> 1][(nf & 1) * 2];
                    const uint32_t* bpl = &bl[nf >> 1][(nf & 1) * 2];
                    mma16816(acc[mf][nf], ah[mf], bph);
                    mma16816(acc[mf][nf], ah[mf], bpl);
                }
        }
        if (++st >= NSTAGE) st = 0;
    }

    const float* bias = bat.bias[z];
    const int lr4 = lane >> 2, lc2 = (lane & 3) * 2;
    const int mode = bat.mode[z];
    if (mode == 0) {
        float* C = bat.C[z];
#pragma unroll
        for (int mf = 0; mf < 4; mf++)
#pragma unroll
            for (int nf = 0; nf < 4; nf++) {
                int gn = bn + nb + nf * 8 + lc2;
                float2 bi = *(const float2*)(bias + gn);
                int gm0 = bm + mb + mf * 16 + lr4;
                if (gm0 < M) {
                    float2 v = make_float2(acc[mf][nf][0] + bi.x, acc[mf][nf][1] + bi.y);
                    *(float2*)(C + (size_t)gm0 * 1024 + gn) = v;
                }
                int gm1 = gm0 + 8;
                if (gm1 < M) {
                    float2 v = make_float2(acc[mf][nf][2] + bi.x, acc[mf][nf][3] + bi.y);
                    *(float2*)(C + (size_t)gm1 * 1024 + gn) = v;
                }
            }
    } else if (mode == 1) {
        __half* Ch = bat.Ch[z];
        __half* Cl = bat.Cl[z];
#pragma unroll
        for (int mf = 0; mf < 4; mf++)
#pragma unroll
            for (int nf = 0; nf < 4; nf++) {
                int gn = bn + nb + nf * 8 + lc2;
                float2 bi = *(const float2*)(bias + gn);
#pragma unroll
                for (int half_i = 0; half_i < 2; half_i++) {
                    int gm = bm + mb + mf * 16 + lr4 + half_i * 8;
                    if (gm < M) {
                        float vx = acc[mf][nf][half_i * 2 + 0] + bi.x;
                        float vy = acc[mf][nf][half_i * 2 + 1] + bi.y;
                        __half hx = __float2half_rn(vx);
                        __half hy = __float2half_rn(vy);
                        __half2 hv; hv.x = hx; hv.y = hy;
                        __half2 lv;
                        lv.x = __float2half_rn(vx - __half2float(hx));
                        lv.y = __float2half_rn(vy - __half2float(hy));
                        *(__half2*)(Ch + (size_t)gm * 1024 + gn) = hv;
                        *(__half2*)(Cl + (size_t)gm * 1024 + gn) = lv;
                    }
                }
            }
    } else {
        __half* Ch = bat.Ch[z];
#pragma unroll
        for (int mf = 0; mf < 4; mf++)
#pragma unroll
            for (int nf = 0; nf < 4; nf++) {
                int gn = bn + nb + nf * 8 + lc2;
                float2 bi = *(const float2*)(bias + gn);
#pragma unroll
                for (int half_i = 0; half_i < 2; half_i++) {
                    int gm = bm + mb + mf * 16 + lr4 + half_i * 8;
                    if (gm < M) {
                        __half2 hv;
                        hv.x = __float2half_rn(acc[mf][nf][half_i * 2 + 0] + bi.x);
                        hv.y = __float2half_rn(acc[mf][nf][half_i * 2 + 1] + bi.y);
                        *(__half2*)(Ch + (size_t)gm * 1024 + gn) = hv;
                    }
                }
            }
    }
}

// ---------------------------------------------------------------------------
// Tensorized fused relative attention (flash-style, causal, fp16x2 MMA).
// Toeplitz-shift QP reuse (rotating 64x128 fp32 buffer); Q single fp16 in
// registers; probs single fp16. CTA: 64 q-rows, 4 warps, 2 CTAs/SM.
// ---------------------------------------------------------------------------
#define ATS      144                 // smem row stride bytes (72 fp16)
#define ST_KH    0                   // 64 x ATS
#define ST_KL    9216
#define ST_VH    18432
#define ST_VL    27648
#define ST_PH    36864               // 64 rows (new P window half)
#define ST_PL    46080
#define ST_UB    55296               // 64 floats
#define ST_BV    55552               // 127 floats (pad to 512)
#define SM_QPS   56064               // fp32 64 x 132 rotating QP = 33792
#define SM_PRB   89856               // probs fp16 single = 9216
#define ATTN_SMEM_BYTES 99072        // 2 CTAs/SM

__device__ __forceinline__ void attn_load_kv(
    uint32_t sb, int tid,
    const __half* Kh, const __half* Kl,
    const __half* Vh, const __half* Vl)
{
#pragma unroll
    for (int j = 0; j < 4; j++) {
        int idx = tid + j * 128;
        int row = idx >> 3, g = idx & 7;
        const size_t go = (size_t)row * D + g * 8;
        uint32_t so = row * ATS + g * 16;
        cp16(sb + ST_KH + so, Kh + go, 16);
        cp16(sb + ST_KL + so, Kl + go, 16);
        cp16(sb + ST_VH + so, Vh + go, 16);
        cp16(sb + ST_VL + so, Vl + go, 16);
    }
}

__device__ __forceinline__ void attn_load_p(
    uint32_t sb, int tid,
    const __half* Ph, const __half* Pl)
{
#pragma unroll
    for (int j = 0; j < 4; j++) {
        int idx = tid + j * 128;
        int row = idx >> 3, g = idx & 7;
        const size_t go = (size_t)row * D + g * 8;
        uint32_t so = row * ATS + g * 16;
        cp16(sb + ST_PH + so, Ph + go, 16);
        cp16(sb + ST_PL + so, Pl + go, 16);
    }
}

__global__ __launch_bounds__(128, 2) void attn_mma(
    const __half* __restrict__ Qh,
    const __half* __restrict__ Kh, const __half* __restrict__ Kl,
    const __half* __restrict__ Vh, const __half* __restrict__ Vl,
    const __half* __restrict__ Ph, const __half* __restrict__ Pl,
    const float* __restrict__ ubias, const float* __restrict__ Bv,
    __half* __restrict__ Oh)
{
    extern __shared__ char smem[];
    const uint32_t sb = smem_to_u32(smem);
    const int tid  = threadIdx.x;
    const int wid  = tid >> 5;
    const int lane = tid & 31;
    const int st = (S / 64 - 1) - blockIdx.y;    // heavy tiles first
    const int b  = blockIdx.x >> 4;
    const int h  = blockIdx.x & 15;
    const int s0 = st * 64;

    const int li = lane >> 3, lr = lane & 7;
    const int a_off = ((li & 1) * 8 + lr) * ATS + (li >> 1) * 16;
    const int b_off = ((li >> 1) * 8 + lr) * ATS + (li & 1) * 16;

    const int r0 = wid * 16 + (lane >> 2);
    const int colbase = (lane & 3) * 2;

    float* QPs = (float*)(smem + SM_QPS);

    // -------- prologue: stage Q once (single fp16), lift to registers ----
    uint32_t qf[4][4];
    {
        const __half* Qg = Qh + (size_t)(b * S + s0) * D + h * DK;
#pragma unroll
        for (int j = 0; j < 4; j++) {
            int idx = tid + j * 128;
            int row = idx >> 3, g = idx & 7;
            cp16(sb + ST_KH + row * ATS + g * 16, Qg + (size_t)row * D + g * 8, 16);
        }
        cp_commit();
        cp_wait<0>();
        __syncthreads();
#pragma unroll
        for (int k16 = 0; k16 < 4; k16++)
            ldsm4(qf[k16], sb + ST_KH + wid * 2304 + a_off + k16 * 32);
    }

    // -------- QP prologue (zt = -1): seed physical half 0 --------
    {
        const int prow0 = 960 - st * 64;
        __syncthreads();
        attn_load_p(sb, tid,
                    Ph + (size_t)prow0 * D + h * DK,
                    Pl + (size_t)prow0 * D + h * DK);
        cp_commit();
        cp_wait<0>();
        __syncthreads();

        float cQPn[8][4];
#pragma unroll
        for (int nf = 0; nf < 8; nf++)
#pragma unroll
            for (int e = 0; e < 4; e++) cQPn[nf][e] = 0.f;
#pragma unroll
        for (int k16 = 0; k16 < 4; k16++) {
            const int ko = k16 * 32;
#pragma unroll
            for (int n16 = 0; n16 < 4; n16++) {
                uint32_t pb[4], pl2[4];
                ldsm4(pb,  sb + ST_PH + b_off + n16 * 2304 + ko);
                ldsm4(pl2, sb + ST_PL + b_off + n16 * 2304 + ko);
#pragma unroll
                for (int sub = 0; sub < 2; sub++) {
                    const int nf = n16 * 2 + sub;
                    mma16816(cQPn[nf], qf[k16], &pb[sub * 2]);
                    mma16816(cQPn[nf], qf[k16], &pl2[sub * 2]);
                }
            }
        }
#pragma unroll
        for (int nf = 0; nf < 8; nf++) {
            int j0 = nf * 8 + colbase;       // physical half 0
            *(float2*)&QPs[r0 * 132 + j0]       = make_float2(cQPn[nf][0], cQPn[nf][1]);
            *(float2*)&QPs[(r0 + 8) * 132 + j0] = make_float2(cQPn[nf][2], cQPn[nf][3]);
        }
        __syncwarp();
    }

    float cO[8][4];
#pragma unroll
    for (int nf = 0; nf < 8; nf++)
#pragma unroll
        for (int e = 0; e < 4; e++) cO[nf][e] = 0.f;
    float mrow[2] = {-1e30f, -1e30f};
    float lsum[2] = {0.f, 0.f};

    for (int zt = 0; zt <= st; zt++) {
        __syncthreads();   // previous iteration's K/V/P reads complete

        const int z0 = zt * 64;
        const int lbase = (zt - st) * 64 + 960;
        const int prow0 = lbase + 64;            // new 64 P rows
        const size_t kvoff = (size_t)(b * S + z0) * D + h * DK;
        attn_load_kv(sb, tid, Kh + kvoff, Kl + kvoff, Vh + kvoff, Vl + kvoff);
        attn_load_p(sb, tid,
                    Ph + (size_t)prow0 * D + h * DK,
                    Pl + (size_t)prow0 * D + h * DK);
        {
            float* ubS = (float*)(smem + ST_UB);
            float* bvS = (float*)(smem + ST_BV);
            if (tid < 64)  ubS[tid] = ubias[(b * H + h) * S + z0 + tid];
            if (tid < 127) bvS[tid] = Bv[h * L + lbase + tid];
        }
        cp_commit();
        cp_wait<0>();
        __syncthreads();

        // -------- QK (64x64) + QP-new (64x64), fp16x2, Q from regs ----
        float cQK[8][4], cQPn[8][4];
#pragma unroll
        for (int nf = 0; nf < 8; nf++)
#pragma unroll
            for (int e = 0; e < 4; e++) { cQK[nf][e] = 0.f; cQPn[nf][e] = 0.f; }

#pragma unroll
        for (int k16 = 0; k16 < 4; k16++) {
            const int ko = k16 * 32;
#pragma unroll
            for (int n16 = 0; n16 < 4; n16++) {
                uint32_t kb[4], kl2[4];
                ldsm4(kb,  sb + ST_KH + b_off + n16 * 2304 + ko);
                ldsm4(kl2, sb + ST_KL + b_off + n16 * 2304 + ko);
#pragma unroll
                for (int sub = 0; sub < 2; sub++) {
                    const int nf = n16 * 2 + sub;
                    mma16816(cQK[nf], qf[k16], &kb[sub * 2]);
                    mma16816(cQK[nf], qf[k16], &kl2[sub * 2]);
                }
            }
#pragma unroll
            for (int n16 = 0; n16 < 4; n16++) {
                uint32_t pb[4], pl2[4];
                ldsm4(pb,  sb + ST_PH + b_off + n16 * 2304 + ko);
                ldsm4(pl2, sb + ST_PL + b_off + n16 * 2304 + ko);
#pragma unroll
                for (int sub = 0; sub < 2; sub++) {
                    const int nf = n16 * 2 + sub;
                    mma16816(cQPn[nf], qf[k16], &pb[sub * 2]);
                    mma16816(cQPn[nf], qf[k16], &pl2[sub * 2]);
                }
            }
        }

        // spill new QP columns into the rotating buffer's target half
        const int hb = ((zt + 1) & 1) << 6;
#pragma unroll
        for (int nf = 0; nf < 8; nf++) {
            int j0 = hb + nf * 8 + colbase;
            *(float2*)&QPs[r0 * 132 + j0]       = make_float2(cQPn[nf][0], cQPn[nf][1]);
            *(float2*)&QPs[(r0 + 8) * 132 + j0] = make_float2(cQPn[nf][2], cQPn[nf][3]);
        }
        __syncwarp();

        // -------- logits + online softmax (rotating-gather) --------
        const float* ubS = (const float*)(smem + ST_UB);
        const float* bvS = (const float*)(smem + ST_BV);
        const int p0 = 63 - r0;
        const int p1 = 55 - r0;
        const int off = (zt & 1) << 6;           // rotation offset
        const float* row0p = &QPs[r0 * 132];
        const float* row1p = &QPs[(r0 + 8) * 132];
        float tm0 = -1e30f, tm1 = -1e30f;
#pragma unroll
        for (int nf = 0; nf < 8; nf++) {
            int j0 = nf * 8 + colbase, j1 = j0 + 1;
            float v0 = (cQK[nf][0] + row0p[(j0 + p0 + off) & 127] + ubS[j0] + bvS[j0 + p0]) * 0.125f;
            float v1 = (cQK[nf][1] + row0p[(j1 + p0 + off) & 127] + ubS[j1] + bvS[j1 + p0]) * 0.125f;
            float v2 = (cQK[nf][2] + row1p[(j0 + p1 + off) & 127] + ubS[j0] + bvS[j0 + p1]) * 0.125f;
            float v3 = (cQK[nf][3] + row1p[(j1 + p1 + off) & 127] + ubS[j1] + bvS[j1 + p1]) * 0.125f;
            if (zt == st) {
                if (j0 > r0) v0 = -1e30f;
                if (j1 > r0) v1 = -1e30f;
                if (j0 > r0 + 8) v2 = -1e30f;
                if (j1 > r0 + 8) v3 = -1e30f;
            }
            cQK[nf][0] = v0; cQK[nf][1] = v1; cQK[nf][2] = v2; cQK[nf][3] = v3;
            tm0 = fmaxf(tm0, fmaxf(v0, v1));
            tm1 = fmaxf(tm1, fmaxf(v2, v3));
        }
        tm0 = fmaxf(tm0, __shfl_xor_sync(0xffffffffu, tm0, 1));
        tm0 = fmaxf(tm0, __shfl_xor_sync(0xffffffffu, tm0, 2));
        tm1 = fmaxf(tm1, __shfl_xor_sync(0xffffffffu, tm1, 1));
        tm1 = fmaxf(tm1, __shfl_xor_sync(0xffffffffu, tm1, 2));

        float nm0 = fmaxf(mrow[0], tm0), nm1 = fmaxf(mrow[1], tm1);
        float sc0 = __expf(mrow[0] - nm0), sc1 = __expf(mrow[1] - nm1);

        __half* phs = (__half*)(smem + SM_PRB);
        float ps0 = 0.f, ps1 = 0.f;
#pragma unroll
        for (int nf = 0; nf < 8; nf++) {
            int j0 = nf * 8 + colbase;
            float e0 = __expf(cQK[nf][0] - nm0);
            float e1 = __expf(cQK[nf][1] - nm0);
            float e2 = __expf(cQK[nf][2] - nm1);
            float e3 = __expf(cQK[nf][3] - nm1);
            ps0 += e0 + e1;
            ps1 += e2 + e3;
            __half2 hv;
            hv.x = __float2half_rn(e0); hv.y = __float2half_rn(e1);
            *(__half2*)&phs[r0 * 72 + j0] = hv;
            hv.x = __float2half_rn(e2); hv.y = __float2half_rn(e3);
            *(__half2*)&phs[(r0 + 8) * 72 + j0] = hv;
        }
        ps0 += __shfl_xor_sync(0xffffffffu, ps0, 1);
        ps0 += __shfl_xor_sync(0xffffffffu, ps0, 2);
        ps1 += __shfl_xor_sync(0xffffffffu, ps1, 1);
        ps1 += __shfl_xor_sync(0xffffffffu, ps1, 2);
        lsum[0] = lsum[0] * sc0 + ps0;
        lsum[1] = lsum[1] * sc1 + ps1;
        mrow[0] = nm0; mrow[1] = nm1;

#pragma unroll
        for (int nf = 0; nf < 8; nf++) {
            cO[nf][0] *= sc0; cO[nf][1] *= sc0;
            cO[nf][2] *= sc1; cO[nf][3] *= sc1;
        }
        __syncwarp();

        // -------- PV MMA (probs x V), fp16x2 --------
#pragma unroll
        for (int k16 = 0; k16 < 4; k16++) {
            const int ko = k16 * 32;
            uint32_t aph[4];
            ldsm4(aph, sb + SM_PRB + wid * 2304 + a_off + ko);
#pragma unroll
            for (int n16 = 0; n16 < 4; n16++) {
                uint32_t vb[4], vl2[4];
                ldsm4t(vb,  sb + ST_VH + a_off + k16 * 2304 + n16 * 32);
                ldsm4t(vl2, sb + ST_VL + a_off + k16 * 2304 + n16 * 32);
#pragma unroll
                for (int sub = 0; sub < 2; sub++) {
                    const int nf = n16 * 2 + sub;
                    mma16816(cO[nf], aph, &vb[sub * 2]);
                    mma16816(cO[nf], aph, &vl2[sub * 2]);
                }
            }
        }
    }

    // -------- output: fp16 single --------
    const float i0 = 1.f / lsum[0];
    const float i1 = 1.f / lsum[1];
    const size_t row0 = (size_t)(b * S + s0 + r0);
    const size_t row1 = row0 + 8;
#pragma unroll
    for (int nf = 0; nf < 8; nf++) {
        int col = h * DK + nf * 8 + colbase;
        __half2 hv;
        hv.x = __float2half_rn(cO[nf][0] * i0);
        hv.y = __float2half_rn(cO[nf][1] * i0);
        *(__half2*)(Oh + row0 * D + col) = hv;
        hv.x = __float2half_rn(cO[nf][2] * i1);
        hv.y = __float2half_rn(cO[nf][3] * i1);
        *(__half2*)(Oh + row1 * D + col) = hv;
    }
}

// ---------------------------------------------------------------------------
// Launch
// ---------------------------------------------------------------------------
extern "C" void kernel_launch(void* const* d_in, const int* in_sizes, int n_in,
                              void* d_out, int out_size)
{
    const float* x      = (const float*)d_in[0];
    const float* Wq     = (const float*)d_in[1];
    const float* bq     = (const float*)d_in[2];
    const float* Wk     = (const float*)d_in[3];
    const float* bk     = (const float*)d_in[4];
    const float* Wv     = (const float*)d_in[5];
    const float* bv     = (const float*)d_in[6];
    const float* Wr     = (const float*)d_in[7];
    const float* br     = (const float*)d_in[8];
    const float* rel_u  = (const float*)d_in[9];
    const float* rel_v  = (const float*)d_in[10];
    const float* Wo     = (const float*)d_in[11];
    const float* bo     = (const float*)d_in[12];
    const float* relpos = (const float*)d_in[13];
    float* out = (float*)d_out;

    float *ubb, *bvb, *uwb, *vwb, *cuvb;
    cudaGetSymbolAddress((void**)&ubb,  g_ub);
    cudaGetSymbolAddress((void**)&bvb,  g_Bv);
    cudaGetSymbolAddress((void**)&uwb,  g_uw);
    cudaGetSymbolAddress((void**)&vwb,  g_vw);
    cudaGetSymbolAddress((void**)&cuvb, g_cuv);

    __half *xh, *Rh, *Wsh, *Wsl, *vh;
    __half *Qbh, *Kbh, *Kbl, *Vbh, *Vbl, *Pbh, *Pbl;
    cudaGetSymbolAddress((void**)&xh,  g_xh);
    cudaGetSymbolAddress((void**)&Rh,  g_Rh);
    cudaGetSymbolAddress((void**)&Wsh, g_Wsh);
    cudaGetSymbolAddress((void**)&Wsl, g_Wsl);
    cudaGetSymbolAddress((void**)&vh,  g_vh);
    cudaGetSymbolAddress((void**)&Qbh, g_Qbh);
    cudaGetSymbolAddress((void**)&Kbh, g_Kbh);
    cudaGetSymbolAddress((void**)&Kbl, g_Kbl);
    cudaGetSymbolAddress((void**)&Vbh, g_Vbh);
    cudaGetSymbolAddress((void**)&Vbl, g_Vbl);
    cudaGetSymbolAddress((void**)&Pbh, g_Pbh);
    cudaGetSymbolAddress((void**)&Pbl, g_Pbl);

    const float* R = relpos + (size_t)1 * D;   // rows [1, 2048)

    // --- weight splits + rel contractions (both vectorized) ---
    SplitBatch sw;
    sw.src[0] = Wq; sw.src[1] = Wk; sw.src[2] = Wv; sw.src[3] = Wr; sw.src[4] = Wo;
    splitW_kernel<<<dim3(D * D / 1024, 5), 256>>>(sw, Wsh, Wsl);
    contract_w<<<2 * H * D / 4 / 256, 256>>>(Wr, br, rel_u, rel_v, uwb, vwb, cuvb);

    // --- merged ubias/Bv rank-16 GEMMs + fp16 conversions (one launch) ---
    rank16_cvt_kernel<<<BS / 32 + LP / 32, 256>>>(
        x, uwb, R, vwb, cuvb, ubb, bvb, xh, Rh);

    cudaFuncSetAttribute(gemm_tc, cudaFuncAttributeMaxDynamicSharedMemorySize,
                         GEMM_SMEM);

    // --- Q/K/V + P projections (merged, grid.z = 4; z=3 is P from R) ---
    GemmBatch b1 = {};
    b1.Wh[0] = Wsh + 0 * (size_t)D * D; b1.Wl[0] = Wsl + 0 * (size_t)D * D;
    b1.bias[0] = bq; b1.mode[0] = 2; b1.Ch[0] = Qbh;                 // Q: single
    b1.Wh[1] = Wsh + 1 * (size_t)D * D; b1.Wl[1] = Wsl + 1 * (size_t)D * D;
    b1.bias[1] = bk; b1.mode[1] = 1; b1.Ch[1] = Kbh; b1.Cl[1] = Kbl; // K: hi+lo
    b1.Wh[2] = Wsh + 2 * (size_t)D * D; b1.Wl[2] = Wsl + 2 * (size_t)D * D;
    b1.bias[2] = bv; b1.mode[2] = 1; b1.Ch[2] = Vbh; b1.Cl[2] = Vbl; // V: hi+lo
    b1.Wh[3] = Wsh + 1 * (size_t)D * D; b1.Wl[3] = Wsl + 1 * (size_t)D * D;
    b1.bias[3] = bk; b1.mode[3] = 1; b1.Ch[3] = Pbh; b1.Cl[3] = Pbl; // P: hi+lo
    gemm_tc<<<dim3(8, 32, 4), 256, GEMM_SMEM>>>(xh, Rh, b1, BS, LP);

    // --- tensorized attention (2 CTAs/SM, QP shift-reuse) ---
    cudaFuncSetAttribute(attn_mma, cudaFuncAttributeMaxDynamicSharedMemorySize,
                         ATTN_SMEM_BYTES);
    attn_mma<<<dim3(B * H, S / 64), 128, ATTN_SMEM_BYTES>>>(
        Qbh, Kbh, Kbl, Vbh, Vbl, Pbh, Pbl, ubb, bvb, vh);

    // --- output projection (fp32 out) ---
    GemmBatch b3 = {};
    b3.Wh[0] = Wsh + 4 * (size_t)D * D; b3.Wl[0] = Wsl + 4 * (size_t)D * D;
    b3.bias[0] = bo; b3.mode[0] = 0; b3.C[0] = out;
    gemm_tc<<<dim3(8, 32, 1), 256, GEMM_SMEM>>>(vh, nullptr, b3, BS, BS);
}